// round 10
// baseline (speedup 1.0000x reference)
#include <cuda_runtime.h>
#include <cuda_bf16.h>
#include <cstdint>
#include <math.h>

typedef unsigned long long ull;
typedef unsigned int uint;

#define B_     32
#define T0     1600
#define C0     80
#define T1     800
#define D_     512
#define VOCABN 1000
#define HIDN   512
#define USTEPS 200
#define EPSV   1e-3f

// ---------------- scratch (static device globals; no allocation) ----------------
__device__ float g_bn[160];
__device__ float g_h1[B_ * T1 * D_];                // fp32 activations (enc ends here)
__device__ float g_h2[B_ * T1 * D_];
__device__ float g_hstate[2][B_ * HIDN];
__device__ float g_mhp[4][B_ * 1536];
__device__ unsigned g_sync[USTEPS];
__device__ float g_scoresall[USTEPS * B_ * T1];
__device__ float g_catall[USTEPS * B_ * 1024];
__device__ float g_logitsall[USTEPS * B_ * VOCABN];
// bf16 split activations (ping-pong) and split transposed weights
__device__ __nv_bfloat16 g_shi0[B_ * T1 * D_];
__device__ __nv_bfloat16 g_slo0[B_ * T1 * D_];
__device__ __nv_bfloat16 g_shi1[B_ * T1 * D_];
__device__ __nv_bfloat16 g_slo1[B_ * T1 * D_];
__device__ __nv_bfloat16 g_wt_hi[4 * 512 * 2560];   // [l][n][kin]
__device__ __nv_bfloat16 g_wt_lo[4 * 512 * 2560];

// ---------------- packed f32x2 helpers (FFMA2) ----------------
__device__ __forceinline__ void fma2(ull& d, ull a, ull b) {
    asm("fma.rn.f32x2 %0, %1, %2, %0;" : "+l"(d) : "l"(a), "l"(b));
}
__device__ __forceinline__ ull pack2(float x) {
    ull r;
    asm("mov.b64 %0, {%1, %1};" : "=l"(r) : "f"(x));
    return r;
}
__device__ __forceinline__ float2 unpack2(ull v) {
    float2 f;
    asm("mov.b64 {%0, %1}, %2;" : "=f"(f.x), "=f"(f.y) : "l"(v));
    return f;
}

// ---------------- bf16 split helpers ----------------
__device__ __forceinline__ void split4(float4 v, uint2& hi, uint2& lo) {
    __nv_bfloat16 h0 = __float2bfloat16(v.x), h1 = __float2bfloat16(v.y);
    __nv_bfloat16 h2 = __float2bfloat16(v.z), h3 = __float2bfloat16(v.w);
    __nv_bfloat16 l0 = __float2bfloat16(v.x - __bfloat162float(h0));
    __nv_bfloat16 l1 = __float2bfloat16(v.y - __bfloat162float(h1));
    __nv_bfloat16 l2 = __float2bfloat16(v.z - __bfloat162float(h2));
    __nv_bfloat16 l3 = __float2bfloat16(v.w - __bfloat162float(h3));
    hi.x = (uint)__bfloat16_as_ushort(h0) | ((uint)__bfloat16_as_ushort(h1) << 16);
    hi.y = (uint)__bfloat16_as_ushort(h2) | ((uint)__bfloat16_as_ushort(h3) << 16);
    lo.x = (uint)__bfloat16_as_ushort(l0) | ((uint)__bfloat16_as_ushort(l1) << 16);
    lo.y = (uint)__bfloat16_as_ushort(l2) | ((uint)__bfloat16_as_ushort(l3) << 16);
}
__device__ __forceinline__ void split2(float x, float y, uint& hi, uint& lo) {
    __nv_bfloat16 hx = __float2bfloat16(x), hy = __float2bfloat16(y);
    __nv_bfloat16 lx = __float2bfloat16(x - __bfloat162float(hx));
    __nv_bfloat16 ly = __float2bfloat16(y - __bfloat162float(hy));
    hi = (uint)__bfloat16_as_ushort(hx) | ((uint)__bfloat16_as_ushort(hy) << 16);
    lo = (uint)__bfloat16_as_ushort(lx) | ((uint)__bfloat16_as_ushort(ly) << 16);
}

// ---------------- mma.sync / ldmatrix / cp.async helpers (sm_80+ portable) ----------------
__device__ __forceinline__ uint32_t smem_to_u32(const void* p) {
    uint32_t a;
    asm("{ .reg .u64 t; cvta.to.shared.u64 t, %1; cvt.u32.u64 %0, t; }" : "=r"(a) : "l"(p));
    return a;
}
__device__ __forceinline__ void mma_bf16(float* d, const uint32_t* a, const uint32_t* b) {
    asm volatile(
        "mma.sync.aligned.m16n8k16.row.col.f32.bf16.bf16.f32 "
        "{%0,%1,%2,%3}, {%4,%5,%6,%7}, {%8,%9}, {%0,%1,%2,%3};"
        : "+f"(d[0]), "+f"(d[1]), "+f"(d[2]), "+f"(d[3])
        : "r"(a[0]), "r"(a[1]), "r"(a[2]), "r"(a[3]), "r"(b[0]), "r"(b[1]));
}
__device__ __forceinline__ void ldsm4(uint32_t* r, uint32_t addr) {
    asm volatile("ldmatrix.sync.aligned.m8n8.x4.shared.b16 {%0,%1,%2,%3}, [%4];"
                 : "=r"(r[0]), "=r"(r[1]), "=r"(r[2]), "=r"(r[3]) : "r"(addr));
}
__device__ __forceinline__ void cp16(uint32_t d, const void* s, int sz) {
    asm volatile("cp.async.cg.shared.global [%0], [%1], 16, %2;"
                 :: "r"(d), "l"(s), "r"(sz) : "memory");
}
#define CP_COMMIT() asm volatile("cp.async.commit_group;" ::: "memory")

// ---------------- BatchNorm statistics ----------------
__global__ void __launch_bounds__(256) bn_stats_kernel(const float* __restrict__ x,
                                                       const float* __restrict__ gamma,
                                                       const float* __restrict__ beta) {
    const int c = blockIdx.x;
    const int tid = threadIdx.x;
    const int N = B_ * T0;
    float s = 0.f, sq = 0.f;
    for (int i = tid; i < N; i += 256) {
        float v = x[(size_t)i * C0 + c];
        s += v; sq += v * v;
    }
    __shared__ float rs[256], rq[256];
    rs[tid] = s; rq[tid] = sq;
    __syncthreads();
    for (int o = 128; o > 0; o >>= 1) {
        if (tid < o) { rs[tid] += rs[tid + o]; rq[tid] += rq[tid + o]; }
        __syncthreads();
    }
    if (tid == 0) {
        float mean = rs[0] / (float)N;
        float var  = rq[0] / (float)N - mean * mean;
        float sc   = gamma[c] * rsqrtf(var + EPSV);
        g_bn[c]      = sc;
        g_bn[80 + c] = beta[c] - mean * sc;
    }
}

__global__ void __launch_bounds__(512) zero_h_kernel() {
    int i = blockIdx.x * blockDim.x + threadIdx.x;
    if (i < B_ * HIDN) g_hstate[0][i] = 0.f;
    if (i < USTEPS) g_sync[i] = 0u;
}

// ---------------- weight transpose + bf16 split: tcr_w [l][kin][512] -> wt[l][n][kin] ----------------
__global__ void __launch_bounds__(256) wsplit_kernel(const float* __restrict__ tcr_w) {
    __shared__ float tile[32][33];
    const int l  = blockIdx.z;
    const int k0 = blockIdx.x * 32;
    const int n0 = blockIdx.y * 32;
    const int tx = threadIdx.x, ty = threadIdx.y;   // 32 x 8
#pragma unroll
    for (int j = 0; j < 32; j += 8)
        tile[ty + j][tx] = tcr_w[((size_t)l * 2560 + k0 + ty + j) * 512 + n0 + tx];
    __syncthreads();
#pragma unroll
    for (int j = 0; j < 32; j += 8) {
        float v = tile[tx][ty + j];
        size_t di = ((size_t)l * 512 + n0 + ty + j) * 2560 + k0 + tx;
        __nv_bfloat16 h = __float2bfloat16(v);
        g_wt_hi[di] = h;
        g_wt_lo[di] = __float2bfloat16(v - __bfloat162float(h));
    }
}

// ---------------- conv0: implicit-im2col SGEMM 128x128x32 FFMA2 (+ split epilogue) ----------------
template<int CIN, int TIN, int TOUT, int STRIDE, int PADL, bool FUSE_BN, bool RESID, bool SPLIT>
__global__ void __launch_bounds__(256, 2) conv5x_kernel(const float* __restrict__ in,
                                                        const float* __restrict__ w,
                                                        const float* __restrict__ bias,
                                                        float* __restrict__ out,
                                                        __nv_bfloat16* __restrict__ ohi,
                                                        __nv_bfloat16* __restrict__ olo) {
    __shared__ __align__(16) float As[32][128];
    __shared__ __align__(16) float Bs[32][128];
    __shared__ __align__(16) float s_bn[160];

    const int tid = threadIdx.x;
    if (FUSE_BN && tid < 160) s_bn[tid] = g_bn[tid];

    const int n0 = blockIdx.x * 128;
    const int m0 = blockIdx.y * 128;
    const int tx = tid & 15;
    const int ty = tid >> 4;

    ull acc[4][8];
#pragma unroll
    for (int i = 0; i < 4; i++)
#pragma unroll
        for (int j = 0; j < 8; j++) acc[i][j] = 0ull;

    __syncthreads();

    const int KIN = 5 * CIN;
    for (int p0 = 0; p0 < KIN; p0 += 32) {
#pragma unroll
        for (int it = 0; it < 4; it++) {
            int s  = tid + it * 256;
            int kq = s & 7;
            int ml = s >> 3;
            int p  = p0 + (kq << 2);
            int k  = p / CIN;
            int ci = p - k * CIN;
            int m  = m0 + ml;
            int bb = m / TOUT;
            int t  = m - bb * TOUT;
            int tin = t * STRIDE - PADL + k;
            float4 av = make_float4(0.f, 0.f, 0.f, 0.f);
            if (tin >= 0 && tin < TIN && p < KIN) {
                av = *reinterpret_cast<const float4*>(in + ((size_t)bb * TIN + tin) * CIN + ci);
                if (FUSE_BN) {
                    float4 sc = *reinterpret_cast<const float4*>(&s_bn[ci]);
                    float4 sh = *reinterpret_cast<const float4*>(&s_bn[80 + ci]);
                    av.x = av.x * sc.x + sh.x;
                    av.y = av.y * sc.y + sh.y;
                    av.z = av.z * sc.z + sh.z;
                    av.w = av.w * sc.w + sh.w;
                }
            }
            int pc = ml ^ (kq << 2);
            As[(kq << 2) + 0][pc] = av.x;
            As[(kq << 2) + 1][pc] = av.y;
            As[(kq << 2) + 2][pc] = av.z;
            As[(kq << 2) + 3][pc] = av.w;
        }
#pragma unroll
        for (int it = 0; it < 4; it++) {
            int s  = tid + it * 256;
            int cq = s & 31;
            int kr = s >> 5;
            float4 v = make_float4(0.f, 0.f, 0.f, 0.f);
            if (p0 + kr < KIN)
                v = *reinterpret_cast<const float4*>(w + (size_t)(p0 + kr) * 512 + n0 + (cq << 2));
            *reinterpret_cast<float4*>(&Bs[kr][cq << 2]) = v;
        }
        __syncthreads();

#pragma unroll
        for (int kk = 0; kk < 32; kk++) {
            const int sw = (kk >> 2) << 2;
            ulonglong2 ap0 = *reinterpret_cast<const ulonglong2*>(&As[kk][(ty << 3) ^ sw]);
            ulonglong2 ap1 = *reinterpret_cast<const ulonglong2*>(&As[kk][((ty << 3) + 4) ^ sw]);
            ull ap[4] = {ap0.x, ap0.y, ap1.x, ap1.y};
            float4 bA = *reinterpret_cast<const float4*>(&Bs[kk][tx << 2]);
            float4 bB = *reinterpret_cast<const float4*>(&Bs[kk][64 + (tx << 2)]);
            ull bd[8];
            bd[0] = pack2(bA.x); bd[1] = pack2(bA.y); bd[2] = pack2(bA.z); bd[3] = pack2(bA.w);
            bd[4] = pack2(bB.x); bd[5] = pack2(bB.y); bd[6] = pack2(bB.z); bd[7] = pack2(bB.w);
#pragma unroll
            for (int mp = 0; mp < 4; mp++)
#pragma unroll
                for (int n = 0; n < 8; n++) fma2(acc[mp][n], ap[mp], bd[n]);
        }
        __syncthreads();
    }

    const int c0 = n0 + (tx << 2);
    const int c1 = n0 + 64 + (tx << 2);
    const float4 bias0 = *reinterpret_cast<const float4*>(bias + c0);
    const float4 bias1 = *reinterpret_cast<const float4*>(bias + c1);
    float2 u0[4][4], u1[4][4];
#pragma unroll
    for (int mp = 0; mp < 4; mp++)
#pragma unroll
        for (int n = 0; n < 4; n++) {
            u0[mp][n] = unpack2(acc[mp][n]);
            u1[mp][n] = unpack2(acc[mp][4 + n]);
        }
#pragma unroll
    for (int i = 0; i < 8; i++) {
        const int mp = i >> 1;
        const bool hi = i & 1;
        int m = m0 + (ty << 3) + i;
        float4 r0, r1;
        r0.x = fmaxf((hi ? u0[mp][0].y : u0[mp][0].x) + bias0.x, 0.f);
        r0.y = fmaxf((hi ? u0[mp][1].y : u0[mp][1].x) + bias0.y, 0.f);
        r0.z = fmaxf((hi ? u0[mp][2].y : u0[mp][2].x) + bias0.z, 0.f);
        r0.w = fmaxf((hi ? u0[mp][3].y : u0[mp][3].x) + bias0.w, 0.f);
        r1.x = fmaxf((hi ? u1[mp][0].y : u1[mp][0].x) + bias1.x, 0.f);
        r1.y = fmaxf((hi ? u1[mp][1].y : u1[mp][1].x) + bias1.y, 0.f);
        r1.z = fmaxf((hi ? u1[mp][2].y : u1[mp][2].x) + bias1.z, 0.f);
        r1.w = fmaxf((hi ? u1[mp][3].y : u1[mp][3].x) + bias1.w, 0.f);
        if (RESID) {
            float4 e0 = *reinterpret_cast<const float4*>(in + (size_t)m * CIN + c0);
            float4 e1 = *reinterpret_cast<const float4*>(in + (size_t)m * CIN + c1);
            r0.x += e0.x; r0.y += e0.y; r0.z += e0.z; r0.w += e0.w;
            r1.x += e1.x; r1.y += e1.y; r1.z += e1.z; r1.w += e1.w;
        }
        *reinterpret_cast<float4*>(out + (size_t)m * 512 + c0) = r0;
        *reinterpret_cast<float4*>(out + (size_t)m * 512 + c1) = r1;
        if (SPLIT) {
            uint2 h4, l4;
            split4(r0, h4, l4);
            *reinterpret_cast<uint2*>(ohi + (size_t)m * 512 + c0) = h4;
            *reinterpret_cast<uint2*>(olo + (size_t)m * 512 + c0) = l4;
            split4(r1, h4, l4);
            *reinterpret_cast<uint2*>(ohi + (size_t)m * 512 + c1) = h4;
            *reinterpret_cast<uint2*>(olo + (size_t)m * 512 + c1) = l4;
        }
    }
}

// ---------------- tcr conv layer on mma.sync, 2-stage cp.async pipeline ----------------
// CTA 128x128, 8 warps (4m x 2n). K-chunk 32 (80 chunks), double-buffered dynamic smem.
// B stored [n][k] -> non-trans ldmatrix yields the .col B fragment directly.
#define ASTR 40
#define BUFB (128 * ASTR * 2)     // 10240 B per buffer
#define STAGEB (4 * BUFB)         // 40960 B per stage (Ah, Al, Bh, Bl)
#define TCR_DSMEM (2 * STAGEB)    // 81920 B
template<bool SPLIT>
__global__ void __launch_bounds__(256, 2) tcr_mma_kernel(const __nv_bfloat16* __restrict__ ahi,
                                                         const __nv_bfloat16* __restrict__ alo,
                                                         const __nv_bfloat16* __restrict__ whi,
                                                         const __nv_bfloat16* __restrict__ wlo,
                                                         const float* __restrict__ resid_in,
                                                         const float* __restrict__ bias,
                                                         float* __restrict__ out,
                                                         __nv_bfloat16* __restrict__ ohi,
                                                         __nv_bfloat16* __restrict__ olo) {
    extern __shared__ __align__(16) uint8_t dsm[];
    const uint32_t base = smem_to_u32(dsm);

    const int tid = threadIdx.x;
    const int wid = tid >> 5, lane = tid & 31;
    const int n0 = blockIdx.x * 128;
    const int m0 = blockIdx.y * 128;
    const int warp_m = (wid >> 1) << 5;    // 0,32,64,96
    const int warp_n = (wid & 1) << 6;     // 0,64

    float acc[2][8][4];
#pragma unroll
    for (int i = 0; i < 2; i++)
#pragma unroll
        for (int j = 0; j < 8; j++)
#pragma unroll
            for (int r = 0; r < 4; r++) acc[i][j][r] = 0.f;

    const int lq = tid & 3;
    const int lrow = tid >> 2;

    const uint32_t aoff = (warp_m + (lane & 15)) * 80 + (lane >> 4) * 16;
    const int browoff = warp_n + (lane & 7) + ((lane >> 4) & 1) * 8;
    const uint32_t boff = browoff * 80 + ((lane >> 3) & 1) * 16;

    // per-chunk async load into stage st
    auto issue = [&](int c, int st) {
        const int tap = c >> 4;
        const int ci0 = (c & 15) << 5;
        const uint32_t sb = base + st * STAGEB;
#pragma unroll
        for (int it = 0; it < 2; it++) {
            int ml = lrow + it * 64;
            int m  = m0 + ml;
            int bb = m / T1;
            int t  = m - bb * T1;
            int tin = t + tap - 2;
            bool v = (tin >= 0 && tin < T1);
            size_t src = ((size_t)bb * T1 + (v ? tin : 0)) * 512 + ci0 + lq * 8;
            uint32_t doff = (uint32_t)(ml * ASTR + lq * 8) * 2;
            cp16(sb + doff,        ahi + src, v ? 16 : 0);
            cp16(sb + BUFB + doff, alo + src, v ? 16 : 0);
        }
#pragma unroll
        for (int it = 0; it < 2; it++) {
            int nl = lrow + it * 64;
            size_t src = (size_t)(n0 + nl) * 2560 + c * 32 + lq * 8;
            uint32_t doff = (uint32_t)(nl * ASTR + lq * 8) * 2;
            cp16(sb + 2 * BUFB + doff, whi + src, 16);
            cp16(sb + 3 * BUFB + doff, wlo + src, 16);
        }
        CP_COMMIT();
    };

    issue(0, 0);
    for (int c = 0; c < 80; c++) {
        const int st = c & 1;
        if (c + 1 < 80) {
            issue(c + 1, (c + 1) & 1);
            asm volatile("cp.async.wait_group 1;" ::: "memory");
        } else {
            asm volatile("cp.async.wait_group 0;" ::: "memory");
        }
        __syncthreads();

        const uint32_t sb = base + st * STAGEB;
        const uint32_t aH = sb + aoff;
        const uint32_t aL = sb + BUFB + aoff;
        const uint32_t bH = sb + 2 * BUFB + boff;
        const uint32_t bL = sb + 3 * BUFB + boff;
#pragma unroll
        for (int s = 0; s < 2; s++) {
            uint32_t ah[2][4], al[2][4];
            ldsm4(ah[0], aH + s * 32);
            ldsm4(ah[1], aH + s * 32 + 16 * 80);
            ldsm4(al[0], aL + s * 32);
            ldsm4(al[1], aL + s * 32 + 16 * 80);
#pragma unroll
            for (int jj = 0; jj < 4; jj++) {
                uint32_t bh[4], bl[4];
                ldsm4(bh, bH + s * 32 + jj * 16 * 80);
                ldsm4(bl, bL + s * 32 + jj * 16 * 80);
#pragma unroll
                for (int i = 0; i < 2; i++) {
                    mma_bf16(acc[i][2 * jj],     ah[i], bh);
                    mma_bf16(acc[i][2 * jj],     ah[i], bl);
                    mma_bf16(acc[i][2 * jj],     al[i], bh);
                    mma_bf16(acc[i][2 * jj + 1], ah[i], bh + 2);
                    mma_bf16(acc[i][2 * jj + 1], ah[i], bl + 2);
                    mma_bf16(acc[i][2 * jj + 1], al[i], bh + 2);
                }
            }
        }
        __syncthreads();
    }

    // ---- epilogue: bias + relu + residual (+ split) ----
    const int r0 = lane >> 2;
    const int cc = (lane & 3) * 2;
#pragma unroll
    for (int i = 0; i < 2; i++) {
        int mrow = m0 + warp_m + i * 16 + r0;
#pragma unroll
        for (int j = 0; j < 8; j++) {
            int col = n0 + warp_n + j * 8 + cc;
            float2 b2 = *reinterpret_cast<const float2*>(bias + col);
#pragma unroll
            for (int half = 0; half < 2; half++) {
                int m = mrow + half * 8;
                float va = acc[i][j][half * 2 + 0];
                float vb = acc[i][j][half * 2 + 1];
                float2 e = *reinterpret_cast<const float2*>(resid_in + (size_t)m * 512 + col);
                float2 v;
                v.x = fmaxf(va + b2.x, 0.f) + e.x;
                v.y = fmaxf(vb + b2.y, 0.f) + e.y;
                *reinterpret_cast<float2*>(out + (size_t)m * 512 + col) = v;
                if (SPLIT) {
                    uint h2, l2;
                    split2(v.x, v.y, h2, l2);
                    *reinterpret_cast<uint*>(ohi + (size_t)m * 512 + col) = h2;
                    *reinterpret_cast<uint*>(olo + (size_t)m * 512 + col) = l2;
                }
            }
        }
    }
}

// ---------------- Fused GRU step: partials + grid barrier + gates, ONE kernel ----------------
// grid (12 n-tiles, 4 k-splits) = 48 co-resident blocks (<=148 SMs).
__global__ void __launch_bounds__(256) gru_step_kernel(const float* __restrict__ grk,
                                                       const int* __restrict__ y,
                                                       const float* __restrict__ gk,
                                                       const float* __restrict__ gb,
                                                       int u) {
    __shared__ float Hs[16][33];
    __shared__ __align__(16) float Ws[16][128];
    const float* h = g_hstate[u & 1];
    const int tid = threadIdx.x;
    const int n0 = blockIdx.x * 128;
    const int kb = blockIdx.y * 128;
    const int bid = blockIdx.y * 12 + blockIdx.x;
    const int nx = tid & 31;
    const int my = tid >> 5;

    ull acc[4][2];
#pragma unroll
    for (int i = 0; i < 4; i++) { acc[i][0] = 0ull; acc[i][1] = 0ull; }

    for (int k0 = 0; k0 < 128; k0 += 16) {
#pragma unroll
        for (int it = 0; it < 2; it++) {
            int e = tid + it * 256;
            int kk = e & 15, m = e >> 4;
            Hs[kk][m] = h[m * 512 + kb + k0 + kk];
        }
#pragma unroll
        for (int it = 0; it < 2; it++) {
            int s = tid + it * 256;
            int cq = s & 31, kr = s >> 5;
            *reinterpret_cast<float4*>(&Ws[kr][cq << 2]) =
                *reinterpret_cast<const float4*>(grk + (size_t)(kb + k0 + kr) * 1536 + n0 + (cq << 2));
        }
        __syncthreads();
#pragma unroll
        for (int kk = 0; kk < 16; kk++) {
            ulonglong2 bp = *reinterpret_cast<const ulonglong2*>(&Ws[kk][nx << 2]);
#pragma unroll
            for (int i = 0; i < 4; i++) {
                ull ad = pack2(Hs[kk][(my << 2) + i]);
                fma2(acc[i][0], ad, bp.x);
                fma2(acc[i][1], ad, bp.y);
            }
        }
        __syncthreads();
    }
    float* outp = g_mhp[blockIdx.y];
#pragma unroll
    for (int i = 0; i < 4; i++) {
        float2 v0 = unpack2(acc[i][0]);
        float2 v1 = unpack2(acc[i][1]);
        *reinterpret_cast<float4*>(&outp[((my << 2) + i) * 1536 + n0 + (nx << 2)]) =
            make_float4(v0.x, v0.y, v1.x, v1.y);
    }

    // ---- grid barrier (48 resident blocks) ----
    __threadfence();
    __syncthreads();
    if (bid >= 32) {
        if (tid == 0) atomicAdd(&g_sync[u], 1u);
        return;
    }
    if (tid == 0) {
        atomicAdd(&g_sync[u], 1u);
        while (atomicAdd(&g_sync[u], 0u) < 48u) { __nanosleep(64); }
    }
    __syncthreads();
    __threadfence();

    // ---- gates: block bid handles batch b = bid; threads cover j and j+256 ----
    const int b = bid;
    const float* bi = gb;
    const float* br = gb + 1536;
    const int tok   = y[b * 201 + u];
    const float* gx = gk + (size_t)tok * 1536;
    const float* hold = g_hstate[u & 1] + b * 512;
    float* hnew     = g_hstate[(u + 1) & 1] + b * 512;
    float* catrow   = g_catall + ((size_t)u * 32 + b) * 1024;
#pragma unroll
    for (int it = 0; it < 2; it++) {
        int j = tid + it * 256;
        float hz = 0.f, hr = 0.f, hh = 0.f;
#pragma unroll
        for (int c = 0; c < 4; c++) {
            const float* p = g_mhp[c] + b * 1536;
            hz += p[j];
            hr += p[512 + j];
            hh += p[1024 + j];
        }
        float xz = gx[j]        + bi[j];
        float xr = gx[512 + j]  + bi[512 + j];
        float xh = gx[1024 + j] + bi[1024 + j];
        hz += br[j];
        hr += br[512 + j];
        hh += br[1024 + j];
        float z = 1.f / (1.f + expf(-(xz + hz)));
        float r = 1.f / (1.f + expf(-(xr + hr)));
        float cand = tanhf(xh + r * hh);
        float hn = z * hold[j] + (1.f - z) * cand;
        hnew[j] = hn;
        catrow[j] = hn;
    }
}

// ---------------- Batched scores GEMM: per b, S[200,800] = H[200,512] @ enc_b^T ----------------
__global__ void __launch_bounds__(256, 2) scores_gemm_kernel() {
    __shared__ __align__(16) float As[16][128];
    __shared__ __align__(16) float Bs[16][128];
    const int tid = threadIdx.x;
    const int n0 = blockIdx.x * 128;
    const int m0 = blockIdx.y * 128;
    const int b  = blockIdx.z;
    const int tx = tid & 15;
    const int ty = tid >> 4;

    ull acc[8][4];
#pragma unroll
    for (int i = 0; i < 8; i++)
#pragma unroll
        for (int j = 0; j < 4; j++) acc[i][j] = 0ull;

    for (int k0 = 0; k0 < 512; k0 += 16) {
#pragma unroll
        for (int it = 0; it < 2; it++) {
            int s  = tid + it * 256;
            int kq = s & 3;
            int ml = s >> 2;
            int urow = m0 + ml;
            float4 av = make_float4(0.f, 0.f, 0.f, 0.f);
            if (urow < USTEPS)
                av = *reinterpret_cast<const float4*>(
                    g_catall + ((size_t)urow * 32 + b) * 1024 + k0 + (kq << 2));
            int pc = ml ^ (kq << 2);
            As[(kq << 2) + 0][pc] = av.x;
            As[(kq << 2) + 1][pc] = av.y;
            As[(kq << 2) + 2][pc] = av.z;
            As[(kq << 2) + 3][pc] = av.w;
        }
#pragma unroll
        for (int it = 0; it < 2; it++) {
            int s  = tid + it * 256;
            int dq = s & 3;
            int tl = s >> 2;
            int t  = n0 + tl;
            float4 bv = make_float4(0.f, 0.f, 0.f, 0.f);
            if (t < T1)
                bv = *reinterpret_cast<const float4*>(
                    g_h1 + ((size_t)b * T1 + t) * 512 + k0 + (dq << 2));
            int pc = tl ^ (dq << 2);
            Bs[(dq << 2) + 0][pc] = bv.x;
            Bs[(dq << 2) + 1][pc] = bv.y;
            Bs[(dq << 2) + 2][pc] = bv.z;
            Bs[(dq << 2) + 3][pc] = bv.w;
        }
        __syncthreads();

#pragma unroll
        for (int kk = 0; kk < 16; kk++) {
            const int sw = (kk >> 2) << 2;
            float4 a0 = *reinterpret_cast<const float4*>(&As[kk][(ty << 3) ^ sw]);
            float4 a1 = *reinterpret_cast<const float4*>(&As[kk][((ty << 3) + 4) ^ sw]);
            ulonglong2 bp0 = *reinterpret_cast<const ulonglong2*>(&Bs[kk][(tx << 3) ^ sw]);
            ulonglong2 bp1 = *reinterpret_cast<const ulonglong2*>(&Bs[kk][((tx << 3) + 4) ^ sw]);
            ull b0 = bp0.x, b1 = bp0.y, b2 = bp1.x, b3 = bp1.y;
            float av[8] = {a0.x, a0.y, a0.z, a0.w, a1.x, a1.y, a1.z, a1.w};
#pragma unroll
            for (int i = 0; i < 8; i++) {
                ull a2 = pack2(av[i]);
                fma2(acc[i][0], a2, b0);
                fma2(acc[i][1], a2, b1);
                fma2(acc[i][2], a2, b2);
                fma2(acc[i][3], a2, b3);
            }
        }
        __syncthreads();
    }

    const int t0 = n0 + (tx << 3);
#pragma unroll
    for (int i = 0; i < 8; i++) {
        int urow = m0 + (ty << 3) + i;
        if (urow < USTEPS && t0 < T1) {
            float2 p0v = unpack2(acc[i][0]);
            float2 p1v = unpack2(acc[i][1]);
            float2 p2v = unpack2(acc[i][2]);
            float2 p3v = unpack2(acc[i][3]);
            float* sp = g_scoresall + ((size_t)urow * 32 + b) * T1 + t0;
            *reinterpret_cast<float4*>(sp)     = make_float4(p0v.x, p0v.y, p1v.x, p1v.y);
            *reinterpret_cast<float4*>(sp + 4) = make_float4(p2v.x, p2v.y, p3v.x, p3v.y);
        }
    }
}

// ---------------- Batched softmax over 800 ----------------
__global__ void __launch_bounds__(256) sm800_kernel() {
    const int row = blockIdx.x;
    const int tid = threadIdx.x;
    float* sp = g_scoresall + (size_t)row * T1;
    __shared__ float sa[800];
    __shared__ float red[8], red2[8];
    const int w = tid >> 5, lane = tid & 31;

    float m = -1e30f;
    for (int t = tid; t < 800; t += 256) {
        float v = sp[t];
        sa[t] = v;
        m = fmaxf(m, v);
    }
#pragma unroll
    for (int o = 16; o; o >>= 1) m = fmaxf(m, __shfl_xor_sync(0xffffffffu, m, o));
    if (lane == 0) red[w] = m;
    __syncthreads();
    float mm = red[0];
#pragma unroll
    for (int i = 1; i < 8; i++) mm = fmaxf(mm, red[i]);

    float ps = 0.f;
    for (int t = tid; t < 800; t += 256) {
        float e = expf(sa[t] - mm);
        sa[t] = e;
        ps += e;
    }
#pragma unroll
    for (int o = 16; o; o >>= 1) ps += __shfl_xor_sync(0xffffffffu, ps, o);
    if (lane == 0) red2[w] = ps;
    __syncthreads();
    float sum = 0.f;
#pragma unroll
    for (int i = 0; i < 8; i++) sum += red2[i];
    const float inv = 1.f / sum;

    for (int t = tid; t < 800; t += 256) sp[t] = sa[t] * inv;
}

// ---------------- Batched ctx: per b, alpha[200,800] @ enc_b[800,512] ----------------
__global__ void __launch_bounds__(256, 2) ctx_gemm_kernel() {
    __shared__ __align__(16) float As[16][128];
    __shared__ __align__(16) float Bs[16][128];
    const int tid = threadIdx.x;
    const int n0 = blockIdx.x * 128;
    const int m0 = blockIdx.y * 128;
    const int b  = blockIdx.z;
    const int tx = tid & 15;
    const int ty = tid >> 4;

    ull acc[8][4];
#pragma unroll
    for (int i = 0; i < 8; i++)
#pragma unroll
        for (int j = 0; j < 4; j++) acc[i][j] = 0ull;

    for (int k0 = 0; k0 < 800; k0 += 16) {
#pragma unroll
        for (int it = 0; it < 2; it++) {
            int s  = tid + it * 256;
            int kq = s & 3;
            int ml = s >> 2;
            int u  = m0 + ml;
            float4 av = make_float4(0.f, 0.f, 0.f, 0.f);
            if (u < USTEPS)
                av = *reinterpret_cast<const float4*>(
                    g_scoresall + ((size_t)u * 32 + b) * T1 + k0 + (kq << 2));
            As[(kq << 2) + 0][ml] = av.x;
            As[(kq << 2) + 1][ml] = av.y;
            As[(kq << 2) + 2][ml] = av.z;
            As[(kq << 2) + 3][ml] = av.w;
        }
#pragma unroll
        for (int it = 0; it < 2; it++) {
            int s  = tid + it * 256;
            int cq = s & 31;
            int kr = s >> 5;
            *reinterpret_cast<float4*>(&Bs[kr][cq << 2]) =
                *reinterpret_cast<const float4*>(
                    g_h1 + ((size_t)b * T1 + k0 + kr) * 512 + n0 + (cq << 2));
        }
        __syncthreads();

#pragma unroll
        for (int kk = 0; kk < 16; kk++) {
            float4 a0 = *reinterpret_cast<const float4*>(&As[kk][ty << 3]);
            float4 a1 = *reinterpret_cast<const float4*>(&As[kk][(ty << 3) + 4]);
            ulonglong2 bp0 = *reinterpret_cast<const ulonglong2*>(&Bs[kk][(tx << 3)]);
            ulonglong2 bp1 = *reinterpret_cast<const ulonglong2*>(&Bs[kk][(tx << 3) + 4]);
            ull b0 = bp0.x, b1 = bp0.y, b2 = bp1.x, b3 = bp1.y;
            float av[8] = {a0.x, a0.y, a0.z, a0.w, a1.x, a1.y, a1.z, a1.w};
#pragma unroll
            for (int i = 0; i < 8; i++) {
                ull a2 = pack2(av[i]);
                fma2(acc[i][0], a2, b0);
                fma2(acc[i][1], a2, b1);
                fma2(acc[i][2], a2, b2);
                fma2(acc[i][3], a2, b3);
            }
        }
        __syncthreads();
    }

#pragma unroll
    for (int i = 0; i < 8; i++) {
        int u = m0 + (ty << 3) + i;
        if (u < USTEPS) {
            float2 p0v = unpack2(acc[i][0]);
            float2 p1v = unpack2(acc[i][1]);
            float2 p2v = unpack2(acc[i][2]);
            float2 p3v = unpack2(acc[i][3]);
            float* cp = g_catall + ((size_t)u * 32 + b) * 1024 + 512 + n0 + (tx << 3);
            *reinterpret_cast<float4*>(cp)     = make_float4(p0v.x, p0v.y, p1v.x, p1v.y);
            *reinterpret_cast<float4*>(cp + 4) = make_float4(p2v.x, p2v.y, p3v.x, p3v.y);
        }
    }
}

// ---------------- Batched FC ----------------
__global__ void __launch_bounds__(256, 2) fc_big_kernel(const float* __restrict__ fw,
                                                        const float* __restrict__ fb) {
    __shared__ __align__(16) float As[16][128];
    __shared__ __align__(16) float Bs[16][128];
    const int tid = threadIdx.x;
    const int n0 = blockIdx.x * 128;
    const int m0 = blockIdx.y * 128;
    const int tx = tid & 15;
    const int ty = tid >> 4;

    ull acc[8][4];
#pragma unroll
    for (int i = 0; i < 8; i++)
#pragma unroll
        for (int j = 0; j < 4; j++) acc[i][j] = 0ull;

    for (int p0 = 0; p0 < 1024; p0 += 16) {
#pragma unroll
        for (int it = 0; it < 2; it++) {
            int s  = tid + it * 256;
            int kq = s & 3;
            int ml = s >> 2;
            float4 av = *reinterpret_cast<const float4*>(
                g_catall + ((size_t)(m0 + ml)) * 1024 + p0 + (kq << 2));
            As[(kq << 2) + 0][ml] = av.x;
            As[(kq << 2) + 1][ml] = av.y;
            As[(kq << 2) + 2][ml] = av.z;
            As[(kq << 2) + 3][ml] = av.w;
        }
#pragma unroll
        for (int it = 0; it < 2; it++) {
            int s  = tid + it * 256;
            int cq = s & 31;
            int kr = s >> 5;
            int c  = n0 + (cq << 2);
            float4 v = make_float4(0.f, 0.f, 0.f, 0.f);
            if (c < 1000)
                v = *reinterpret_cast<const float4*>(fw + (size_t)(p0 + kr) * 1000 + c);
            *reinterpret_cast<float4*>(&Bs[kr][cq << 2]) = v;
        }
        __syncthreads();

#pragma unroll
        for (int kk = 0; kk < 16; kk++) {
            float4 a0 = *reinterpret_cast<const float4*>(&As[kk][ty << 3]);
            float4 a1 = *reinterpret_cast<const float4*>(&As[kk][(ty << 3) + 4]);
            ulonglong2 bp0 = *reinterpret_cast<const ulonglong2*>(&Bs[kk][(tx << 3)]);
            ulonglong2 bp1 = *reinterpret_cast<const ulonglong2*>(&Bs[kk][(tx << 3) + 4]);
            ull b0 = bp0.x, b1 = bp0.y, b2 = bp1.x, b3 = bp1.y;
            float av[8] = {a0.x, a0.y, a0.z, a0.w, a1.x, a1.y, a1.z, a1.w};
#pragma unroll
            for (int i = 0; i < 8; i++) {
                ull a2 = pack2(av[i]);
                fma2(acc[i][0], a2, b0);
                fma2(acc[i][1], a2, b1);
                fma2(acc[i][2], a2, b2);
                fma2(acc[i][3], a2, b3);
            }
        }
        __syncthreads();
    }

    const int c0 = n0 + (tx << 3);
    float bias[8];
#pragma unroll
    for (int j = 0; j < 8; j++) bias[j] = (c0 + j < 1000) ? fb[c0 + j] : 0.f;
#pragma unroll
    for (int i = 0; i < 8; i++) {
        int m = m0 + (ty << 3) + i;
        float2 p0v = unpack2(acc[i][0]);
        float2 p1v = unpack2(acc[i][1]);
        float2 p2v = unpack2(acc[i][2]);
        float2 p3v = unpack2(acc[i][3]);
        float4 r0 = make_float4(p0v.x + bias[0], p0v.y + bias[1], p1v.x + bias[2], p1v.y + bias[3]);
        float4 r1 = make_float4(p2v.x + bias[4], p2v.y + bias[5], p3v.x + bias[6], p3v.y + bias[7]);
        float* lp = g_logitsall + (size_t)m * 1000;
        if (c0 < 1000)     *reinterpret_cast<float4*>(lp + c0)     = r0;
        if (c0 + 4 < 1000) *reinterpret_cast<float4*>(lp + c0 + 4) = r1;
    }
}

// ---------------- Batched output softmax ----------------
__global__ void __launch_bounds__(256) outsm_all_kernel(float* __restrict__ out) {
    const int m = blockIdx.x;
    const int u = m >> 5, b = m & 31;
    const int tid = threadIdx.x;
    __shared__ float sh[1000];
    __shared__ float red[8], red2[8];
    const int w = tid >> 5, lane = tid & 31;
    const float* lp = g_logitsall + (size_t)m * 1000;

    float mx = -1e30f;
    for (int c = tid; c < 1000; c += 256) {
        float v = lp[c];
        sh[c] = v;
        mx = fmaxf(mx, v);
    }
#pragma unroll
    for (int o = 16; o; o >>= 1) mx = fmaxf(mx, __shfl_xor_sync(0xffffffffu, mx, o));
    if (lane == 0) red[w] = mx;
    __syncthreads();
    float mm = red[0];
#pragma unroll
    for (int i = 1; i < 8; i++) mm = fmaxf(mm, red[i]);

    float ps = 0.f;
    for (int c = tid; c < 1000; c += 256) {
        float e = expf(sh[c] - mm);
        sh[c] = e;
        ps += e;
    }
#pragma unroll
    for (int o = 16; o; o >>= 1) ps += __shfl_xor_sync(0xffffffffu, ps, o);
    if (lane == 0) red2[w] = ps;
    __syncthreads();
    float sum = 0.f;
#pragma unroll
    for (int i = 0; i < 8; i++) sum += red2[i];
    const float inv = 1.f / sum;

    float* op = out + ((size_t)b * USTEPS + u) * VOCABN;
    for (int c = tid; c < 1000; c += 256) op[c] = sh[c] * inv;
}

// ---------------- launch ----------------
extern "C" void kernel_launch(void* const* d_in, const int* in_sizes, int n_in,
                              void* d_out, int out_size) {
    const float* x        = (const float*)d_in[0];
    const int*   y        = (const int*)  d_in[1];
    const float* bn_gamma = (const float*)d_in[2];
    const float* bn_beta  = (const float*)d_in[3];
    const float* conv0_w  = (const float*)d_in[4];
    const float* conv0_b  = (const float*)d_in[5];
    const float* tcr_w    = (const float*)d_in[6];
    const float* tcr_b    = (const float*)d_in[7];
    const float* gru_k    = (const float*)d_in[8];
    const float* gru_rk   = (const float*)d_in[9];
    const float* gru_b    = (const float*)d_in[10];
    const float* fc_w     = (const float*)d_in[11];
    const float* fc_b     = (const float*)d_in[12];
    float* out = (float*)d_out;

    float *h1, *h2;
    __nv_bfloat16 *shi0, *slo0, *shi1, *slo1, *wth, *wtl;
    cudaGetSymbolAddress((void**)&h1, g_h1);
    cudaGetSymbolAddress((void**)&h2, g_h2);
    cudaGetSymbolAddress((void**)&shi0, g_shi0);
    cudaGetSymbolAddress((void**)&slo0, g_slo0);
    cudaGetSymbolAddress((void**)&shi1, g_shi1);
    cudaGetSymbolAddress((void**)&slo1, g_slo1);
    cudaGetSymbolAddress((void**)&wth, g_wt_hi);
    cudaGetSymbolAddress((void**)&wtl, g_wt_lo);

    cudaFuncSetAttribute(tcr_mma_kernel<true>,  cudaFuncAttributeMaxDynamicSharedMemorySize, TCR_DSMEM);
    cudaFuncSetAttribute(tcr_mma_kernel<false>, cudaFuncAttributeMaxDynamicSharedMemorySize, TCR_DSMEM);

    // ---- encoder ----
    bn_stats_kernel<<<80, 256>>>(x, bn_gamma, bn_beta);
    zero_h_kernel<<<32, 512>>>();
    dim3 wgrid(80, 16, 4);          // 2560/32, 512/32, 4 layers
    wsplit_kernel<<<wgrid, dim3(32, 8)>>>(tcr_w);

    dim3 cgrid(4, 200);
    conv5x_kernel<80, 1600, 800, 2, 1, true, false, true><<<cgrid, 256>>>(
        x, conv0_w, conv0_b, h1, shi0, slo0);

    const size_t WT = (size_t)512 * 2560;
    dim3 tgrid(4, 200);
    tcr_mma_kernel<true><<<tgrid, 256, TCR_DSMEM>>>(
        shi0, slo0, wth + 0 * WT, wtl + 0 * WT, h1, tcr_b + 0 * 512, h2, shi1, slo1);
    tcr_mma_kernel<true><<<tgrid, 256, TCR_DSMEM>>>(
        shi1, slo1, wth + 1 * WT, wtl + 1 * WT, h2, tcr_b + 1 * 512, h1, shi0, slo0);
    tcr_mma_kernel<true><<<tgrid, 256, TCR_DSMEM>>>(
        shi0, slo0, wth + 2 * WT, wtl + 2 * WT, h1, tcr_b + 2 * 512, h2, shi1, slo1);
    tcr_mma_kernel<false><<<tgrid, 256, TCR_DSMEM>>>(
        shi1, slo1, wth + 3 * WT, wtl + 3 * WT, h2, tcr_b + 3 * 512, h1, nullptr, nullptr);
    // enc lives in g_h1 (fp32)

    // ---- GRU recurrence: ONE fused kernel per step ----
    dim3 pgrid(12, 4);
    for (int u = 0; u < USTEPS; u++) {
        gru_step_kernel<<<pgrid, 256>>>(gru_rk, y, gru_k, gru_b, u);
    }

    // ---- batched tail ----
    dim3 sgrid(7, 2, 32);
    scores_gemm_kernel<<<sgrid, 256>>>();
    sm800_kernel<<<USTEPS * B_, 256>>>();
    dim3 xgrid(4, 2, 32);
    ctx_gemm_kernel<<<xgrid, 256>>>();
    dim3 fgrid(8, 50);
    fc_big_kernel<<<fgrid, 256>>>(fc_w, fc_b);
    outsm_all_kernel<<<USTEPS * B_, 256>>>(out);
}

// round 11
// speedup vs baseline: 1.1884x; 1.1884x over previous
#include <cuda_runtime.h>
#include <cuda_bf16.h>
#include <cstdint>
#include <math.h>

typedef unsigned long long ull;
typedef unsigned int uint;

#define B_     32
#define T0     1600
#define C0     80
#define T1     800
#define D_     512
#define VOCABN 1000
#define HIDN   512
#define USTEPS 200
#define EPSV   1e-3f

// ---------------- scratch (static device globals; no allocation) ----------------
__device__ float g_bn[160];
__device__ float g_h1[B_ * T1 * D_];                // fp32 activations (enc ends here)
__device__ float g_h2[B_ * T1 * D_];
__device__ float g_hstate[2][B_ * HIDN];
__device__ float g_mhp[8][B_ * 1536];               // k-split partials of h @ grk
__device__ float g_scoresall[USTEPS * B_ * T1];
__device__ float g_catall[USTEPS * B_ * 1024];
__device__ float g_logitsall[USTEPS * B_ * VOCABN];
// bf16 split activations (ping-pong) and split transposed weights
__device__ __nv_bfloat16 g_shi0[B_ * T1 * D_];
__device__ __nv_bfloat16 g_slo0[B_ * T1 * D_];
__device__ __nv_bfloat16 g_shi1[B_ * T1 * D_];
__device__ __nv_bfloat16 g_slo1[B_ * T1 * D_];
__device__ __nv_bfloat16 g_wt_hi[4 * 512 * 2560];   // [l][n][kin]
__device__ __nv_bfloat16 g_wt_lo[4 * 512 * 2560];

// ---------------- packed f32x2 helpers (FFMA2) ----------------
__device__ __forceinline__ void fma2(ull& d, ull a, ull b) {
    asm("fma.rn.f32x2 %0, %1, %2, %0;" : "+l"(d) : "l"(a), "l"(b));
}
__device__ __forceinline__ ull pack2(float x) {
    ull r;
    asm("mov.b64 %0, {%1, %1};" : "=l"(r) : "f"(x));
    return r;
}
__device__ __forceinline__ float2 unpack2(ull v) {
    float2 f;
    asm("mov.b64 {%0, %1}, %2;" : "=f"(f.x), "=f"(f.y) : "l"(v));
    return f;
}

// ---------------- bf16 split helpers ----------------
__device__ __forceinline__ void split4(float4 v, uint2& hi, uint2& lo) {
    __nv_bfloat16 h0 = __float2bfloat16(v.x), h1 = __float2bfloat16(v.y);
    __nv_bfloat16 h2 = __float2bfloat16(v.z), h3 = __float2bfloat16(v.w);
    __nv_bfloat16 l0 = __float2bfloat16(v.x - __bfloat162float(h0));
    __nv_bfloat16 l1 = __float2bfloat16(v.y - __bfloat162float(h1));
    __nv_bfloat16 l2 = __float2bfloat16(v.z - __bfloat162float(h2));
    __nv_bfloat16 l3 = __float2bfloat16(v.w - __bfloat162float(h3));
    hi.x = (uint)__bfloat16_as_ushort(h0) | ((uint)__bfloat16_as_ushort(h1) << 16);
    hi.y = (uint)__bfloat16_as_ushort(h2) | ((uint)__bfloat16_as_ushort(h3) << 16);
    lo.x = (uint)__bfloat16_as_ushort(l0) | ((uint)__bfloat16_as_ushort(l1) << 16);
    lo.y = (uint)__bfloat16_as_ushort(l2) | ((uint)__bfloat16_as_ushort(l3) << 16);
}
__device__ __forceinline__ void split2(float x, float y, uint& hi, uint& lo) {
    __nv_bfloat16 hx = __float2bfloat16(x), hy = __float2bfloat16(y);
    __nv_bfloat16 lx = __float2bfloat16(x - __bfloat162float(hx));
    __nv_bfloat16 ly = __float2bfloat16(y - __bfloat162float(hy));
    hi = (uint)__bfloat16_as_ushort(hx) | ((uint)__bfloat16_as_ushort(hy) << 16);
    lo = (uint)__bfloat16_as_ushort(lx) | ((uint)__bfloat16_as_ushort(ly) << 16);
}

// ---------------- mma.sync / ldmatrix helpers (sm_80+ portable) ----------------
__device__ __forceinline__ uint32_t smem_to_u32(const void* p) {
    uint32_t a;
    asm("{ .reg .u64 t; cvta.to.shared.u64 t, %1; cvt.u32.u64 %0, t; }" : "=r"(a) : "l"(p));
    return a;
}
__device__ __forceinline__ void mma_bf16(float* d, const uint32_t* a, const uint32_t* b) {
    asm volatile(
        "mma.sync.aligned.m16n8k16.row.col.f32.bf16.bf16.f32 "
        "{%0,%1,%2,%3}, {%4,%5,%6,%7}, {%8,%9}, {%0,%1,%2,%3};"
        : "+f"(d[0]), "+f"(d[1]), "+f"(d[2]), "+f"(d[3])
        : "r"(a[0]), "r"(a[1]), "r"(a[2]), "r"(a[3]), "r"(b[0]), "r"(b[1]));
}
__device__ __forceinline__ void ldsm4(uint32_t* r, uint32_t addr) {
    asm volatile("ldmatrix.sync.aligned.m8n8.x4.shared.b16 {%0,%1,%2,%3}, [%4];"
                 : "=r"(r[0]), "=r"(r[1]), "=r"(r[2]), "=r"(r[3]) : "r"(addr));
}

// ---------------- BatchNorm statistics ----------------
__global__ void __launch_bounds__(256) bn_stats_kernel(const float* __restrict__ x,
                                                       const float* __restrict__ gamma,
                                                       const float* __restrict__ beta) {
    const int c = blockIdx.x;
    const int tid = threadIdx.x;
    const int N = B_ * T0;
    float s = 0.f, sq = 0.f;
    for (int i = tid; i < N; i += 256) {
        float v = x[(size_t)i * C0 + c];
        s += v; sq += v * v;
    }
    __shared__ float rs[256], rq[256];
    rs[tid] = s; rq[tid] = sq;
    __syncthreads();
    for (int o = 128; o > 0; o >>= 1) {
        if (tid < o) { rs[tid] += rs[tid + o]; rq[tid] += rq[tid + o]; }
        __syncthreads();
    }
    if (tid == 0) {
        float mean = rs[0] / (float)N;
        float var  = rq[0] / (float)N - mean * mean;
        float sc   = gamma[c] * rsqrtf(var + EPSV);
        g_bn[c]      = sc;
        g_bn[80 + c] = beta[c] - mean * sc;
    }
}

__global__ void __launch_bounds__(512) zero_h_kernel() {
    int i = blockIdx.x * blockDim.x + threadIdx.x;
    if (i < B_ * HIDN) g_hstate[0][i] = 0.f;
}

// ---------------- weight transpose + bf16 split: tcr_w [l][kin][512] -> wt[l][n][kin] ----------------
__global__ void __launch_bounds__(256) wsplit_kernel(const float* __restrict__ tcr_w) {
    __shared__ float tile[32][33];
    const int l  = blockIdx.z;
    const int k0 = blockIdx.x * 32;
    const int n0 = blockIdx.y * 32;
    const int tx = threadIdx.x, ty = threadIdx.y;   // 32 x 8
#pragma unroll
    for (int j = 0; j < 32; j += 8)
        tile[ty + j][tx] = tcr_w[((size_t)l * 2560 + k0 + ty + j) * 512 + n0 + tx];
    __syncthreads();
#pragma unroll
    for (int j = 0; j < 32; j += 8) {
        float v = tile[tx][ty + j];
        size_t di = ((size_t)l * 512 + n0 + ty + j) * 2560 + k0 + tx;
        __nv_bfloat16 h = __float2bfloat16(v);
        g_wt_hi[di] = h;
        g_wt_lo[di] = __float2bfloat16(v - __bfloat162float(h));
    }
}

// ---------------- conv0: implicit-im2col SGEMM 128x128x32 FFMA2 (+ split epilogue) ----------------
template<int CIN, int TIN, int TOUT, int STRIDE, int PADL, bool FUSE_BN, bool RESID, bool SPLIT>
__global__ void __launch_bounds__(256, 2) conv5x_kernel(const float* __restrict__ in,
                                                        const float* __restrict__ w,
                                                        const float* __restrict__ bias,
                                                        float* __restrict__ out,
                                                        __nv_bfloat16* __restrict__ ohi,
                                                        __nv_bfloat16* __restrict__ olo) {
    __shared__ __align__(16) float As[32][128];
    __shared__ __align__(16) float Bs[32][128];
    __shared__ __align__(16) float s_bn[160];

    const int tid = threadIdx.x;
    if (FUSE_BN && tid < 160) s_bn[tid] = g_bn[tid];

    const int n0 = blockIdx.x * 128;
    const int m0 = blockIdx.y * 128;
    const int tx = tid & 15;
    const int ty = tid >> 4;

    ull acc[4][8];
#pragma unroll
    for (int i = 0; i < 4; i++)
#pragma unroll
        for (int j = 0; j < 8; j++) acc[i][j] = 0ull;

    __syncthreads();

    const int KIN = 5 * CIN;
    for (int p0 = 0; p0 < KIN; p0 += 32) {
#pragma unroll
        for (int it = 0; it < 4; it++) {
            int s  = tid + it * 256;
            int kq = s & 7;
            int ml = s >> 3;
            int p  = p0 + (kq << 2);
            int k  = p / CIN;
            int ci = p - k * CIN;
            int m  = m0 + ml;
            int bb = m / TOUT;
            int t  = m - bb * TOUT;
            int tin = t * STRIDE - PADL + k;
            float4 av = make_float4(0.f, 0.f, 0.f, 0.f);
            if (tin >= 0 && tin < TIN && p < KIN) {
                av = *reinterpret_cast<const float4*>(in + ((size_t)bb * TIN + tin) * CIN + ci);
                if (FUSE_BN) {
                    float4 sc = *reinterpret_cast<const float4*>(&s_bn[ci]);
                    float4 sh = *reinterpret_cast<const float4*>(&s_bn[80 + ci]);
                    av.x = av.x * sc.x + sh.x;
                    av.y = av.y * sc.y + sh.y;
                    av.z = av.z * sc.z + sh.z;
                    av.w = av.w * sc.w + sh.w;
                }
            }
            int pc = ml ^ (kq << 2);
            As[(kq << 2) + 0][pc] = av.x;
            As[(kq << 2) + 1][pc] = av.y;
            As[(kq << 2) + 2][pc] = av.z;
            As[(kq << 2) + 3][pc] = av.w;
        }
#pragma unroll
        for (int it = 0; it < 4; it++) {
            int s  = tid + it * 256;
            int cq = s & 31;
            int kr = s >> 5;
            float4 v = make_float4(0.f, 0.f, 0.f, 0.f);
            if (p0 + kr < KIN)
                v = *reinterpret_cast<const float4*>(w + (size_t)(p0 + kr) * 512 + n0 + (cq << 2));
            *reinterpret_cast<float4*>(&Bs[kr][cq << 2]) = v;
        }
        __syncthreads();

#pragma unroll
        for (int kk = 0; kk < 32; kk++) {
            const int sw = (kk >> 2) << 2;
            ulonglong2 ap0 = *reinterpret_cast<const ulonglong2*>(&As[kk][(ty << 3) ^ sw]);
            ulonglong2 ap1 = *reinterpret_cast<const ulonglong2*>(&As[kk][((ty << 3) + 4) ^ sw]);
            ull ap[4] = {ap0.x, ap0.y, ap1.x, ap1.y};
            float4 bA = *reinterpret_cast<const float4*>(&Bs[kk][tx << 2]);
            float4 bB = *reinterpret_cast<const float4*>(&Bs[kk][64 + (tx << 2)]);
            ull bd[8];
            bd[0] = pack2(bA.x); bd[1] = pack2(bA.y); bd[2] = pack2(bA.z); bd[3] = pack2(bA.w);
            bd[4] = pack2(bB.x); bd[5] = pack2(bB.y); bd[6] = pack2(bB.z); bd[7] = pack2(bB.w);
#pragma unroll
            for (int mp = 0; mp < 4; mp++)
#pragma unroll
                for (int n = 0; n < 8; n++) fma2(acc[mp][n], ap[mp], bd[n]);
        }
        __syncthreads();
    }

    const int c0 = n0 + (tx << 2);
    const int c1 = n0 + 64 + (tx << 2);
    const float4 bias0 = *reinterpret_cast<const float4*>(bias + c0);
    const float4 bias1 = *reinterpret_cast<const float4*>(bias + c1);
    float2 u0[4][4], u1[4][4];
#pragma unroll
    for (int mp = 0; mp < 4; mp++)
#pragma unroll
        for (int n = 0; n < 4; n++) {
            u0[mp][n] = unpack2(acc[mp][n]);
            u1[mp][n] = unpack2(acc[mp][4 + n]);
        }
#pragma unroll
    for (int i = 0; i < 8; i++) {
        const int mp = i >> 1;
        const bool hi = i & 1;
        int m = m0 + (ty << 3) + i;
        float4 r0, r1;
        r0.x = fmaxf((hi ? u0[mp][0].y : u0[mp][0].x) + bias0.x, 0.f);
        r0.y = fmaxf((hi ? u0[mp][1].y : u0[mp][1].x) + bias0.y, 0.f);
        r0.z = fmaxf((hi ? u0[mp][2].y : u0[mp][2].x) + bias0.z, 0.f);
        r0.w = fmaxf((hi ? u0[mp][3].y : u0[mp][3].x) + bias0.w, 0.f);
        r1.x = fmaxf((hi ? u1[mp][0].y : u1[mp][0].x) + bias1.x, 0.f);
        r1.y = fmaxf((hi ? u1[mp][1].y : u1[mp][1].x) + bias1.y, 0.f);
        r1.z = fmaxf((hi ? u1[mp][2].y : u1[mp][2].x) + bias1.z, 0.f);
        r1.w = fmaxf((hi ? u1[mp][3].y : u1[mp][3].x) + bias1.w, 0.f);
        if (RESID) {
            float4 e0 = *reinterpret_cast<const float4*>(in + (size_t)m * CIN + c0);
            float4 e1 = *reinterpret_cast<const float4*>(in + (size_t)m * CIN + c1);
            r0.x += e0.x; r0.y += e0.y; r0.z += e0.z; r0.w += e0.w;
            r1.x += e1.x; r1.y += e1.y; r1.z += e1.z; r1.w += e1.w;
        }
        *reinterpret_cast<float4*>(out + (size_t)m * 512 + c0) = r0;
        *reinterpret_cast<float4*>(out + (size_t)m * 512 + c1) = r1;
        if (SPLIT) {
            uint2 h4, l4;
            split4(r0, h4, l4);
            *reinterpret_cast<uint2*>(ohi + (size_t)m * 512 + c0) = h4;
            *reinterpret_cast<uint2*>(olo + (size_t)m * 512 + c0) = l4;
            split4(r1, h4, l4);
            *reinterpret_cast<uint2*>(ohi + (size_t)m * 512 + c1) = h4;
            *reinterpret_cast<uint2*>(olo + (size_t)m * 512 + c1) = l4;
        }
    }
}

// ---------------- tcr conv layer on mma.sync (bf16 3-product split) ----------------
// CTA 128x128, 8 warps (4m x 2n), warp 32x64 = 2 mtiles x 8 ntiles of m16n8k16.
// A[m][kin] split hi/lo, B = weights [n][kin] split hi/lo. K-chunk 32 (80 chunks).
// smem rows padded to 40 bf16 (80 B). B stored [n][k] -> NON-trans ldmatrix gives the
// .col B fragment (lane j: n=j>>2, k=2*(j%4)+h) directly.
#define ASTR 40
template<bool SPLIT>
__global__ void __launch_bounds__(256, 2) tcr_mma_kernel(const __nv_bfloat16* __restrict__ ahi,
                                                         const __nv_bfloat16* __restrict__ alo,
                                                         const __nv_bfloat16* __restrict__ whi,
                                                         const __nv_bfloat16* __restrict__ wlo,
                                                         const float* __restrict__ resid_in,
                                                         const float* __restrict__ bias,
                                                         float* __restrict__ out,
                                                         __nv_bfloat16* __restrict__ ohi,
                                                         __nv_bfloat16* __restrict__ olo) {
    __shared__ __align__(16) __nv_bfloat16 sAh[128 * ASTR];
    __shared__ __align__(16) __nv_bfloat16 sAl[128 * ASTR];
    __shared__ __align__(16) __nv_bfloat16 sBh[128 * ASTR];
    __shared__ __align__(16) __nv_bfloat16 sBl[128 * ASTR];

    const int tid = threadIdx.x;
    const int wid = tid >> 5, lane = tid & 31;
    const int n0 = blockIdx.x * 128;
    const int m0 = blockIdx.y * 128;
    const int warp_m = (wid >> 1) << 5;    // 0,32,64,96
    const int warp_n = (wid & 1) << 6;     // 0,64

    float acc[2][8][4];
#pragma unroll
    for (int i = 0; i < 2; i++)
#pragma unroll
        for (int j = 0; j < 8; j++)
#pragma unroll
            for (int r = 0; r < 4; r++) acc[i][j][r] = 0.f;

    const int lq = tid & 3;       // 16B quad within 64B row-chunk
    const int lrow = tid >> 2;    // 0..63

    // ldmatrix per-lane base addresses (bytes)
    const uint32_t aAddrH = smem_to_u32(sAh) + (warp_m + (lane & 15)) * 80 + (lane >> 4) * 16;
    const uint32_t aAddrL = smem_to_u32(sAl) + (warp_m + (lane & 15)) * 80 + (lane >> 4) * 16;
    const int browoff = warp_n + (lane & 7) + ((lane >> 4) & 1) * 8;
    const uint32_t bAddrH = smem_to_u32(sBh) + browoff * 80 + ((lane >> 3) & 1) * 16;
    const uint32_t bAddrL = smem_to_u32(sBl) + browoff * 80 + ((lane >> 3) & 1) * 16;

    for (int c = 0; c < 80; c++) {
        const int tap = c >> 4;
        const int ci0 = (c & 15) << 5;
        // ---- load A (hi/lo): 128 rows x 32 bf16 ----
#pragma unroll
        for (int it = 0; it < 2; it++) {
            int ml = lrow + it * 64;
            int m  = m0 + ml;
            int bb = m / T1;
            int t  = m - bb * T1;
            int tin = t + tap - 2;
            uint4 vh = make_uint4(0, 0, 0, 0), vl = make_uint4(0, 0, 0, 0);
            if (tin >= 0 && tin < T1) {
                size_t src = ((size_t)bb * T1 + tin) * 512 + ci0 + lq * 8;
                vh = *reinterpret_cast<const uint4*>(ahi + src);
                vl = *reinterpret_cast<const uint4*>(alo + src);
            }
            *reinterpret_cast<uint4*>(&sAh[ml * ASTR + lq * 8]) = vh;
            *reinterpret_cast<uint4*>(&sAl[ml * ASTR + lq * 8]) = vl;
        }
        // ---- load B (hi/lo): 128 n-rows x 32 bf16 ----
#pragma unroll
        for (int it = 0; it < 2; it++) {
            int nl = lrow + it * 64;
            size_t src = (size_t)(n0 + nl) * 2560 + c * 32 + lq * 8;
            *reinterpret_cast<uint4*>(&sBh[nl * ASTR + lq * 8]) = *reinterpret_cast<const uint4*>(whi + src);
            *reinterpret_cast<uint4*>(&sBl[nl * ASTR + lq * 8]) = *reinterpret_cast<const uint4*>(wlo + src);
        }
        __syncthreads();

#pragma unroll
        for (int s = 0; s < 2; s++) {
            uint32_t ah[2][4], al[2][4];
            ldsm4(ah[0], aAddrH + s * 32);
            ldsm4(ah[1], aAddrH + s * 32 + 16 * 80);
            ldsm4(al[0], aAddrL + s * 32);
            ldsm4(al[1], aAddrL + s * 32 + 16 * 80);
#pragma unroll
            for (int jj = 0; jj < 4; jj++) {
                uint32_t bh[4], bl[4];
                ldsm4(bh, bAddrH + s * 32 + jj * 16 * 80);
                ldsm4(bl, bAddrL + s * 32 + jj * 16 * 80);
#pragma unroll
                for (int i = 0; i < 2; i++) {
                    mma_bf16(acc[i][2 * jj],     ah[i], bh);
                    mma_bf16(acc[i][2 * jj],     ah[i], bl);
                    mma_bf16(acc[i][2 * jj],     al[i], bh);
                    mma_bf16(acc[i][2 * jj + 1], ah[i], bh + 2);
                    mma_bf16(acc[i][2 * jj + 1], ah[i], bl + 2);
                    mma_bf16(acc[i][2 * jj + 1], al[i], bh + 2);
                }
            }
        }
        __syncthreads();
    }

    // ---- epilogue: bias + relu + residual (+ split) ----
    const int r0 = lane >> 2;
    const int cc = (lane & 3) * 2;
#pragma unroll
    for (int i = 0; i < 2; i++) {
        int mrow = m0 + warp_m + i * 16 + r0;
#pragma unroll
        for (int j = 0; j < 8; j++) {
            int col = n0 + warp_n + j * 8 + cc;
            float2 b2 = *reinterpret_cast<const float2*>(bias + col);
#pragma unroll
            for (int half = 0; half < 2; half++) {
                int m = mrow + half * 8;
                float va = acc[i][j][half * 2 + 0];
                float vb = acc[i][j][half * 2 + 1];
                float2 e = *reinterpret_cast<const float2*>(resid_in + (size_t)m * 512 + col);
                float2 v;
                v.x = fmaxf(va + b2.x, 0.f) + e.x;
                v.y = fmaxf(vb + b2.y, 0.f) + e.y;
                *reinterpret_cast<float2*>(out + (size_t)m * 512 + col) = v;
                if (SPLIT) {
                    uint h2, l2;
                    split2(v.x, v.y, h2, l2);
                    *reinterpret_cast<uint*>(ohi + (size_t)m * 512 + col) = h2;
                    *reinterpret_cast<uint*>(olo + (size_t)m * 512 + col) = l2;
                }
            }
        }
    }
}

// ---------------- Recurrence kernel A: mh partials (k-split x8 GEMM) ----------------
// grid (12 n-tiles, 8 k-chunks of 64) = 96 blocks.
__global__ void __launch_bounds__(256) gru_part_kernel(const float* __restrict__ grk, int u) {
    __shared__ float Hs[16][33];
    __shared__ __align__(16) float Ws[16][128];
    const float* h = g_hstate[u & 1];
    const int tid = threadIdx.x;
    const int n0 = blockIdx.x * 128;
    const int kb = blockIdx.y * 64;
    const int nx = tid & 31;
    const int my = tid >> 5;

    ull acc[4][2];
#pragma unroll
    for (int i = 0; i < 4; i++) { acc[i][0] = 0ull; acc[i][1] = 0ull; }

    for (int k0 = 0; k0 < 64; k0 += 16) {
#pragma unroll
        for (int it = 0; it < 2; it++) {
            int e = tid + it * 256;
            int kk = e & 15, m = e >> 4;
            Hs[kk][m] = h[m * 512 + kb + k0 + kk];
        }
#pragma unroll
        for (int it = 0; it < 2; it++) {
            int s = tid + it * 256;
            int cq = s & 31, kr = s >> 5;
            *reinterpret_cast<float4*>(&Ws[kr][cq << 2]) =
                *reinterpret_cast<const float4*>(grk + (size_t)(kb + k0 + kr) * 1536 + n0 + (cq << 2));
        }
        __syncthreads();
#pragma unroll
        for (int kk = 0; kk < 16; kk++) {
            ulonglong2 bp = *reinterpret_cast<const ulonglong2*>(&Ws[kk][nx << 2]);
#pragma unroll
            for (int i = 0; i < 4; i++) {
                ull ad = pack2(Hs[kk][(my << 2) + i]);
                fma2(acc[i][0], ad, bp.x);
                fma2(acc[i][1], ad, bp.y);
            }
        }
        __syncthreads();
    }
    float* outp = g_mhp[blockIdx.y];
#pragma unroll
    for (int i = 0; i < 4; i++) {
        float2 v0 = unpack2(acc[i][0]);
        float2 v1 = unpack2(acc[i][1]);
        *reinterpret_cast<float4*>(&outp[((my << 2) + i) * 1536 + n0 + (nx << 2)]) =
            make_float4(v0.x, v0.y, v1.x, v1.y);
    }
}

// ---------------- Recurrence kernel B: sum 8 partials + GRU gates ----------------
__global__ void __launch_bounds__(512) gru_gates_kernel(const int* __restrict__ y,
                                                        const float* __restrict__ gk,
                                                        const float* __restrict__ gb,
                                                        int u) {
    const int b = blockIdx.x;
    const int j = threadIdx.x;
    float hz = 0.f, hr = 0.f, hh = 0.f;
#pragma unroll
    for (int c = 0; c < 8; c++) {
        const float* p = g_mhp[c] + b * 1536;
        hz += p[j];
        hr += p[512 + j];
        hh += p[1024 + j];
    }
    const float* bi = gb;
    const float* br = gb + 1536;
    const int tok   = y[b * 201 + u];
    const float* gx = gk + (size_t)tok * 1536;
    float xz = gx[j]        + bi[j];
    float xr = gx[512 + j]  + bi[512 + j];
    float xh = gx[1024 + j] + bi[1024 + j];
    hz += br[j];
    hr += br[512 + j];
    hh += br[1024 + j];
    float z = 1.f / (1.f + expf(-(xz + hz)));
    float r = 1.f / (1.f + expf(-(xr + hr)));
    float cand = tanhf(xh + r * hh);
    float hold = g_hstate[u & 1][b * 512 + j];
    float hn = z * hold + (1.f - z) * cand;
    g_hstate[(u + 1) & 1][b * 512 + j] = hn;
    g_catall[((size_t)u * 32 + b) * 1024 + j] = hn;
}

// ---------------- Batched scores GEMM: per b, S[200,800] = H[200,512] @ enc_b^T ----------------
__global__ void __launch_bounds__(256, 2) scores_gemm_kernel() {
    __shared__ __align__(16) float As[16][128];
    __shared__ __align__(16) float Bs[16][128];
    const int tid = threadIdx.x;
    const int n0 = blockIdx.x * 128;
    const int m0 = blockIdx.y * 128;
    const int b  = blockIdx.z;
    const int tx = tid & 15;
    const int ty = tid >> 4;

    ull acc[8][4];
#pragma unroll
    for (int i = 0; i < 8; i++)
#pragma unroll
        for (int j = 0; j < 4; j++) acc[i][j] = 0ull;

    for (int k0 = 0; k0 < 512; k0 += 16) {
#pragma unroll
        for (int it = 0; it < 2; it++) {
            int s  = tid + it * 256;
            int kq = s & 3;
            int ml = s >> 2;
            int urow = m0 + ml;
            float4 av = make_float4(0.f, 0.f, 0.f, 0.f);
            if (urow < USTEPS)
                av = *reinterpret_cast<const float4*>(
                    g_catall + ((size_t)urow * 32 + b) * 1024 + k0 + (kq << 2));
            int pc = ml ^ (kq << 2);
            As[(kq << 2) + 0][pc] = av.x;
            As[(kq << 2) + 1][pc] = av.y;
            As[(kq << 2) + 2][pc] = av.z;
            As[(kq << 2) + 3][pc] = av.w;
        }
#pragma unroll
        for (int it = 0; it < 2; it++) {
            int s  = tid + it * 256;
            int dq = s & 3;
            int tl = s >> 2;
            int t  = n0 + tl;
            float4 bv = make_float4(0.f, 0.f, 0.f, 0.f);
            if (t < T1)
                bv = *reinterpret_cast<const float4*>(
                    g_h1 + ((size_t)b * T1 + t) * 512 + k0 + (dq << 2));
            int pc = tl ^ (dq << 2);
            Bs[(dq << 2) + 0][pc] = bv.x;
            Bs[(dq << 2) + 1][pc] = bv.y;
            Bs[(dq << 2) + 2][pc] = bv.z;
            Bs[(dq << 2) + 3][pc] = bv.w;
        }
        __syncthreads();

#pragma unroll
        for (int kk = 0; kk < 16; kk++) {
            const int sw = (kk >> 2) << 2;
            float4 a0 = *reinterpret_cast<const float4*>(&As[kk][(ty << 3) ^ sw]);
            float4 a1 = *reinterpret_cast<const float4*>(&As[kk][((ty << 3) + 4) ^ sw]);
            ulonglong2 bp0 = *reinterpret_cast<const ulonglong2*>(&Bs[kk][(tx << 3) ^ sw]);
            ulonglong2 bp1 = *reinterpret_cast<const ulonglong2*>(&Bs[kk][((tx << 3) + 4) ^ sw]);
            ull b0 = bp0.x, b1 = bp0.y, b2 = bp1.x, b3 = bp1.y;
            float av[8] = {a0.x, a0.y, a0.z, a0.w, a1.x, a1.y, a1.z, a1.w};
#pragma unroll
            for (int i = 0; i < 8; i++) {
                ull a2 = pack2(av[i]);
                fma2(acc[i][0], a2, b0);
                fma2(acc[i][1], a2, b1);
                fma2(acc[i][2], a2, b2);
                fma2(acc[i][3], a2, b3);
            }
        }
        __syncthreads();
    }

    const int t0 = n0 + (tx << 3);
#pragma unroll
    for (int i = 0; i < 8; i++) {
        int urow = m0 + (ty << 3) + i;
        if (urow < USTEPS && t0 < T1) {
            float2 p0v = unpack2(acc[i][0]);
            float2 p1v = unpack2(acc[i][1]);
            float2 p2v = unpack2(acc[i][2]);
            float2 p3v = unpack2(acc[i][3]);
            float* sp = g_scoresall + ((size_t)urow * 32 + b) * T1 + t0;
            *reinterpret_cast<float4*>(sp)     = make_float4(p0v.x, p0v.y, p1v.x, p1v.y);
            *reinterpret_cast<float4*>(sp + 4) = make_float4(p2v.x, p2v.y, p3v.x, p3v.y);
        }
    }
}

// ---------------- Batched softmax over 800 ----------------
__global__ void __launch_bounds__(256) sm800_kernel() {
    const int row = blockIdx.x;
    const int tid = threadIdx.x;
    float* sp = g_scoresall + (size_t)row * T1;
    __shared__ float sa[800];
    __shared__ float red[8], red2[8];
    const int w = tid >> 5, lane = tid & 31;

    float m = -1e30f;
    for (int t = tid; t < 800; t += 256) {
        float v = sp[t];
        sa[t] = v;
        m = fmaxf(m, v);
    }
#pragma unroll
    for (int o = 16; o; o >>= 1) m = fmaxf(m, __shfl_xor_sync(0xffffffffu, m, o));
    if (lane == 0) red[w] = m;
    __syncthreads();
    float mm = red[0];
#pragma unroll
    for (int i = 1; i < 8; i++) mm = fmaxf(mm, red[i]);

    float ps = 0.f;
    for (int t = tid; t < 800; t += 256) {
        float e = expf(sa[t] - mm);
        sa[t] = e;
        ps += e;
    }
#pragma unroll
    for (int o = 16; o; o >>= 1) ps += __shfl_xor_sync(0xffffffffu, ps, o);
    if (lane == 0) red2[w] = ps;
    __syncthreads();
    float sum = 0.f;
#pragma unroll
    for (int i = 0; i < 8; i++) sum += red2[i];
    const float inv = 1.f / sum;

    for (int t = tid; t < 800; t += 256) sp[t] = sa[t] * inv;
}

// ---------------- Batched ctx: per b, alpha[200,800] @ enc_b[800,512] ----------------
__global__ void __launch_bounds__(256, 2) ctx_gemm_kernel() {
    __shared__ __align__(16) float As[16][128];
    __shared__ __align__(16) float Bs[16][128];
    const int tid = threadIdx.x;
    const int n0 = blockIdx.x * 128;
    const int m0 = blockIdx.y * 128;
    const int b  = blockIdx.z;
    const int tx = tid & 15;
    const int ty = tid >> 4;

    ull acc[8][4];
#pragma unroll
    for (int i = 0; i < 8; i++)
#pragma unroll
        for (int j = 0; j < 4; j++) acc[i][j] = 0ull;

    for (int k0 = 0; k0 < 800; k0 += 16) {
#pragma unroll
        for (int it = 0; it < 2; it++) {
            int s  = tid + it * 256;
            int kq = s & 3;
            int ml = s >> 2;
            int u  = m0 + ml;
            float4 av = make_float4(0.f, 0.f, 0.f, 0.f);
            if (u < USTEPS)
                av = *reinterpret_cast<const float4*>(
                    g_scoresall + ((size_t)u * 32 + b) * T1 + k0 + (kq << 2));
            As[(kq << 2) + 0][ml] = av.x;
            As[(kq << 2) + 1][ml] = av.y;
            As[(kq << 2) + 2][ml] = av.z;
            As[(kq << 2) + 3][ml] = av.w;
        }
#pragma unroll
        for (int it = 0; it < 2; it++) {
            int s  = tid + it * 256;
            int cq = s & 31;
            int kr = s >> 5;
            *reinterpret_cast<float4*>(&Bs[kr][cq << 2]) =
                *reinterpret_cast<const float4*>(
                    g_h1 + ((size_t)b * T1 + k0 + kr) * 512 + n0 + (cq << 2));
        }
        __syncthreads();

#pragma unroll
        for (int kk = 0; kk < 16; kk++) {
            float4 a0 = *reinterpret_cast<const float4*>(&As[kk][ty << 3]);
            float4 a1 = *reinterpret_cast<const float4*>(&As[kk][(ty << 3) + 4]);
            ulonglong2 bp0 = *reinterpret_cast<const ulonglong2*>(&Bs[kk][(tx << 3)]);
            ulonglong2 bp1 = *reinterpret_cast<const ulonglong2*>(&Bs[kk][(tx << 3) + 4]);
            ull b0 = bp0.x, b1 = bp0.y, b2 = bp1.x, b3 = bp1.y;
            float av[8] = {a0.x, a0.y, a0.z, a0.w, a1.x, a1.y, a1.z, a1.w};
#pragma unroll
            for (int i = 0; i < 8; i++) {
                ull a2 = pack2(av[i]);
                fma2(acc[i][0], a2, b0);
                fma2(acc[i][1], a2, b1);
                fma2(acc[i][2], a2, b2);
                fma2(acc[i][3], a2, b3);
            }
        }
        __syncthreads();
    }

#pragma unroll
    for (int i = 0; i < 8; i++) {
        int u = m0 + (ty << 3) + i;
        if (u < USTEPS) {
            float2 p0v = unpack2(acc[i][0]);
            float2 p1v = unpack2(acc[i][1]);
            float2 p2v = unpack2(acc[i][2]);
            float2 p3v = unpack2(acc[i][3]);
            float* cp = g_catall + ((size_t)u * 32 + b) * 1024 + 512 + n0 + (tx << 3);
            *reinterpret_cast<float4*>(cp)     = make_float4(p0v.x, p0v.y, p1v.x, p1v.y);
            *reinterpret_cast<float4*>(cp + 4) = make_float4(p2v.x, p2v.y, p3v.x, p3v.y);
        }
    }
}

// ---------------- Batched FC ----------------
__global__ void __launch_bounds__(256, 2) fc_big_kernel(const float* __restrict__ fw,
                                                        const float* __restrict__ fb) {
    __shared__ __align__(16) float As[16][128];
    __shared__ __align__(16) float Bs[16][128];
    const int tid = threadIdx.x;
    const int n0 = blockIdx.x * 128;
    const int m0 = blockIdx.y * 128;
    const int tx = tid & 15;
    const int ty = tid >> 4;

    ull acc[8][4];
#pragma unroll
    for (int i = 0; i < 8; i++)
#pragma unroll
        for (int j = 0; j < 4; j++) acc[i][j] = 0ull;

    for (int p0 = 0; p0 < 1024; p0 += 16) {
#pragma unroll
        for (int it = 0; it < 2; it++) {
            int s  = tid + it * 256;
            int kq = s & 3;
            int ml = s >> 2;
            float4 av = *reinterpret_cast<const float4*>(
                g_catall + ((size_t)(m0 + ml)) * 1024 + p0 + (kq << 2));
            As[(kq << 2) + 0][ml] = av.x;
            As[(kq << 2) + 1][ml] = av.y;
            As[(kq << 2) + 2][ml] = av.z;
            As[(kq << 2) + 3][ml] = av.w;
        }
#pragma unroll
        for (int it = 0; it < 2; it++) {
            int s  = tid + it * 256;
            int cq = s & 31;
            int kr = s >> 5;
            int c  = n0 + (cq << 2);
            float4 v = make_float4(0.f, 0.f, 0.f, 0.f);
            if (c < 1000)
                v = *reinterpret_cast<const float4*>(fw + (size_t)(p0 + kr) * 1000 + c);
            *reinterpret_cast<float4*>(&Bs[kr][cq << 2]) = v;
        }
        __syncthreads();

#pragma unroll
        for (int kk = 0; kk < 16; kk++) {
            float4 a0 = *reinterpret_cast<const float4*>(&As[kk][ty << 3]);
            float4 a1 = *reinterpret_cast<const float4*>(&As[kk][(ty << 3) + 4]);
            ulonglong2 bp0 = *reinterpret_cast<const ulonglong2*>(&Bs[kk][(tx << 3)]);
            ulonglong2 bp1 = *reinterpret_cast<const ulonglong2*>(&Bs[kk][(tx << 3) + 4]);
            ull b0 = bp0.x, b1 = bp0.y, b2 = bp1.x, b3 = bp1.y;
            float av[8] = {a0.x, a0.y, a0.z, a0.w, a1.x, a1.y, a1.z, a1.w};
#pragma unroll
            for (int i = 0; i < 8; i++) {
                ull a2 = pack2(av[i]);
                fma2(acc[i][0], a2, b0);
                fma2(acc[i][1], a2, b1);
                fma2(acc[i][2], a2, b2);
                fma2(acc[i][3], a2, b3);
            }
        }
        __syncthreads();
    }

    const int c0 = n0 + (tx << 3);
    float bias[8];
#pragma unroll
    for (int j = 0; j < 8; j++) bias[j] = (c0 + j < 1000) ? fb[c0 + j] : 0.f;
#pragma unroll
    for (int i = 0; i < 8; i++) {
        int m = m0 + (ty << 3) + i;
        float2 p0v = unpack2(acc[i][0]);
        float2 p1v = unpack2(acc[i][1]);
        float2 p2v = unpack2(acc[i][2]);
        float2 p3v = unpack2(acc[i][3]);
        float4 r0 = make_float4(p0v.x + bias[0], p0v.y + bias[1], p1v.x + bias[2], p1v.y + bias[3]);
        float4 r1 = make_float4(p2v.x + bias[4], p2v.y + bias[5], p3v.x + bias[6], p3v.y + bias[7]);
        float* lp = g_logitsall + (size_t)m * 1000;
        if (c0 < 1000)     *reinterpret_cast<float4*>(lp + c0)     = r0;
        if (c0 + 4 < 1000) *reinterpret_cast<float4*>(lp + c0 + 4) = r1;
    }
}

// ---------------- Batched output softmax ----------------
__global__ void __launch_bounds__(256) outsm_all_kernel(float* __restrict__ out) {
    const int m = blockIdx.x;
    const int u = m >> 5, b = m & 31;
    const int tid = threadIdx.x;
    __shared__ float sh[1000];
    __shared__ float red[8], red2[8];
    const int w = tid >> 5, lane = tid & 31;
    const float* lp = g_logitsall + (size_t)m * 1000;

    float mx = -1e30f;
    for (int c = tid; c < 1000; c += 256) {
        float v = lp[c];
        sh[c] = v;
        mx = fmaxf(mx, v);
    }
#pragma unroll
    for (int o = 16; o; o >>= 1) mx = fmaxf(mx, __shfl_xor_sync(0xffffffffu, mx, o));
    if (lane == 0) red[w] = mx;
    __syncthreads();
    float mm = red[0];
#pragma unroll
    for (int i = 1; i < 8; i++) mm = fmaxf(mm, red[i]);

    float ps = 0.f;
    for (int c = tid; c < 1000; c += 256) {
        float e = expf(sh[c] - mm);
        sh[c] = e;
        ps += e;
    }
#pragma unroll
    for (int o = 16; o; o >>= 1) ps += __shfl_xor_sync(0xffffffffu, ps, o);
    if (lane == 0) red2[w] = ps;
    __syncthreads();
    float sum = 0.f;
#pragma unroll
    for (int i = 0; i < 8; i++) sum += red2[i];
    const float inv = 1.f / sum;

    float* op = out + ((size_t)b * USTEPS + u) * VOCABN;
    for (int c = tid; c < 1000; c += 256) op[c] = sh[c] * inv;
}

// ---------------- launch ----------------
extern "C" void kernel_launch(void* const* d_in, const int* in_sizes, int n_in,
                              void* d_out, int out_size) {
    const float* x        = (const float*)d_in[0];
    const int*   y        = (const int*)  d_in[1];
    const float* bn_gamma = (const float*)d_in[2];
    const float* bn_beta  = (const float*)d_in[3];
    const float* conv0_w  = (const float*)d_in[4];
    const float* conv0_b  = (const float*)d_in[5];
    const float* tcr_w    = (const float*)d_in[6];
    const float* tcr_b    = (const float*)d_in[7];
    const float* gru_k    = (const float*)d_in[8];
    const float* gru_rk   = (const float*)d_in[9];
    const float* gru_b    = (const float*)d_in[10];
    const float* fc_w     = (const float*)d_in[11];
    const float* fc_b     = (const float*)d_in[12];
    float* out = (float*)d_out;

    float *h1, *h2;
    __nv_bfloat16 *shi0, *slo0, *shi1, *slo1, *wth, *wtl;
    cudaGetSymbolAddress((void**)&h1, g_h1);
    cudaGetSymbolAddress((void**)&h2, g_h2);
    cudaGetSymbolAddress((void**)&shi0, g_shi0);
    cudaGetSymbolAddress((void**)&slo0, g_slo0);
    cudaGetSymbolAddress((void**)&shi1, g_shi1);
    cudaGetSymbolAddress((void**)&slo1, g_slo1);
    cudaGetSymbolAddress((void**)&wth, g_wt_hi);
    cudaGetSymbolAddress((void**)&wtl, g_wt_lo);

    // ---- encoder ----
    bn_stats_kernel<<<80, 256>>>(x, bn_gamma, bn_beta);
    zero_h_kernel<<<32, 512>>>();
    dim3 wgrid(80, 16, 4);          // 2560/32, 512/32, 4 layers
    wsplit_kernel<<<wgrid, dim3(32, 8)>>>(tcr_w);

    dim3 cgrid(4, 200);
    conv5x_kernel<80, 1600, 800, 2, 1, true, false, true><<<cgrid, 256>>>(
        x, conv0_w, conv0_b, h1, shi0, slo0);

    const size_t WT = (size_t)512 * 2560;
    dim3 tgrid(4, 200);
    tcr_mma_kernel<true><<<tgrid, 256>>>(
        shi0, slo0, wth + 0 * WT, wtl + 0 * WT, h1, tcr_b + 0 * 512, h2, shi1, slo1);
    tcr_mma_kernel<true><<<tgrid, 256>>>(
        shi1, slo1, wth + 1 * WT, wtl + 1 * WT, h2, tcr_b + 1 * 512, h1, shi0, slo0);
    tcr_mma_kernel<true><<<tgrid, 256>>>(
        shi0, slo0, wth + 2 * WT, wtl + 2 * WT, h1, tcr_b + 2 * 512, h2, shi1, slo1);
    tcr_mma_kernel<false><<<tgrid, 256>>>(
        shi1, slo1, wth + 3 * WT, wtl + 3 * WT, h2, tcr_b + 3 * 512, h1, nullptr, nullptr);
    // enc lives in g_h1 (fp32)

    // ---- GRU recurrence: 2 kernels per step, 8-way k-split (96 blocks) ----
    dim3 pgrid(12, 8);
    for (int u = 0; u < USTEPS; u++) {
        gru_part_kernel<<<pgrid, 256>>>(gru_rk, u);
        gru_gates_kernel<<<32, 512>>>(y, gru_k, gru_b, u);
    }

    // ---- batched tail ----
    dim3 sgrid(7, 2, 32);
    scores_gemm_kernel<<<sgrid, 256>>>();
    sm800_kernel<<<USTEPS * B_, 256>>>();
    dim3 xgrid(4, 2, 32);
    ctx_gemm_kernel<<<xgrid, 256>>>();
    dim3 fgrid(8, 50);
    fc_big_kernel<<<fgrid, 256>>>(fc_w, fc_b);
    outsm_all_kernel<<<USTEPS * B_, 256>>>(out);
}

// round 12
// speedup vs baseline: 1.3244x; 1.1145x over previous
#include <cuda_runtime.h>
#include <cuda_fp16.h>
#include <cstdint>
#include <math.h>

typedef unsigned long long ull;
typedef unsigned int uint;

#define B_     32
#define T0     1600
#define C0     80
#define T1     800
#define D_     512
#define VOCABN 1000
#define HIDN   512
#define USTEPS 200
#define EPSV   1e-3f

// ---------------- scratch (static device globals; no allocation) ----------------
__device__ float g_bn[160];
__device__ float g_h1[B_ * T1 * D_];                // fp32 activations (enc ends here)
__device__ float g_h2[B_ * T1 * D_];
__device__ float g_hstate[2][B_ * HIDN];
__device__ float g_mhp[8][B_ * 1536];               // k-split partials of h @ grk
__device__ float g_scoresall[USTEPS * B_ * T1];
__device__ float g_catall[USTEPS * B_ * 1024];
__device__ float g_logitsall[USTEPS * B_ * VOCABN];
// fp16 activations (ping-pong) and fp16-split transposed weights [l][n][kin]
__device__ __half g_sa0[B_ * T1 * D_];
__device__ __half g_sa1[B_ * T1 * D_];
__device__ __half g_wh[4 * 512 * 2560];
__device__ __half g_wl[4 * 512 * 2560];

// ---------------- packed f32x2 helpers (FFMA2) ----------------
__device__ __forceinline__ void fma2(ull& d, ull a, ull b) {
    asm("fma.rn.f32x2 %0, %1, %2, %0;" : "+l"(d) : "l"(a), "l"(b));
}
__device__ __forceinline__ ull pack2(float x) {
    ull r;
    asm("mov.b64 %0, {%1, %1};" : "=l"(r) : "f"(x));
    return r;
}
__device__ __forceinline__ float2 unpack2(ull v) {
    float2 f;
    asm("mov.b64 {%0, %1}, %2;" : "=f"(f.x), "=f"(f.y) : "l"(v));
    return f;
}

// ---------------- mma.sync / ldmatrix helpers (sm_80+ portable) ----------------
__device__ __forceinline__ uint32_t smem_to_u32(const void* p) {
    uint32_t a;
    asm("{ .reg .u64 t; cvta.to.shared.u64 t, %1; cvt.u32.u64 %0, t; }" : "=r"(a) : "l"(p));
    return a;
}
__device__ __forceinline__ void mma_f16(float* d, const uint32_t* a, const uint32_t* b) {
    asm volatile(
        "mma.sync.aligned.m16n8k16.row.col.f32.f16.f16.f32 "
        "{%0,%1,%2,%3}, {%4,%5,%6,%7}, {%8,%9}, {%0,%1,%2,%3};"
        : "+f"(d[0]), "+f"(d[1]), "+f"(d[2]), "+f"(d[3])
        : "r"(a[0]), "r"(a[1]), "r"(a[2]), "r"(a[3]), "r"(b[0]), "r"(b[1]));
}
__device__ __forceinline__ void ldsm4(uint32_t* r, uint32_t addr) {
    asm volatile("ldmatrix.sync.aligned.m8n8.x4.shared.b16 {%0,%1,%2,%3}, [%4];"
                 : "=r"(r[0]), "=r"(r[1]), "=r"(r[2]), "=r"(r[3]) : "r"(addr));
}

// ---------------- BatchNorm statistics ----------------
__global__ void __launch_bounds__(256) bn_stats_kernel(const float* __restrict__ x,
                                                       const float* __restrict__ gamma,
                                                       const float* __restrict__ beta) {
    const int c = blockIdx.x;
    const int tid = threadIdx.x;
    const int N = B_ * T0;
    float s = 0.f, sq = 0.f;
    for (int i = tid; i < N; i += 256) {
        float v = x[(size_t)i * C0 + c];
        s += v; sq += v * v;
    }
    __shared__ float rs[256], rq[256];
    rs[tid] = s; rq[tid] = sq;
    __syncthreads();
    for (int o = 128; o > 0; o >>= 1) {
        if (tid < o) { rs[tid] += rs[tid + o]; rq[tid] += rq[tid + o]; }
        __syncthreads();
    }
    if (tid == 0) {
        float mean = rs[0] / (float)N;
        float var  = rq[0] / (float)N - mean * mean;
        float sc   = gamma[c] * rsqrtf(var + EPSV);
        g_bn[c]      = sc;
        g_bn[80 + c] = beta[c] - mean * sc;
    }
}

__global__ void __launch_bounds__(512) zero_h_kernel() {
    int i = blockIdx.x * blockDim.x + threadIdx.x;
    if (i < B_ * HIDN) g_hstate[0][i] = 0.f;
}

// ---------------- weight transpose + fp16 split: tcr_w [l][kin][512] -> w[l][n][kin] ----------------
__global__ void __launch_bounds__(256) wsplit_kernel(const float* __restrict__ tcr_w) {
    __shared__ float tile[32][33];
    const int l  = blockIdx.z;
    const int k0 = blockIdx.x * 32;
    const int n0 = blockIdx.y * 32;
    const int tx = threadIdx.x, ty = threadIdx.y;   // 32 x 8
#pragma unroll
    for (int j = 0; j < 32; j += 8)
        tile[ty + j][tx] = tcr_w[((size_t)l * 2560 + k0 + ty + j) * 512 + n0 + tx];
    __syncthreads();
#pragma unroll
    for (int j = 0; j < 32; j += 8) {
        float v = tile[tx][ty + j];
        size_t di = ((size_t)l * 512 + n0 + ty + j) * 2560 + k0 + tx;
        __half h = __float2half_rn(v);
        g_wh[di] = h;
        g_wl[di] = __float2half_rn(v - __half2float(h));
    }
}

// ---------------- conv0: implicit-im2col SGEMM 128x128x32 FFMA2 (+ fp16 epilogue) ----------------
template<int CIN, int TIN, int TOUT, int STRIDE, int PADL, bool FUSE_BN, bool RESID, bool SPLIT>
__global__ void __launch_bounds__(256, 2) conv5x_kernel(const float* __restrict__ in,
                                                        const float* __restrict__ w,
                                                        const float* __restrict__ bias,
                                                        float* __restrict__ out,
                                                        __half* __restrict__ oh) {
    __shared__ __align__(16) float As[32][128];
    __shared__ __align__(16) float Bs[32][128];
    __shared__ __align__(16) float s_bn[160];

    const int tid = threadIdx.x;
    if (FUSE_BN && tid < 160) s_bn[tid] = g_bn[tid];

    const int n0 = blockIdx.x * 128;
    const int m0 = blockIdx.y * 128;
    const int tx = tid & 15;
    const int ty = tid >> 4;

    ull acc[4][8];
#pragma unroll
    for (int i = 0; i < 4; i++)
#pragma unroll
        for (int j = 0; j < 8; j++) acc[i][j] = 0ull;

    __syncthreads();

    const int KIN = 5 * CIN;
    for (int p0 = 0; p0 < KIN; p0 += 32) {
#pragma unroll
        for (int it = 0; it < 4; it++) {
            int s  = tid + it * 256;
            int kq = s & 7;
            int ml = s >> 3;
            int p  = p0 + (kq << 2);
            int k  = p / CIN;
            int ci = p - k * CIN;
            int m  = m0 + ml;
            int bb = m / TOUT;
            int t  = m - bb * TOUT;
            int tin = t * STRIDE - PADL + k;
            float4 av = make_float4(0.f, 0.f, 0.f, 0.f);
            if (tin >= 0 && tin < TIN && p < KIN) {
                av = *reinterpret_cast<const float4*>(in + ((size_t)bb * TIN + tin) * CIN + ci);
                if (FUSE_BN) {
                    float4 sc = *reinterpret_cast<const float4*>(&s_bn[ci]);
                    float4 sh = *reinterpret_cast<const float4*>(&s_bn[80 + ci]);
                    av.x = av.x * sc.x + sh.x;
                    av.y = av.y * sc.y + sh.y;
                    av.z = av.z * sc.z + sh.z;
                    av.w = av.w * sc.w + sh.w;
                }
            }
            int pc = ml ^ (kq << 2);
            As[(kq << 2) + 0][pc] = av.x;
            As[(kq << 2) + 1][pc] = av.y;
            As[(kq << 2) + 2][pc] = av.z;
            As[(kq << 2) + 3][pc] = av.w;
        }
#pragma unroll
        for (int it = 0; it < 4; it++) {
            int s  = tid + it * 256;
            int cq = s & 31;
            int kr = s >> 5;
            float4 v = make_float4(0.f, 0.f, 0.f, 0.f);
            if (p0 + kr < KIN)
                v = *reinterpret_cast<const float4*>(w + (size_t)(p0 + kr) * 512 + n0 + (cq << 2));
            *reinterpret_cast<float4*>(&Bs[kr][cq << 2]) = v;
        }
        __syncthreads();

#pragma unroll
        for (int kk = 0; kk < 32; kk++) {
            const int sw = (kk >> 2) << 2;
            ulonglong2 ap0 = *reinterpret_cast<const ulonglong2*>(&As[kk][(ty << 3) ^ sw]);
            ulonglong2 ap1 = *reinterpret_cast<const ulonglong2*>(&As[kk][((ty << 3) + 4) ^ sw]);
            ull ap[4] = {ap0.x, ap0.y, ap1.x, ap1.y};
            float4 bA = *reinterpret_cast<const float4*>(&Bs[kk][tx << 2]);
            float4 bB = *reinterpret_cast<const float4*>(&Bs[kk][64 + (tx << 2)]);
            ull bd[8];
            bd[0] = pack2(bA.x); bd[1] = pack2(bA.y); bd[2] = pack2(bA.z); bd[3] = pack2(bA.w);
            bd[4] = pack2(bB.x); bd[5] = pack2(bB.y); bd[6] = pack2(bB.z); bd[7] = pack2(bB.w);
#pragma unroll
            for (int mp = 0; mp < 4; mp++)
#pragma unroll
                for (int n = 0; n < 8; n++) fma2(acc[mp][n], ap[mp], bd[n]);
        }
        __syncthreads();
    }

    const int c0 = n0 + (tx << 2);
    const int c1 = n0 + 64 + (tx << 2);
    const float4 bias0 = *reinterpret_cast<const float4*>(bias + c0);
    const float4 bias1 = *reinterpret_cast<const float4*>(bias + c1);
    float2 u0[4][4], u1[4][4];
#pragma unroll
    for (int mp = 0; mp < 4; mp++)
#pragma unroll
        for (int n = 0; n < 4; n++) {
            u0[mp][n] = unpack2(acc[mp][n]);
            u1[mp][n] = unpack2(acc[mp][4 + n]);
        }
#pragma unroll
    for (int i = 0; i < 8; i++) {
        const int mp = i >> 1;
        const bool hi = i & 1;
        int m = m0 + (ty << 3) + i;
        float4 r0, r1;
        r0.x = fmaxf((hi ? u0[mp][0].y : u0[mp][0].x) + bias0.x, 0.f);
        r0.y = fmaxf((hi ? u0[mp][1].y : u0[mp][1].x) + bias0.y, 0.f);
        r0.z = fmaxf((hi ? u0[mp][2].y : u0[mp][2].x) + bias0.z, 0.f);
        r0.w = fmaxf((hi ? u0[mp][3].y : u0[mp][3].x) + bias0.w, 0.f);
        r1.x = fmaxf((hi ? u1[mp][0].y : u1[mp][0].x) + bias1.x, 0.f);
        r1.y = fmaxf((hi ? u1[mp][1].y : u1[mp][1].x) + bias1.y, 0.f);
        r1.z = fmaxf((hi ? u1[mp][2].y : u1[mp][2].x) + bias1.z, 0.f);
        r1.w = fmaxf((hi ? u1[mp][3].y : u1[mp][3].x) + bias1.w, 0.f);
        if (RESID) {
            float4 e0 = *reinterpret_cast<const float4*>(in + (size_t)m * CIN + c0);
            float4 e1 = *reinterpret_cast<const float4*>(in + (size_t)m * CIN + c1);
            r0.x += e0.x; r0.y += e0.y; r0.z += e0.z; r0.w += e0.w;
            r1.x += e1.x; r1.y += e1.y; r1.z += e1.z; r1.w += e1.w;
        }
        *reinterpret_cast<float4*>(out + (size_t)m * 512 + c0) = r0;
        *reinterpret_cast<float4*>(out + (size_t)m * 512 + c1) = r1;
        if (SPLIT) {
            __half* hp = oh + (size_t)m * 512;
            *reinterpret_cast<__half2*>(hp + c0)     = __floats2half2_rn(r0.x, r0.y);
            *reinterpret_cast<__half2*>(hp + c0 + 2) = __floats2half2_rn(r0.z, r0.w);
            *reinterpret_cast<__half2*>(hp + c1)     = __floats2half2_rn(r1.x, r1.y);
            *reinterpret_cast<__half2*>(hp + c1 + 2) = __floats2half2_rn(r1.z, r1.w);
        }
    }
}

// ---------------- tcr conv layer on mma.sync (fp16, weight-split 2-product) ----------------
// CTA 128x128, 8 warps (4m x 2n). A = fp16 activation (single), B = weight hi/lo fp16.
// K-chunk 32 (80 chunks). smem rows 40 halves (80 B). B stored [n][k] -> non-trans
// ldmatrix yields the .col B fragment directly. D = A*Wh + A*Wl, fp32 accum.
#define ASTR 40
template<bool SPLIT>
__global__ void __launch_bounds__(256, 2) tcr_mma_kernel(const __half* __restrict__ a16,
                                                         const __half* __restrict__ wh,
                                                         const __half* __restrict__ wl,
                                                         const float* __restrict__ resid_in,
                                                         const float* __restrict__ bias,
                                                         float* __restrict__ out,
                                                         __half* __restrict__ oh) {
    __shared__ __align__(16) __half sA [128 * ASTR];
    __shared__ __align__(16) __half sBh[128 * ASTR];
    __shared__ __align__(16) __half sBl[128 * ASTR];

    const int tid = threadIdx.x;
    const int wid = tid >> 5, lane = tid & 31;
    const int n0 = blockIdx.x * 128;
    const int m0 = blockIdx.y * 128;
    const int warp_m = (wid >> 1) << 5;    // 0,32,64,96
    const int warp_n = (wid & 1) << 6;     // 0,64

    float acc[2][8][4];
#pragma unroll
    for (int i = 0; i < 2; i++)
#pragma unroll
        for (int j = 0; j < 8; j++)
#pragma unroll
            for (int r = 0; r < 4; r++) acc[i][j][r] = 0.f;

    const int lq = tid & 3;       // 16B quad within 64B row-chunk
    const int lrow = tid >> 2;    // 0..63

    const uint32_t aAddr  = smem_to_u32(sA)  + (warp_m + (lane & 15)) * 80 + (lane >> 4) * 16;
    const int browoff = warp_n + (lane & 7) + ((lane >> 4) & 1) * 8;
    const uint32_t bAddrH = smem_to_u32(sBh) + browoff * 80 + ((lane >> 3) & 1) * 16;
    const uint32_t bAddrL = smem_to_u32(sBl) + browoff * 80 + ((lane >> 3) & 1) * 16;

    for (int c = 0; c < 80; c++) {
        const int tap = c >> 4;
        const int ci0 = (c & 15) << 5;
        // ---- load A: 128 rows x 32 fp16 ----
#pragma unroll
        for (int it = 0; it < 2; it++) {
            int ml = lrow + it * 64;
            int m  = m0 + ml;
            int bb = m / T1;
            int t  = m - bb * T1;
            int tin = t + tap - 2;
            uint4 va = make_uint4(0, 0, 0, 0);
            if (tin >= 0 && tin < T1)
                va = *reinterpret_cast<const uint4*>(a16 + ((size_t)bb * T1 + tin) * 512 + ci0 + lq * 8);
            *reinterpret_cast<uint4*>(&sA[ml * ASTR + lq * 8]) = va;
        }
        // ---- load B (hi/lo): 128 n-rows x 32 fp16 ----
#pragma unroll
        for (int it = 0; it < 2; it++) {
            int nl = lrow + it * 64;
            size_t src = (size_t)(n0 + nl) * 2560 + c * 32 + lq * 8;
            *reinterpret_cast<uint4*>(&sBh[nl * ASTR + lq * 8]) = *reinterpret_cast<const uint4*>(wh + src);
            *reinterpret_cast<uint4*>(&sBl[nl * ASTR + lq * 8]) = *reinterpret_cast<const uint4*>(wl + src);
        }
        __syncthreads();

#pragma unroll
        for (int s = 0; s < 2; s++) {
            uint32_t a[2][4];
            ldsm4(a[0], aAddr + s * 32);
            ldsm4(a[1], aAddr + s * 32 + 16 * 80);
#pragma unroll
            for (int jj = 0; jj < 4; jj++) {
                uint32_t bh[4], bl[4];
                ldsm4(bh, bAddrH + s * 32 + jj * 16 * 80);
                ldsm4(bl, bAddrL + s * 32 + jj * 16 * 80);
#pragma unroll
                for (int i = 0; i < 2; i++) {
                    mma_f16(acc[i][2 * jj],     a[i], bh);
                    mma_f16(acc[i][2 * jj],     a[i], bl);
                    mma_f16(acc[i][2 * jj + 1], a[i], bh + 2);
                    mma_f16(acc[i][2 * jj + 1], a[i], bl + 2);
                }
            }
        }
        __syncthreads();
    }

    // ---- epilogue: bias + relu + residual (+ fp16 emit) ----
    const int r0 = lane >> 2;
    const int cc = (lane & 3) * 2;
#pragma unroll
    for (int i = 0; i < 2; i++) {
        int mrow = m0 + warp_m + i * 16 + r0;
#pragma unroll
        for (int j = 0; j < 8; j++) {
            int col = n0 + warp_n + j * 8 + cc;
            float2 b2 = *reinterpret_cast<const float2*>(bias + col);
#pragma unroll
            for (int half = 0; half < 2; half++) {
                int m = mrow + half * 8;
                float va = acc[i][j][half * 2 + 0];
                float vb = acc[i][j][half * 2 + 1];
                float2 e = *reinterpret_cast<const float2*>(resid_in + (size_t)m * 512 + col);
                float2 v;
                v.x = fmaxf(va + b2.x, 0.f) + e.x;
                v.y = fmaxf(vb + b2.y, 0.f) + e.y;
                *reinterpret_cast<float2*>(out + (size_t)m * 512 + col) = v;
                if (SPLIT)
                    *reinterpret_cast<__half2*>(oh + (size_t)m * 512 + col) = __floats2half2_rn(v.x, v.y);
            }
        }
    }
}

// ---------------- Recurrence kernel A: mh partials (k-split x8 GEMM) ----------------
// grid (12 n-tiles, 8 k-chunks of 64) = 96 blocks.
__global__ void __launch_bounds__(256) gru_part_kernel(const float* __restrict__ grk, int u) {
    __shared__ float Hs[16][33];
    __shared__ __align__(16) float Ws[16][128];
    const float* h = g_hstate[u & 1];
    const int tid = threadIdx.x;
    const int n0 = blockIdx.x * 128;
    const int kb = blockIdx.y * 64;
    const int nx = tid & 31;
    const int my = tid >> 5;

    ull acc[4][2];
#pragma unroll
    for (int i = 0; i < 4; i++) { acc[i][0] = 0ull; acc[i][1] = 0ull; }

    for (int k0 = 0; k0 < 64; k0 += 16) {
#pragma unroll
        for (int it = 0; it < 2; it++) {
            int e = tid + it * 256;
            int kk = e & 15, m = e >> 4;
            Hs[kk][m] = h[m * 512 + kb + k0 + kk];
        }
#pragma unroll
        for (int it = 0; it < 2; it++) {
            int s = tid + it * 256;
            int cq = s & 31, kr = s >> 5;
            *reinterpret_cast<float4*>(&Ws[kr][cq << 2]) =
                *reinterpret_cast<const float4*>(grk + (size_t)(kb + k0 + kr) * 1536 + n0 + (cq << 2));
        }
        __syncthreads();
#pragma unroll
        for (int kk = 0; kk < 16; kk++) {
            ulonglong2 bp = *reinterpret_cast<const ulonglong2*>(&Ws[kk][nx << 2]);
#pragma unroll
            for (int i = 0; i < 4; i++) {
                ull ad = pack2(Hs[kk][(my << 2) + i]);
                fma2(acc[i][0], ad, bp.x);
                fma2(acc[i][1], ad, bp.y);
            }
        }
        __syncthreads();
    }
    float* outp = g_mhp[blockIdx.y];
#pragma unroll
    for (int i = 0; i < 4; i++) {
        float2 v0 = unpack2(acc[i][0]);
        float2 v1 = unpack2(acc[i][1]);
        *reinterpret_cast<float4*>(&outp[((my << 2) + i) * 1536 + n0 + (nx << 2)]) =
            make_float4(v0.x, v0.y, v1.x, v1.y);
    }
}

// ---------------- Recurrence kernel B: sum 8 partials + GRU gates ----------------
__global__ void __launch_bounds__(512) gru_gates_kernel(const int* __restrict__ y,
                                                        const float* __restrict__ gk,
                                                        const float* __restrict__ gb,
                                                        int u) {
    const int b = blockIdx.x;
    const int j = threadIdx.x;
    float hz = 0.f, hr = 0.f, hh = 0.f;
#pragma unroll
    for (int c = 0; c < 8; c++) {
        const float* p = g_mhp[c] + b * 1536;
        hz += p[j];
        hr += p[512 + j];
        hh += p[1024 + j];
    }
    const float* bi = gb;
    const float* br = gb + 1536;
    const int tok   = y[b * 201 + u];
    const float* gx = gk + (size_t)tok * 1536;
    float xz = gx[j]        + bi[j];
    float xr = gx[512 + j]  + bi[512 + j];
    float xh = gx[1024 + j] + bi[1024 + j];
    hz += br[j];
    hr += br[512 + j];
    hh += br[1024 + j];
    float z = 1.f / (1.f + expf(-(xz + hz)));
    float r = 1.f / (1.f + expf(-(xr + hr)));
    float cand = tanhf(xh + r * hh);
    float hold = g_hstate[u & 1][b * 512 + j];
    float hn = z * hold + (1.f - z) * cand;
    g_hstate[(u + 1) & 1][b * 512 + j] = hn;
    g_catall[((size_t)u * 32 + b) * 1024 + j] = hn;
}

// ---------------- Batched scores GEMM: per b, S[200,800] = H[200,512] @ enc_b^T ----------------
__global__ void __launch_bounds__(256, 2) scores_gemm_kernel() {
    __shared__ __align__(16) float As[16][128];
    __shared__ __align__(16) float Bs[16][128];
    const int tid = threadIdx.x;
    const int n0 = blockIdx.x * 128;
    const int m0 = blockIdx.y * 128;
    const int b  = blockIdx.z;
    const int tx = tid & 15;
    const int ty = tid >> 4;

    ull acc[8][4];
#pragma unroll
    for (int i = 0; i < 8; i++)
#pragma unroll
        for (int j = 0; j < 4; j++) acc[i][j] = 0ull;

    for (int k0 = 0; k0 < 512; k0 += 16) {
#pragma unroll
        for (int it = 0; it < 2; it++) {
            int s  = tid + it * 256;
            int kq = s & 3;
            int ml = s >> 2;
            int urow = m0 + ml;
            float4 av = make_float4(0.f, 0.f, 0.f, 0.f);
            if (urow < USTEPS)
                av = *reinterpret_cast<const float4*>(
                    g_catall + ((size_t)urow * 32 + b) * 1024 + k0 + (kq << 2));
            int pc = ml ^ (kq << 2);
            As[(kq << 2) + 0][pc] = av.x;
            As[(kq << 2) + 1][pc] = av.y;
            As[(kq << 2) + 2][pc] = av.z;
            As[(kq << 2) + 3][pc] = av.w;
        }
#pragma unroll
        for (int it = 0; it < 2; it++) {
            int s  = tid + it * 256;
            int dq = s & 3;
            int tl = s >> 2;
            int t  = n0 + tl;
            float4 bv = make_float4(0.f, 0.f, 0.f, 0.f);
            if (t < T1)
                bv = *reinterpret_cast<const float4*>(
                    g_h1 + ((size_t)b * T1 + t) * 512 + k0 + (dq << 2));
            int pc = tl ^ (dq << 2);
            Bs[(dq << 2) + 0][pc] = bv.x;
            Bs[(dq << 2) + 1][pc] = bv.y;
            Bs[(dq << 2) + 2][pc] = bv.z;
            Bs[(dq << 2) + 3][pc] = bv.w;
        }
        __syncthreads();

#pragma unroll
        for (int kk = 0; kk < 16; kk++) {
            const int sw = (kk >> 2) << 2;
            float4 a0 = *reinterpret_cast<const float4*>(&As[kk][(ty << 3) ^ sw]);
            float4 a1 = *reinterpret_cast<const float4*>(&As[kk][((ty << 3) + 4) ^ sw]);
            ulonglong2 bp0 = *reinterpret_cast<const ulonglong2*>(&Bs[kk][(tx << 3) ^ sw]);
            ulonglong2 bp1 = *reinterpret_cast<const ulonglong2*>(&Bs[kk][((tx << 3) + 4) ^ sw]);
            ull b0 = bp0.x, b1 = bp0.y, b2 = bp1.x, b3 = bp1.y;
            float av[8] = {a0.x, a0.y, a0.z, a0.w, a1.x, a1.y, a1.z, a1.w};
#pragma unroll
            for (int i = 0; i < 8; i++) {
                ull a2 = pack2(av[i]);
                fma2(acc[i][0], a2, b0);
                fma2(acc[i][1], a2, b1);
                fma2(acc[i][2], a2, b2);
                fma2(acc[i][3], a2, b3);
            }
        }
        __syncthreads();
    }

    const int t0 = n0 + (tx << 3);
#pragma unroll
    for (int i = 0; i < 8; i++) {
        int urow = m0 + (ty << 3) + i;
        if (urow < USTEPS && t0 < T1) {
            float2 p0v = unpack2(acc[i][0]);
            float2 p1v = unpack2(acc[i][1]);
            float2 p2v = unpack2(acc[i][2]);
            float2 p3v = unpack2(acc[i][3]);
            float* sp = g_scoresall + ((size_t)urow * 32 + b) * T1 + t0;
            *reinterpret_cast<float4*>(sp)     = make_float4(p0v.x, p0v.y, p1v.x, p1v.y);
            *reinterpret_cast<float4*>(sp + 4) = make_float4(p2v.x, p2v.y, p3v.x, p3v.y);
        }
    }
}

// ---------------- Batched softmax over 800 ----------------
__global__ void __launch_bounds__(256) sm800_kernel() {
    const int row = blockIdx.x;
    const int tid = threadIdx.x;
    float* sp = g_scoresall + (size_t)row * T1;
    __shared__ float sa[800];
    __shared__ float red[8], red2[8];
    const int w = tid >> 5, lane = tid & 31;

    float m = -1e30f;
    for (int t = tid; t < 800; t += 256) {
        float v = sp[t];
        sa[t] = v;
        m = fmaxf(m, v);
    }
#pragma unroll
    for (int o = 16; o; o >>= 1) m = fmaxf(m, __shfl_xor_sync(0xffffffffu, m, o));
    if (lane == 0) red[w] = m;
    __syncthreads();
    float mm = red[0];
#pragma unroll
    for (int i = 1; i < 8; i++) mm = fmaxf(mm, red[i]);

    float ps = 0.f;
    for (int t = tid; t < 800; t += 256) {
        float e = expf(sa[t] - mm);
        sa[t] = e;
        ps += e;
    }
#pragma unroll
    for (int o = 16; o; o >>= 1) ps += __shfl_xor_sync(0xffffffffu, ps, o);
    if (lane == 0) red2[w] = ps;
    __syncthreads();
    float sum = 0.f;
#pragma unroll
    for (int i = 0; i < 8; i++) sum += red2[i];
    const float inv = 1.f / sum;

    for (int t = tid; t < 800; t += 256) sp[t] = sa[t] * inv;
}

// ---------------- Batched ctx: per b, alpha[200,800] @ enc_b[800,512] ----------------
__global__ void __launch_bounds__(256, 2) ctx_gemm_kernel() {
    __shared__ __align__(16) float As[16][128];
    __shared__ __align__(16) float Bs[16][128];
    const int tid = threadIdx.x;
    const int n0 = blockIdx.x * 128;
    const int m0 = blockIdx.y * 128;
    const int b  = blockIdx.z;
    const int tx = tid & 15;
    const int ty = tid >> 4;

    ull acc[8][4];
#pragma unroll
    for (int i = 0; i < 8; i++)
#pragma unroll
        for (int j = 0; j < 4; j++) acc[i][j] = 0ull;

    for (int k0 = 0; k0 < 800; k0 += 16) {
#pragma unroll
        for (int it = 0; it < 2; it++) {
            int s  = tid + it * 256;
            int kq = s & 3;
            int ml = s >> 2;
            int u  = m0 + ml;
            float4 av = make_float4(0.f, 0.f, 0.f, 0.f);
            if (u < USTEPS)
                av = *reinterpret_cast<const float4*>(
                    g_scoresall + ((size_t)u * 32 + b) * T1 + k0 + (kq << 2));
            As[(kq << 2) + 0][ml] = av.x;
            As[(kq << 2) + 1][ml] = av.y;
            As[(kq << 2) + 2][ml] = av.z;
            As[(kq << 2) + 3][ml] = av.w;
        }
#pragma unroll
        for (int it = 0; it < 2; it++) {
            int s  = tid + it * 256;
            int cq = s & 31;
            int kr = s >> 5;
            *reinterpret_cast<float4*>(&Bs[kr][cq << 2]) =
                *reinterpret_cast<const float4*>(
                    g_h1 + ((size_t)b * T1 + k0 + kr) * 512 + n0 + (cq << 2));
        }
        __syncthreads();

#pragma unroll
        for (int kk = 0; kk < 16; kk++) {
            float4 a0 = *reinterpret_cast<const float4*>(&As[kk][ty << 3]);
            float4 a1 = *reinterpret_cast<const float4*>(&As[kk][(ty << 3) + 4]);
            ulonglong2 bp0 = *reinterpret_cast<const ulonglong2*>(&Bs[kk][(tx << 3)]);
            ulonglong2 bp1 = *reinterpret_cast<const ulonglong2*>(&Bs[kk][(tx << 3) + 4]);
            ull b0 = bp0.x, b1 = bp0.y, b2 = bp1.x, b3 = bp1.y;
            float av[8] = {a0.x, a0.y, a0.z, a0.w, a1.x, a1.y, a1.z, a1.w};
#pragma unroll
            for (int i = 0; i < 8; i++) {
                ull a2 = pack2(av[i]);
                fma2(acc[i][0], a2, b0);
                fma2(acc[i][1], a2, b1);
                fma2(acc[i][2], a2, b2);
                fma2(acc[i][3], a2, b3);
            }
        }
        __syncthreads();
    }

#pragma unroll
    for (int i = 0; i < 8; i++) {
        int u = m0 + (ty << 3) + i;
        if (u < USTEPS) {
            float2 p0v = unpack2(acc[i][0]);
            float2 p1v = unpack2(acc[i][1]);
            float2 p2v = unpack2(acc[i][2]);
            float2 p3v = unpack2(acc[i][3]);
            float* cp = g_catall + ((size_t)u * 32 + b) * 1024 + 512 + n0 + (tx << 3);
            *reinterpret_cast<float4*>(cp)     = make_float4(p0v.x, p0v.y, p1v.x, p1v.y);
            *reinterpret_cast<float4*>(cp + 4) = make_float4(p2v.x, p2v.y, p3v.x, p3v.y);
        }
    }
}

// ---------------- Batched FC ----------------
__global__ void __launch_bounds__(256, 2) fc_big_kernel(const float* __restrict__ fw,
                                                        const float* __restrict__ fb) {
    __shared__ __align__(16) float As[16][128];
    __shared__ __align__(16) float Bs[16][128];
    const int tid = threadIdx.x;
    const int n0 = blockIdx.x * 128;
    const int m0 = blockIdx.y * 128;
    const int tx = tid & 15;
    const int ty = tid >> 4;

    ull acc[8][4];
#pragma unroll
    for (int i = 0; i < 8; i++)
#pragma unroll
        for (int j = 0; j < 4; j++) acc[i][j] = 0ull;

    for (int p0 = 0; p0 < 1024; p0 += 16) {
#pragma unroll
        for (int it = 0; it < 2; it++) {
            int s  = tid + it * 256;
            int kq = s & 3;
            int ml = s >> 2;
            float4 av = *reinterpret_cast<const float4*>(
                g_catall + ((size_t)(m0 + ml)) * 1024 + p0 + (kq << 2));
            As[(kq << 2) + 0][ml] = av.x;
            As[(kq << 2) + 1][ml] = av.y;
            As[(kq << 2) + 2][ml] = av.z;
            As[(kq << 2) + 3][ml] = av.w;
        }
#pragma unroll
        for (int it = 0; it < 2; it++) {
            int s  = tid + it * 256;
            int cq = s & 31;
            int kr = s >> 5;
            int c  = n0 + (cq << 2);
            float4 v = make_float4(0.f, 0.f, 0.f, 0.f);
            if (c < 1000)
                v = *reinterpret_cast<const float4*>(fw + (size_t)(p0 + kr) * 1000 + c);
            *reinterpret_cast<float4*>(&Bs[kr][cq << 2]) = v;
        }
        __syncthreads();

#pragma unroll
        for (int kk = 0; kk < 16; kk++) {
            float4 a0 = *reinterpret_cast<const float4*>(&As[kk][ty << 3]);
            float4 a1 = *reinterpret_cast<const float4*>(&As[kk][(ty << 3) + 4]);
            ulonglong2 bp0 = *reinterpret_cast<const ulonglong2*>(&Bs[kk][(tx << 3)]);
            ulonglong2 bp1 = *reinterpret_cast<const ulonglong2*>(&Bs[kk][(tx << 3) + 4]);
            ull b0 = bp0.x, b1 = bp0.y, b2 = bp1.x, b3 = bp1.y;
            float av[8] = {a0.x, a0.y, a0.z, a0.w, a1.x, a1.y, a1.z, a1.w};
#pragma unroll
            for (int i = 0; i < 8; i++) {
                ull a2 = pack2(av[i]);
                fma2(acc[i][0], a2, b0);
                fma2(acc[i][1], a2, b1);
                fma2(acc[i][2], a2, b2);
                fma2(acc[i][3], a2, b3);
            }
        }
        __syncthreads();
    }

    const int c0 = n0 + (tx << 3);
    float bias[8];
#pragma unroll
    for (int j = 0; j < 8; j++) bias[j] = (c0 + j < 1000) ? fb[c0 + j] : 0.f;
#pragma unroll
    for (int i = 0; i < 8; i++) {
        int m = m0 + (ty << 3) + i;
        float2 p0v = unpack2(acc[i][0]);
        float2 p1v = unpack2(acc[i][1]);
        float2 p2v = unpack2(acc[i][2]);
        float2 p3v = unpack2(acc[i][3]);
        float4 r0 = make_float4(p0v.x + bias[0], p0v.y + bias[1], p1v.x + bias[2], p1v.y + bias[3]);
        float4 r1 = make_float4(p2v.x + bias[4], p2v.y + bias[5], p3v.x + bias[6], p3v.y + bias[7]);
        float* lp = g_logitsall + (size_t)m * 1000;
        if (c0 < 1000)     *reinterpret_cast<float4*>(lp + c0)     = r0;
        if (c0 + 4 < 1000) *reinterpret_cast<float4*>(lp + c0 + 4) = r1;
    }
}

// ---------------- Batched output softmax ----------------
__global__ void __launch_bounds__(256) outsm_all_kernel(float* __restrict__ out) {
    const int m = blockIdx.x;
    const int u = m >> 5, b = m & 31;
    const int tid = threadIdx.x;
    __shared__ float sh[1000];
    __shared__ float red[8], red2[8];
    const int w = tid >> 5, lane = tid & 31;
    const float* lp = g_logitsall + (size_t)m * 1000;

    float mx = -1e30f;
    for (int c = tid; c < 1000; c += 256) {
        float v = lp[c];
        sh[c] = v;
        mx = fmaxf(mx, v);
    }
#pragma unroll
    for (int o = 16; o; o >>= 1) mx = fmaxf(mx, __shfl_xor_sync(0xffffffffu, mx, o));
    if (lane == 0) red[w] = mx;
    __syncthreads();
    float mm = red[0];
#pragma unroll
    for (int i = 1; i < 8; i++) mm = fmaxf(mm, red[i]);

    float ps = 0.f;
    for (int c = tid; c < 1000; c += 256) {
        float e = expf(sh[c] - mm);
        sh[c] = e;
        ps += e;
    }
#pragma unroll
    for (int o = 16; o; o >>= 1) ps += __shfl_xor_sync(0xffffffffu, ps, o);
    if (lane == 0) red2[w] = ps;
    __syncthreads();
    float sum = 0.f;
#pragma unroll
    for (int i = 0; i < 8; i++) sum += red2[i];
    const float inv = 1.f / sum;

    float* op = out + ((size_t)b * USTEPS + u) * VOCABN;
    for (int c = tid; c < 1000; c += 256) op[c] = sh[c] * inv;
}

// ---------------- launch ----------------
extern "C" void kernel_launch(void* const* d_in, const int* in_sizes, int n_in,
                              void* d_out, int out_size) {
    const float* x        = (const float*)d_in[0];
    const int*   y        = (const int*)  d_in[1];
    const float* bn_gamma = (const float*)d_in[2];
    const float* bn_beta  = (const float*)d_in[3];
    const float* conv0_w  = (const float*)d_in[4];
    const float* conv0_b  = (const float*)d_in[5];
    const float* tcr_w    = (const float*)d_in[6];
    const float* tcr_b    = (const float*)d_in[7];
    const float* gru_k    = (const float*)d_in[8];
    const float* gru_rk   = (const float*)d_in[9];
    const float* gru_b    = (const float*)d_in[10];
    const float* fc_w     = (const float*)d_in[11];
    const float* fc_b     = (const float*)d_in[12];
    float* out = (float*)d_out;

    float *h1, *h2;
    __half *a0, *a1, *wh, *wl;
    cudaGetSymbolAddress((void**)&h1, g_h1);
    cudaGetSymbolAddress((void**)&h2, g_h2);
    cudaGetSymbolAddress((void**)&a0, g_sa0);
    cudaGetSymbolAddress((void**)&a1, g_sa1);
    cudaGetSymbolAddress((void**)&wh, g_wh);
    cudaGetSymbolAddress((void**)&wl, g_wl);

    // ---- encoder ----
    bn_stats_kernel<<<80, 256>>>(x, bn_gamma, bn_beta);
    zero_h_kernel<<<32, 512>>>();
    dim3 wgrid(80, 16, 4);          // 2560/32, 512/32, 4 layers
    wsplit_kernel<<<wgrid, dim3(32, 8)>>>(tcr_w);

    dim3 cgrid(4, 200);
    conv5x_kernel<80, 1600, 800, 2, 1, true, false, true><<<cgrid, 256>>>(
        x, conv0_w, conv0_b, h1, a0);

    const size_t WT = (size_t)512 * 2560;
    dim3 tgrid(4, 200);
    tcr_mma_kernel<true><<<tgrid, 256>>>(
        a0, wh + 0 * WT, wl + 0 * WT, h1, tcr_b + 0 * 512, h2, a1);
    tcr_mma_kernel<true><<<tgrid, 256>>>(
        a1, wh + 1 * WT, wl + 1 * WT, h2, tcr_b + 1 * 512, h1, a0);
    tcr_mma_kernel<true><<<tgrid, 256>>>(
        a0, wh + 2 * WT, wl + 2 * WT, h1, tcr_b + 2 * 512, h2, a1);
    tcr_mma_kernel<false><<<tgrid, 256>>>(
        a1, wh + 3 * WT, wl + 3 * WT, h2, tcr_b + 3 * 512, h1, nullptr);
    // enc lives in g_h1 (fp32)

    // ---- GRU recurrence: 2 kernels per step, 8-way k-split (96 blocks) ----
    dim3 pgrid(12, 8);
    for (int u = 0; u < USTEPS; u++) {
        gru_part_kernel<<<pgrid, 256>>>(gru_rk, u);
        gru_gates_kernel<<<32, 512>>>(y, gru_k, gru_b, u);
    }

    // ---- batched tail ----
    dim3 sgrid(7, 2, 32);
    scores_gemm_kernel<<<sgrid, 256>>>();
    sm800_kernel<<<USTEPS * B_, 256>>>();
    dim3 xgrid(4, 2, 32);
    ctx_gemm_kernel<<<xgrid, 256>>>();
    dim3 fgrid(8, 50);
    fc_big_kernel<<<fgrid, 256>>>(fc_w, fc_b);
    outsm_all_kernel<<<USTEPS * B_, 256>>>(out);
}

// round 13
// speedup vs baseline: 1.6927x; 1.2781x over previous
#include <cuda_runtime.h>
#include <cuda_fp16.h>
#include <cstdint>
#include <math.h>

typedef unsigned long long ull;
typedef unsigned int uint;

#define B_     32
#define T0     1600
#define C0     80
#define T1     800
#define D_     512
#define VOCABN 1000
#define HIDN   512
#define USTEPS 200
#define EPSV   1e-3f

// ---------------- scratch (static device globals; no allocation) ----------------
__device__ float g_bn[160];
__device__ float g_h1[B_ * T1 * D_];                // fp32 activations (enc ends here)
__device__ float g_h2[B_ * T1 * D_];
__device__ float g_hstate[2][B_ * HIDN];
__device__ float g_mhp[8][B_ * 1536];               // k-split partials of h @ grk
__device__ float g_scoresall[USTEPS * B_ * T1];
__device__ float g_catall[USTEPS * B_ * 1024];
__device__ float g_logitsall[USTEPS * B_ * VOCABN];
// fp16 activations (ping-pong) and fp16 transposed weights [l][n][kin]
__device__ __half g_sa0[B_ * T1 * D_];
__device__ __half g_sa1[B_ * T1 * D_];
__device__ __half g_wh[4 * 512 * 2560];

// ---------------- packed f32x2 helpers (FFMA2) ----------------
__device__ __forceinline__ void fma2(ull& d, ull a, ull b) {
    asm("fma.rn.f32x2 %0, %1, %2, %0;" : "+l"(d) : "l"(a), "l"(b));
}
__device__ __forceinline__ ull pack2(float x) {
    ull r;
    asm("mov.b64 %0, {%1, %1};" : "=l"(r) : "f"(x));
    return r;
}
__device__ __forceinline__ float2 unpack2(ull v) {
    float2 f;
    asm("mov.b64 {%0, %1}, %2;" : "=f"(f.x), "=f"(f.y) : "l"(v));
    return f;
}

// ---------------- mma.sync / ldmatrix helpers (sm_80+ portable) ----------------
__device__ __forceinline__ uint32_t smem_to_u32(const void* p) {
    uint32_t a;
    asm("{ .reg .u64 t; cvta.to.shared.u64 t, %1; cvt.u32.u64 %0, t; }" : "=r"(a) : "l"(p));
    return a;
}
__device__ __forceinline__ void mma_f16(float* d, const uint32_t* a, const uint32_t* b) {
    asm volatile(
        "mma.sync.aligned.m16n8k16.row.col.f32.f16.f16.f32 "
        "{%0,%1,%2,%3}, {%4,%5,%6,%7}, {%8,%9}, {%0,%1,%2,%3};"
        : "+f"(d[0]), "+f"(d[1]), "+f"(d[2]), "+f"(d[3])
        : "r"(a[0]), "r"(a[1]), "r"(a[2]), "r"(a[3]), "r"(b[0]), "r"(b[1]));
}
__device__ __forceinline__ void ldsm4(uint32_t* r, uint32_t addr) {
    asm volatile("ldmatrix.sync.aligned.m8n8.x4.shared.b16 {%0,%1,%2,%3}, [%4];"
                 : "=r"(r[0]), "=r"(r[1]), "=r"(r[2]), "=r"(r[3]) : "r"(addr));
}

// ---------------- BatchNorm statistics ----------------
__global__ void __launch_bounds__(256) bn_stats_kernel(const float* __restrict__ x,
                                                       const float* __restrict__ gamma,
                                                       const float* __restrict__ beta) {
    const int c = blockIdx.x;
    const int tid = threadIdx.x;
    const int N = B_ * T0;
    float s = 0.f, sq = 0.f;
    for (int i = tid; i < N; i += 256) {
        float v = x[(size_t)i * C0 + c];
        s += v; sq += v * v;
    }
    __shared__ float rs[256], rq[256];
    rs[tid] = s; rq[tid] = sq;
    __syncthreads();
    for (int o = 128; o > 0; o >>= 1) {
        if (tid < o) { rs[tid] += rs[tid + o]; rq[tid] += rq[tid + o]; }
        __syncthreads();
    }
    if (tid == 0) {
        float mean = rs[0] / (float)N;
        float var  = rq[0] / (float)N - mean * mean;
        float sc   = gamma[c] * rsqrtf(var + EPSV);
        g_bn[c]      = sc;
        g_bn[80 + c] = beta[c] - mean * sc;
    }
}

__global__ void __launch_bounds__(512) zero_h_kernel() {
    int i = blockIdx.x * blockDim.x + threadIdx.x;
    if (i < B_ * HIDN) g_hstate[0][i] = 0.f;
}

// ---------------- weight transpose to fp16: tcr_w [l][kin][512] -> wh[l][n][kin] ----------------
__global__ void __launch_bounds__(256) wsplit_kernel(const float* __restrict__ tcr_w) {
    __shared__ float tile[32][33];
    const int l  = blockIdx.z;
    const int k0 = blockIdx.x * 32;
    const int n0 = blockIdx.y * 32;
    const int tx = threadIdx.x, ty = threadIdx.y;   // 32 x 8
#pragma unroll
    for (int j = 0; j < 32; j += 8)
        tile[ty + j][tx] = tcr_w[((size_t)l * 2560 + k0 + ty + j) * 512 + n0 + tx];
    __syncthreads();
#pragma unroll
    for (int j = 0; j < 32; j += 8) {
        float v = tile[tx][ty + j];
        size_t di = ((size_t)l * 512 + n0 + ty + j) * 2560 + k0 + tx;
        g_wh[di] = __float2half_rn(v);
    }
}

// ---------------- conv0: implicit-im2col SGEMM 128x128x32 FFMA2 (+ fp16 epilogue) ----------------
template<int CIN, int TIN, int TOUT, int STRIDE, int PADL, bool FUSE_BN, bool RESID, bool SPLIT>
__global__ void __launch_bounds__(256, 2) conv5x_kernel(const float* __restrict__ in,
                                                        const float* __restrict__ w,
                                                        const float* __restrict__ bias,
                                                        float* __restrict__ out,
                                                        __half* __restrict__ oh) {
    __shared__ __align__(16) float As[32][128];
    __shared__ __align__(16) float Bs[32][128];
    __shared__ __align__(16) float s_bn[160];

    const int tid = threadIdx.x;
    if (FUSE_BN && tid < 160) s_bn[tid] = g_bn[tid];

    const int n0 = blockIdx.x * 128;
    const int m0 = blockIdx.y * 128;
    const int tx = tid & 15;
    const int ty = tid >> 4;

    ull acc[4][8];
#pragma unroll
    for (int i = 0; i < 4; i++)
#pragma unroll
        for (int j = 0; j < 8; j++) acc[i][j] = 0ull;

    __syncthreads();

    const int KIN = 5 * CIN;
    for (int p0 = 0; p0 < KIN; p0 += 32) {
#pragma unroll
        for (int it = 0; it < 4; it++) {
            int s  = tid + it * 256;
            int kq = s & 7;
            int ml = s >> 3;
            int p  = p0 + (kq << 2);
            int k  = p / CIN;
            int ci = p - k * CIN;
            int m  = m0 + ml;
            int bb = m / TOUT;
            int t  = m - bb * TOUT;
            int tin = t * STRIDE - PADL + k;
            float4 av = make_float4(0.f, 0.f, 0.f, 0.f);
            if (tin >= 0 && tin < TIN && p < KIN) {
                av = *reinterpret_cast<const float4*>(in + ((size_t)bb * TIN + tin) * CIN + ci);
                if (FUSE_BN) {
                    float4 sc = *reinterpret_cast<const float4*>(&s_bn[ci]);
                    float4 sh = *reinterpret_cast<const float4*>(&s_bn[80 + ci]);
                    av.x = av.x * sc.x + sh.x;
                    av.y = av.y * sc.y + sh.y;
                    av.z = av.z * sc.z + sh.z;
                    av.w = av.w * sc.w + sh.w;
                }
            }
            int pc = ml ^ (kq << 2);
            As[(kq << 2) + 0][pc] = av.x;
            As[(kq << 2) + 1][pc] = av.y;
            As[(kq << 2) + 2][pc] = av.z;
            As[(kq << 2) + 3][pc] = av.w;
        }
#pragma unroll
        for (int it = 0; it < 4; it++) {
            int s  = tid + it * 256;
            int cq = s & 31;
            int kr = s >> 5;
            float4 v = make_float4(0.f, 0.f, 0.f, 0.f);
            if (p0 + kr < KIN)
                v = *reinterpret_cast<const float4*>(w + (size_t)(p0 + kr) * 512 + n0 + (cq << 2));
            *reinterpret_cast<float4*>(&Bs[kr][cq << 2]) = v;
        }
        __syncthreads();

#pragma unroll
        for (int kk = 0; kk < 32; kk++) {
            const int sw = (kk >> 2) << 2;
            ulonglong2 ap0 = *reinterpret_cast<const ulonglong2*>(&As[kk][(ty << 3) ^ sw]);
            ulonglong2 ap1 = *reinterpret_cast<const ulonglong2*>(&As[kk][((ty << 3) + 4) ^ sw]);
            ull ap[4] = {ap0.x, ap0.y, ap1.x, ap1.y};
            float4 bA = *reinterpret_cast<const float4*>(&Bs[kk][tx << 2]);
            float4 bB = *reinterpret_cast<const float4*>(&Bs[kk][64 + (tx << 2)]);
            ull bd[8];
            bd[0] = pack2(bA.x); bd[1] = pack2(bA.y); bd[2] = pack2(bA.z); bd[3] = pack2(bA.w);
            bd[4] = pack2(bB.x); bd[5] = pack2(bB.y); bd[6] = pack2(bB.z); bd[7] = pack2(bB.w);
#pragma unroll
            for (int mp = 0; mp < 4; mp++)
#pragma unroll
                for (int n = 0; n < 8; n++) fma2(acc[mp][n], ap[mp], bd[n]);
        }
        __syncthreads();
    }

    const int c0 = n0 + (tx << 2);
    const int c1 = n0 + 64 + (tx << 2);
    const float4 bias0 = *reinterpret_cast<const float4*>(bias + c0);
    const float4 bias1 = *reinterpret_cast<const float4*>(bias + c1);
    float2 u0[4][4], u1[4][4];
#pragma unroll
    for (int mp = 0; mp < 4; mp++)
#pragma unroll
        for (int n = 0; n < 4; n++) {
            u0[mp][n] = unpack2(acc[mp][n]);
            u1[mp][n] = unpack2(acc[mp][4 + n]);
        }
#pragma unroll
    for (int i = 0; i < 8; i++) {
        const int mp = i >> 1;
        const bool hi = i & 1;
        int m = m0 + (ty << 3) + i;
        float4 r0, r1;
        r0.x = fmaxf((hi ? u0[mp][0].y : u0[mp][0].x) + bias0.x, 0.f);
        r0.y = fmaxf((hi ? u0[mp][1].y : u0[mp][1].x) + bias0.y, 0.f);
        r0.z = fmaxf((hi ? u0[mp][2].y : u0[mp][2].x) + bias0.z, 0.f);
        r0.w = fmaxf((hi ? u0[mp][3].y : u0[mp][3].x) + bias0.w, 0.f);
        r1.x = fmaxf((hi ? u1[mp][0].y : u1[mp][0].x) + bias1.x, 0.f);
        r1.y = fmaxf((hi ? u1[mp][1].y : u1[mp][1].x) + bias1.y, 0.f);
        r1.z = fmaxf((hi ? u1[mp][2].y : u1[mp][2].x) + bias1.z, 0.f);
        r1.w = fmaxf((hi ? u1[mp][3].y : u1[mp][3].x) + bias1.w, 0.f);
        if (RESID) {
            float4 e0 = *reinterpret_cast<const float4*>(in + (size_t)m * CIN + c0);
            float4 e1 = *reinterpret_cast<const float4*>(in + (size_t)m * CIN + c1);
            r0.x += e0.x; r0.y += e0.y; r0.z += e0.z; r0.w += e0.w;
            r1.x += e1.x; r1.y += e1.y; r1.z += e1.z; r1.w += e1.w;
        }
        *reinterpret_cast<float4*>(out + (size_t)m * 512 + c0) = r0;
        *reinterpret_cast<float4*>(out + (size_t)m * 512 + c1) = r1;
        if (SPLIT) {
            __half* hp = oh + (size_t)m * 512;
            *reinterpret_cast<__half2*>(hp + c0)     = __floats2half2_rn(r0.x, r0.y);
            *reinterpret_cast<__half2*>(hp + c0 + 2) = __floats2half2_rn(r0.z, r0.w);
            *reinterpret_cast<__half2*>(hp + c1)     = __floats2half2_rn(r1.x, r1.y);
            *reinterpret_cast<__half2*>(hp + c1 + 2) = __floats2half2_rn(r1.z, r1.w);
        }
    }
}

// ---------------- tcr conv layer on mma.sync (pure fp16, single product) ----------------
// CTA 128x128, 8 warps (4m x 2n). K-chunk 64 (40 chunks). smem rows 72 halves (144 B):
// 8 rows at stride 144 hit i*16 mod 128 -> all banks, conflict-free ldmatrix.
// B stored [n][k] -> non-trans ldmatrix yields the .col B fragment directly.
#define ASTR 72
template<bool SPLIT>
__global__ void __launch_bounds__(256, 2) tcr_mma_kernel(const __half* __restrict__ a16,
                                                         const __half* __restrict__ wh,
                                                         const float* __restrict__ resid_in,
                                                         const float* __restrict__ bias,
                                                         float* __restrict__ out,
                                                         __half* __restrict__ oh) {
    __shared__ __align__(16) __half sA[128 * ASTR];
    __shared__ __align__(16) __half sB[128 * ASTR];

    const int tid = threadIdx.x;
    const int wid = tid >> 5, lane = tid & 31;
    const int n0 = blockIdx.x * 128;
    const int m0 = blockIdx.y * 128;
    const int warp_m = (wid >> 1) << 5;    // 0,32,64,96
    const int warp_n = (wid & 1) << 6;     // 0,64

    float acc[2][8][4];
#pragma unroll
    for (int i = 0; i < 2; i++)
#pragma unroll
        for (int j = 0; j < 8; j++)
#pragma unroll
            for (int r = 0; r < 4; r++) acc[i][j][r] = 0.f;

    const int lq = tid & 7;       // 16B quad within 128B row payload
    const int lrow = tid >> 3;    // 0..31

    const uint32_t aAddr = smem_to_u32(sA) + (warp_m + (lane & 15)) * 144 + (lane >> 4) * 16;
    const int browoff = warp_n + (lane & 7) + ((lane >> 4) & 1) * 8;
    const uint32_t bAddr = smem_to_u32(sB) + browoff * 144 + ((lane >> 3) & 1) * 16;

    for (int c = 0; c < 40; c++) {
        const int tap = c >> 3;
        const int ci0 = (c & 7) << 6;
        // ---- load A: 128 rows x 64 fp16 (4 iters x 32 rows) ----
#pragma unroll
        for (int it = 0; it < 4; it++) {
            int ml = lrow + it * 32;
            int m  = m0 + ml;
            int bb = m / T1;
            int t  = m - bb * T1;
            int tin = t + tap - 2;
            uint4 va = make_uint4(0, 0, 0, 0);
            if (tin >= 0 && tin < T1)
                va = *reinterpret_cast<const uint4*>(a16 + ((size_t)bb * T1 + tin) * 512 + ci0 + lq * 8);
            *reinterpret_cast<uint4*>(&sA[ml * ASTR + lq * 8]) = va;
        }
        // ---- load B: 128 n-rows x 64 fp16 ----
#pragma unroll
        for (int it = 0; it < 4; it++) {
            int nl = lrow + it * 32;
            size_t src = (size_t)(n0 + nl) * 2560 + c * 64 + lq * 8;
            *reinterpret_cast<uint4*>(&sB[nl * ASTR + lq * 8]) = *reinterpret_cast<const uint4*>(wh + src);
        }
        __syncthreads();

#pragma unroll
        for (int s = 0; s < 4; s++) {
            uint32_t a[2][4];
            ldsm4(a[0], aAddr + s * 32);
            ldsm4(a[1], aAddr + s * 32 + 16 * 144);
#pragma unroll
            for (int jj = 0; jj < 4; jj++) {
                uint32_t b[4];
                ldsm4(b, bAddr + s * 32 + jj * 16 * 144);
#pragma unroll
                for (int i = 0; i < 2; i++) {
                    mma_f16(acc[i][2 * jj],     a[i], b);
                    mma_f16(acc[i][2 * jj + 1], a[i], b + 2);
                }
            }
        }
        __syncthreads();
    }

    // ---- epilogue: bias + relu + residual (+ fp16 emit) ----
    const int r0 = lane >> 2;
    const int cc = (lane & 3) * 2;
#pragma unroll
    for (int i = 0; i < 2; i++) {
        int mrow = m0 + warp_m + i * 16 + r0;
#pragma unroll
        for (int j = 0; j < 8; j++) {
            int col = n0 + warp_n + j * 8 + cc;
            float2 b2 = *reinterpret_cast<const float2*>(bias + col);
#pragma unroll
            for (int half = 0; half < 2; half++) {
                int m = mrow + half * 8;
                float va = acc[i][j][half * 2 + 0];
                float vb = acc[i][j][half * 2 + 1];
                float2 e = *reinterpret_cast<const float2*>(resid_in + (size_t)m * 512 + col);
                float2 v;
                v.x = fmaxf(va + b2.x, 0.f) + e.x;
                v.y = fmaxf(vb + b2.y, 0.f) + e.y;
                *reinterpret_cast<float2*>(out + (size_t)m * 512 + col) = v;
                if (SPLIT)
                    *reinterpret_cast<__half2*>(oh + (size_t)m * 512 + col) = __floats2half2_rn(v.x, v.y);
            }
        }
    }
}

// ---------------- Recurrence kernel A: mh partials (k-split x8 GEMM) ----------------
// grid (12 n-tiles, 8 k-chunks of 64) = 96 blocks.
__global__ void __launch_bounds__(256) gru_part_kernel(const float* __restrict__ grk, int u) {
    __shared__ float Hs[16][33];
    __shared__ __align__(16) float Ws[16][128];
    const float* h = g_hstate[u & 1];
    const int tid = threadIdx.x;
    const int n0 = blockIdx.x * 128;
    const int kb = blockIdx.y * 64;
    const int nx = tid & 31;
    const int my = tid >> 5;

    ull acc[4][2];
#pragma unroll
    for (int i = 0; i < 4; i++) { acc[i][0] = 0ull; acc[i][1] = 0ull; }

    for (int k0 = 0; k0 < 64; k0 += 16) {
#pragma unroll
        for (int it = 0; it < 2; it++) {
            int e = tid + it * 256;
            int kk = e & 15, m = e >> 4;
            Hs[kk][m] = h[m * 512 + kb + k0 + kk];
        }
#pragma unroll
        for (int it = 0; it < 2; it++) {
            int s = tid + it * 256;
            int cq = s & 31, kr = s >> 5;
            *reinterpret_cast<float4*>(&Ws[kr][cq << 2]) =
                *reinterpret_cast<const float4*>(grk + (size_t)(kb + k0 + kr) * 1536 + n0 + (cq << 2));
        }
        __syncthreads();
#pragma unroll
        for (int kk = 0; kk < 16; kk++) {
            ulonglong2 bp = *reinterpret_cast<const ulonglong2*>(&Ws[kk][nx << 2]);
#pragma unroll
            for (int i = 0; i < 4; i++) {
                ull ad = pack2(Hs[kk][(my << 2) + i]);
                fma2(acc[i][0], ad, bp.x);
                fma2(acc[i][1], ad, bp.y);
            }
        }
        __syncthreads();
    }
    float* outp = g_mhp[blockIdx.y];
#pragma unroll
    for (int i = 0; i < 4; i++) {
        float2 v0 = unpack2(acc[i][0]);
        float2 v1 = unpack2(acc[i][1]);
        *reinterpret_cast<float4*>(&outp[((my << 2) + i) * 1536 + n0 + (nx << 2)]) =
            make_float4(v0.x, v0.y, v1.x, v1.y);
    }
}

// ---------------- Recurrence kernel B: sum 8 partials + GRU gates ----------------
__global__ void __launch_bounds__(512) gru_gates_kernel(const int* __restrict__ y,
                                                        const float* __restrict__ gk,
                                                        const float* __restrict__ gb,
                                                        int u) {
    const int b = blockIdx.x;
    const int j = threadIdx.x;
    float hz = 0.f, hr = 0.f, hh = 0.f;
#pragma unroll
    for (int c = 0; c < 8; c++) {
        const float* p = g_mhp[c] + b * 1536;
        hz += p[j];
        hr += p[512 + j];
        hh += p[1024 + j];
    }
    const float* bi = gb;
    const float* br = gb + 1536;
    const int tok   = y[b * 201 + u];
    const float* gx = gk + (size_t)tok * 1536;
    float xz = gx[j]        + bi[j];
    float xr = gx[512 + j]  + bi[512 + j];
    float xh = gx[1024 + j] + bi[1024 + j];
    hz += br[j];
    hr += br[512 + j];
    hh += br[1024 + j];
    float z = 1.f / (1.f + expf(-(xz + hz)));
    float r = 1.f / (1.f + expf(-(xr + hr)));
    float cand = tanhf(xh + r * hh);
    float hold = g_hstate[u & 1][b * 512 + j];
    float hn = z * hold + (1.f - z) * cand;
    g_hstate[(u + 1) & 1][b * 512 + j] = hn;
    g_catall[((size_t)u * 32 + b) * 1024 + j] = hn;
}

// ---------------- Batched scores GEMM: per b, S[200,800] = H[200,512] @ enc_b^T ----------------
__global__ void __launch_bounds__(256, 2) scores_gemm_kernel() {
    __shared__ __align__(16) float As[16][128];
    __shared__ __align__(16) float Bs[16][128];
    const int tid = threadIdx.x;
    const int n0 = blockIdx.x * 128;
    const int m0 = blockIdx.y * 128;
    const int b  = blockIdx.z;
    const int tx = tid & 15;
    const int ty = tid >> 4;

    ull acc[8][4];
#pragma unroll
    for (int i = 0; i < 8; i++)
#pragma unroll
        for (int j = 0; j < 4; j++) acc[i][j] = 0ull;

    for (int k0 = 0; k0 < 512; k0 += 16) {
#pragma unroll
        for (int it = 0; it < 2; it++) {
            int s  = tid + it * 256;
            int kq = s & 3;
            int ml = s >> 2;
            int urow = m0 + ml;
            float4 av = make_float4(0.f, 0.f, 0.f, 0.f);
            if (urow < USTEPS)
                av = *reinterpret_cast<const float4*>(
                    g_catall + ((size_t)urow * 32 + b) * 1024 + k0 + (kq << 2));
            int pc = ml ^ (kq << 2);
            As[(kq << 2) + 0][pc] = av.x;
            As[(kq << 2) + 1][pc] = av.y;
            As[(kq << 2) + 2][pc] = av.z;
            As[(kq << 2) + 3][pc] = av.w;
        }
#pragma unroll
        for (int it = 0; it < 2; it++) {
            int s  = tid + it * 256;
            int dq = s & 3;
            int tl = s >> 2;
            int t  = n0 + tl;
            float4 bv = make_float4(0.f, 0.f, 0.f, 0.f);
            if (t < T1)
                bv = *reinterpret_cast<const float4*>(
                    g_h1 + ((size_t)b * T1 + t) * 512 + k0 + (dq << 2));
            int pc = tl ^ (dq << 2);
            Bs[(dq << 2) + 0][pc] = bv.x;
            Bs[(dq << 2) + 1][pc] = bv.y;
            Bs[(dq << 2) + 2][pc] = bv.z;
            Bs[(dq << 2) + 3][pc] = bv.w;
        }
        __syncthreads();

#pragma unroll
        for (int kk = 0; kk < 16; kk++) {
            const int sw = (kk >> 2) << 2;
            float4 a0 = *reinterpret_cast<const float4*>(&As[kk][(ty << 3) ^ sw]);
            float4 a1 = *reinterpret_cast<const float4*>(&As[kk][((ty << 3) + 4) ^ sw]);
            ulonglong2 bp0 = *reinterpret_cast<const ulonglong2*>(&Bs[kk][(tx << 3) ^ sw]);
            ulonglong2 bp1 = *reinterpret_cast<const ulonglong2*>(&Bs[kk][((tx << 3) + 4) ^ sw]);
            ull b0 = bp0.x, b1 = bp0.y, b2 = bp1.x, b3 = bp1.y;
            float av[8] = {a0.x, a0.y, a0.z, a0.w, a1.x, a1.y, a1.z, a1.w};
#pragma unroll
            for (int i = 0; i < 8; i++) {
                ull a2 = pack2(av[i]);
                fma2(acc[i][0], a2, b0);
                fma2(acc[i][1], a2, b1);
                fma2(acc[i][2], a2, b2);
                fma2(acc[i][3], a2, b3);
            }
        }
        __syncthreads();
    }

    const int t0 = n0 + (tx << 3);
#pragma unroll
    for (int i = 0; i < 8; i++) {
        int urow = m0 + (ty << 3) + i;
        if (urow < USTEPS && t0 < T1) {
            float2 p0v = unpack2(acc[i][0]);
            float2 p1v = unpack2(acc[i][1]);
            float2 p2v = unpack2(acc[i][2]);
            float2 p3v = unpack2(acc[i][3]);
            float* sp = g_scoresall + ((size_t)urow * 32 + b) * T1 + t0;
            *reinterpret_cast<float4*>(sp)     = make_float4(p0v.x, p0v.y, p1v.x, p1v.y);
            *reinterpret_cast<float4*>(sp + 4) = make_float4(p2v.x, p2v.y, p3v.x, p3v.y);
        }
    }
}

// ---------------- Batched softmax over 800 ----------------
__global__ void __launch_bounds__(256) sm800_kernel() {
    const int row = blockIdx.x;
    const int tid = threadIdx.x;
    float* sp = g_scoresall + (size_t)row * T1;
    __shared__ float sa[800];
    __shared__ float red[8], red2[8];
    const int w = tid >> 5, lane = tid & 31;

    float m = -1e30f;
    for (int t = tid; t < 800; t += 256) {
        float v = sp[t];
        sa[t] = v;
        m = fmaxf(m, v);
    }
#pragma unroll
    for (int o = 16; o; o >>= 1) m = fmaxf(m, __shfl_xor_sync(0xffffffffu, m, o));
    if (lane == 0) red[w] = m;
    __syncthreads();
    float mm = red[0];
#pragma unroll
    for (int i = 1; i < 8; i++) mm = fmaxf(mm, red[i]);

    float ps = 0.f;
    for (int t = tid; t < 800; t += 256) {
        float e = expf(sa[t] - mm);
        sa[t] = e;
        ps += e;
    }
#pragma unroll
    for (int o = 16; o; o >>= 1) ps += __shfl_xor_sync(0xffffffffu, ps, o);
    if (lane == 0) red2[w] = ps;
    __syncthreads();
    float sum = 0.f;
#pragma unroll
    for (int i = 0; i < 8; i++) sum += red2[i];
    const float inv = 1.f / sum;

    for (int t = tid; t < 800; t += 256) sp[t] = sa[t] * inv;
}

// ---------------- Batched ctx: per b, alpha[200,800] @ enc_b[800,512] ----------------
__global__ void __launch_bounds__(256, 2) ctx_gemm_kernel() {
    __shared__ __align__(16) float As[16][128];
    __shared__ __align__(16) float Bs[16][128];
    const int tid = threadIdx.x;
    const int n0 = blockIdx.x * 128;
    const int m0 = blockIdx.y * 128;
    const int b  = blockIdx.z;
    const int tx = tid & 15;
    const int ty = tid >> 4;

    ull acc[8][4];
#pragma unroll
    for (int i = 0; i < 8; i++)
#pragma unroll
        for (int j = 0; j < 4; j++) acc[i][j] = 0ull;

    for (int k0 = 0; k0 < 800; k0 += 16) {
#pragma unroll
        for (int it = 0; it < 2; it++) {
            int s  = tid + it * 256;
            int kq = s & 3;
            int ml = s >> 2;
            int u  = m0 + ml;
            float4 av = make_float4(0.f, 0.f, 0.f, 0.f);
            if (u < USTEPS)
                av = *reinterpret_cast<const float4*>(
                    g_scoresall + ((size_t)u * 32 + b) * T1 + k0 + (kq << 2));
            As[(kq << 2) + 0][ml] = av.x;
            As[(kq << 2) + 1][ml] = av.y;
            As[(kq << 2) + 2][ml] = av.z;
            As[(kq << 2) + 3][ml] = av.w;
        }
#pragma unroll
        for (int it = 0; it < 2; it++) {
            int s  = tid + it * 256;
            int cq = s & 31;
            int kr = s >> 5;
            *reinterpret_cast<float4*>(&Bs[kr][cq << 2]) =
                *reinterpret_cast<const float4*>(
                    g_h1 + ((size_t)b * T1 + k0 + kr) * 512 + n0 + (cq << 2));
        }
        __syncthreads();

#pragma unroll
        for (int kk = 0; kk < 16; kk++) {
            float4 a0 = *reinterpret_cast<const float4*>(&As[kk][ty << 3]);
            float4 a1 = *reinterpret_cast<const float4*>(&As[kk][(ty << 3) + 4]);
            ulonglong2 bp0 = *reinterpret_cast<const ulonglong2*>(&Bs[kk][(tx << 3)]);
            ulonglong2 bp1 = *reinterpret_cast<const ulonglong2*>(&Bs[kk][(tx << 3) + 4]);
            ull b0 = bp0.x, b1 = bp0.y, b2 = bp1.x, b3 = bp1.y;
            float av[8] = {a0.x, a0.y, a0.z, a0.w, a1.x, a1.y, a1.z, a1.w};
#pragma unroll
            for (int i = 0; i < 8; i++) {
                ull a2 = pack2(av[i]);
                fma2(acc[i][0], a2, b0);
                fma2(acc[i][1], a2, b1);
                fma2(acc[i][2], a2, b2);
                fma2(acc[i][3], a2, b3);
            }
        }
        __syncthreads();
    }

#pragma unroll
    for (int i = 0; i < 8; i++) {
        int u = m0 + (ty << 3) + i;
        if (u < USTEPS) {
            float2 p0v = unpack2(acc[i][0]);
            float2 p1v = unpack2(acc[i][1]);
            float2 p2v = unpack2(acc[i][2]);
            float2 p3v = unpack2(acc[i][3]);
            float* cp = g_catall + ((size_t)u * 32 + b) * 1024 + 512 + n0 + (tx << 3);
            *reinterpret_cast<float4*>(cp)     = make_float4(p0v.x, p0v.y, p1v.x, p1v.y);
            *reinterpret_cast<float4*>(cp + 4) = make_float4(p2v.x, p2v.y, p3v.x, p3v.y);
        }
    }
}

// ---------------- Batched FC ----------------
__global__ void __launch_bounds__(256, 2) fc_big_kernel(const float* __restrict__ fw,
                                                        const float* __restrict__ fb) {
    __shared__ __align__(16) float As[16][128];
    __shared__ __align__(16) float Bs[16][128];
    const int tid = threadIdx.x;
    const int n0 = blockIdx.x * 128;
    const int m0 = blockIdx.y * 128;
    const int tx = tid & 15;
    const int ty = tid >> 4;

    ull acc[8][4];
#pragma unroll
    for (int i = 0; i < 8; i++)
#pragma unroll
        for (int j = 0; j < 4; j++) acc[i][j] = 0ull;

    for (int p0 = 0; p0 < 1024; p0 += 16) {
#pragma unroll
        for (int it = 0; it < 2; it++) {
            int s  = tid + it * 256;
            int kq = s & 3;
            int ml = s >> 2;
            float4 av = *reinterpret_cast<const float4*>(
                g_catall + ((size_t)(m0 + ml)) * 1024 + p0 + (kq << 2));
            As[(kq << 2) + 0][ml] = av.x;
            As[(kq << 2) + 1][ml] = av.y;
            As[(kq << 2) + 2][ml] = av.z;
            As[(kq << 2) + 3][ml] = av.w;
        }
#pragma unroll
        for (int it = 0; it < 2; it++) {
            int s  = tid + it * 256;
            int cq = s & 31;
            int kr = s >> 5;
            int c  = n0 + (cq << 2);
            float4 v = make_float4(0.f, 0.f, 0.f, 0.f);
            if (c < 1000)
                v = *reinterpret_cast<const float4*>(fw + (size_t)(p0 + kr) * 1000 + c);
            *reinterpret_cast<float4*>(&Bs[kr][cq << 2]) = v;
        }
        __syncthreads();

#pragma unroll
        for (int kk = 0; kk < 16; kk++) {
            float4 a0 = *reinterpret_cast<const float4*>(&As[kk][ty << 3]);
            float4 a1 = *reinterpret_cast<const float4*>(&As[kk][(ty << 3) + 4]);
            ulonglong2 bp0 = *reinterpret_cast<const ulonglong2*>(&Bs[kk][(tx << 3)]);
            ulonglong2 bp1 = *reinterpret_cast<const ulonglong2*>(&Bs[kk][(tx << 3) + 4]);
            ull b0 = bp0.x, b1 = bp0.y, b2 = bp1.x, b3 = bp1.y;
            float av[8] = {a0.x, a0.y, a0.z, a0.w, a1.x, a1.y, a1.z, a1.w};
#pragma unroll
            for (int i = 0; i < 8; i++) {
                ull a2 = pack2(av[i]);
                fma2(acc[i][0], a2, b0);
                fma2(acc[i][1], a2, b1);
                fma2(acc[i][2], a2, b2);
                fma2(acc[i][3], a2, b3);
            }
        }
        __syncthreads();
    }

    const int c0 = n0 + (tx << 3);
    float bias[8];
#pragma unroll
    for (int j = 0; j < 8; j++) bias[j] = (c0 + j < 1000) ? fb[c0 + j] : 0.f;
#pragma unroll
    for (int i = 0; i < 8; i++) {
        int m = m0 + (ty << 3) + i;
        float2 p0v = unpack2(acc[i][0]);
        float2 p1v = unpack2(acc[i][1]);
        float2 p2v = unpack2(acc[i][2]);
        float2 p3v = unpack2(acc[i][3]);
        float4 r0 = make_float4(p0v.x + bias[0], p0v.y + bias[1], p1v.x + bias[2], p1v.y + bias[3]);
        float4 r1 = make_float4(p2v.x + bias[4], p2v.y + bias[5], p3v.x + bias[6], p3v.y + bias[7]);
        float* lp = g_logitsall + (size_t)m * 1000;
        if (c0 < 1000)     *reinterpret_cast<float4*>(lp + c0)     = r0;
        if (c0 + 4 < 1000) *reinterpret_cast<float4*>(lp + c0 + 4) = r1;
    }
}

// ---------------- Batched output softmax ----------------
__global__ void __launch_bounds__(256) outsm_all_kernel(float* __restrict__ out) {
    const int m = blockIdx.x;
    const int u = m >> 5, b = m & 31;
    const int tid = threadIdx.x;
    __shared__ float sh[1000];
    __shared__ float red[8], red2[8];
    const int w = tid >> 5, lane = tid & 31;
    const float* lp = g_logitsall + (size_t)m * 1000;

    float mx = -1e30f;
    for (int c = tid; c < 1000; c += 256) {
        float v = lp[c];
        sh[c] = v;
        mx = fmaxf(mx, v);
    }
#pragma unroll
    for (int o = 16; o; o >>= 1) mx = fmaxf(mx, __shfl_xor_sync(0xffffffffu, mx, o));
    if (lane == 0) red[w] = mx;
    __syncthreads();
    float mm = red[0];
#pragma unroll
    for (int i = 1; i < 8; i++) mm = fmaxf(mm, red[i]);

    float ps = 0.f;
    for (int c = tid; c < 1000; c += 256) {
        float e = expf(sh[c] - mm);
        sh[c] = e;
        ps += e;
    }
#pragma unroll
    for (int o = 16; o; o >>= 1) ps += __shfl_xor_sync(0xffffffffu, ps, o);
    if (lane == 0) red2[w] = ps;
    __syncthreads();
    float sum = 0.f;
#pragma unroll
    for (int i = 0; i < 8; i++) sum += red2[i];
    const float inv = 1.f / sum;

    float* op = out + ((size_t)b * USTEPS + u) * VOCABN;
    for (int c = tid; c < 1000; c += 256) op[c] = sh[c] * inv;
}

// ---------------- launch ----------------
extern "C" void kernel_launch(void* const* d_in, const int* in_sizes, int n_in,
                              void* d_out, int out_size) {
    const float* x        = (const float*)d_in[0];
    const int*   y        = (const int*)  d_in[1];
    const float* bn_gamma = (const float*)d_in[2];
    const float* bn_beta  = (const float*)d_in[3];
    const float* conv0_w  = (const float*)d_in[4];
    const float* conv0_b  = (const float*)d_in[5];
    const float* tcr_w    = (const float*)d_in[6];
    const float* tcr_b    = (const float*)d_in[7];
    const float* gru_k    = (const float*)d_in[8];
    const float* gru_rk   = (const float*)d_in[9];
    const float* gru_b    = (const float*)d_in[10];
    const float* fc_w     = (const float*)d_in[11];
    const float* fc_b     = (const float*)d_in[12];
    float* out = (float*)d_out;

    float *h1, *h2;
    __half *a0, *a1, *wh;
    cudaGetSymbolAddress((void**)&h1, g_h1);
    cudaGetSymbolAddress((void**)&h2, g_h2);
    cudaGetSymbolAddress((void**)&a0, g_sa0);
    cudaGetSymbolAddress((void**)&a1, g_sa1);
    cudaGetSymbolAddress((void**)&wh, g_wh);

    // ---- encoder ----
    bn_stats_kernel<<<80, 256>>>(x, bn_gamma, bn_beta);
    zero_h_kernel<<<32, 512>>>();
    dim3 wgrid(80, 16, 4);          // 2560/32, 512/32, 4 layers
    wsplit_kernel<<<wgrid, dim3(32, 8)>>>(tcr_w);

    dim3 cgrid(4, 200);
    conv5x_kernel<80, 1600, 800, 2, 1, true, false, true><<<cgrid, 256>>>(
        x, conv0_w, conv0_b, h1, a0);

    const size_t WT = (size_t)512 * 2560;
    dim3 tgrid(4, 200);
    tcr_mma_kernel<true><<<tgrid, 256>>>(
        a0, wh + 0 * WT, h1, tcr_b + 0 * 512, h2, a1);
    tcr_mma_kernel<true><<<tgrid, 256>>>(
        a1, wh + 1 * WT, h2, tcr_b + 1 * 512, h1, a0);
    tcr_mma_kernel<true><<<tgrid, 256>>>(
        a0, wh + 2 * WT, h1, tcr_b + 2 * 512, h2, a1);
    tcr_mma_kernel<false><<<tgrid, 256>>>(
        a1, wh + 3 * WT, h2, tcr_b + 3 * 512, h1, nullptr);
    // enc lives in g_h1 (fp32)

    // ---- GRU recurrence: 2 kernels per step, 8-way k-split (96 blocks) ----
    dim3 pgrid(12, 8);
    for (int u = 0; u < USTEPS; u++) {
        gru_part_kernel<<<pgrid, 256>>>(gru_rk, u);
        gru_gates_kernel<<<32, 512>>>(y, gru_k, gru_b, u);
    }

    // ---- batched tail ----
    dim3 sgrid(7, 2, 32);
    scores_gemm_kernel<<<sgrid, 256>>>();
    sm800_kernel<<<USTEPS * B_, 256>>>();
    dim3 xgrid(4, 2, 32);
    ctx_gemm_kernel<<<xgrid, 256>>>();
    dim3 fgrid(8, 50);
    fc_big_kernel<<<fgrid, 256>>>(fc_w, fc_b);
    outsm_all_kernel<<<USTEPS * B_, 256>>>(out);
}

// round 14
// speedup vs baseline: 2.0032x; 1.1834x over previous
#include <cuda_runtime.h>
#include <cuda_fp16.h>
#include <cstdint>
#include <math.h>

typedef unsigned long long ull;
typedef unsigned int uint;

#define B_     32
#define T0     1600
#define C0     80
#define T1     800
#define D_     512
#define VOCABN 1000
#define HIDN   512
#define USTEPS 200
#define EPSV   1e-3f
#define TPAD   832       // T1 padded to multiple of 64

// ---------------- scratch (static device globals; no allocation) ----------------
__device__ float g_bn[160];
__device__ float g_h1[B_ * T1 * D_];                // fp32 activations (enc ends here)
__device__ float g_h2[B_ * T1 * D_];
__device__ float g_hstate[2][B_ * HIDN];
__device__ float g_mhp[8][B_ * 1536];               // k-split partials of h @ grk
__device__ float g_scoresall[USTEPS * B_ * T1];     // fp32 scores
__device__ float g_logitsall[USTEPS * B_ * VOCABN];
// fp16 side
__device__ __half g_sa0[B_ * T1 * D_];              // fp16 activations ping
__device__ __half g_sa1[B_ * T1 * D_];              // fp16 activations pong (enc16 ends in g_sa0)
__device__ __half g_wh[4 * 512 * 2560];             // tcr weights [l][n][kin]
__device__ __half g_cat16[USTEPS * B_ * 1024];      // [u*32+b][1024] = concat(h, ctx) fp16
__device__ __half g_alpha16[USTEPS * B_ * TPAD];    // softmaxed scores, fp16, padded
__device__ __half g_encT16[B_ * D_ * TPAD];         // enc transposed [b][d][t], padded
__device__ __half g_fcwT16[1024 * 1024];            // fc_w transposed [c][k], c padded

// ---------------- packed f32x2 helpers (FFMA2) ----------------
__device__ __forceinline__ void fma2(ull& d, ull a, ull b) {
    asm("fma.rn.f32x2 %0, %1, %2, %0;" : "+l"(d) : "l"(a), "l"(b));
}
__device__ __forceinline__ ull pack2(float x) {
    ull r;
    asm("mov.b64 %0, {%1, %1};" : "=l"(r) : "f"(x));
    return r;
}
__device__ __forceinline__ float2 unpack2(ull v) {
    float2 f;
    asm("mov.b64 {%0, %1}, %2;" : "=f"(f.x), "=f"(f.y) : "l"(v));
    return f;
}

// ---------------- mma.sync / ldmatrix helpers (sm_80+ portable) ----------------
__device__ __forceinline__ uint32_t smem_to_u32(const void* p) {
    uint32_t a;
    asm("{ .reg .u64 t; cvta.to.shared.u64 t, %1; cvt.u32.u64 %0, t; }" : "=r"(a) : "l"(p));
    return a;
}
__device__ __forceinline__ void mma_f16(float* d, const uint32_t* a, const uint32_t* b) {
    asm volatile(
        "mma.sync.aligned.m16n8k16.row.col.f32.f16.f16.f32 "
        "{%0,%1,%2,%3}, {%4,%5,%6,%7}, {%8,%9}, {%0,%1,%2,%3};"
        : "+f"(d[0]), "+f"(d[1]), "+f"(d[2]), "+f"(d[3])
        : "r"(a[0]), "r"(a[1]), "r"(a[2]), "r"(a[3]), "r"(b[0]), "r"(b[1]));
}
__device__ __forceinline__ void ldsm4(uint32_t* r, uint32_t addr) {
    asm volatile("ldmatrix.sync.aligned.m8n8.x4.shared.b16 {%0,%1,%2,%3}, [%4];"
                 : "=r"(r[0]), "=r"(r[1]), "=r"(r[2]), "=r"(r[3]) : "r"(addr));
}

// ---------------- BatchNorm statistics ----------------
__global__ void __launch_bounds__(256) bn_stats_kernel(const float* __restrict__ x,
                                                       const float* __restrict__ gamma,
                                                       const float* __restrict__ beta) {
    const int c = blockIdx.x;
    const int tid = threadIdx.x;
    const int N = B_ * T0;
    float s = 0.f, sq = 0.f;
    for (int i = tid; i < N; i += 256) {
        float v = x[(size_t)i * C0 + c];
        s += v; sq += v * v;
    }
    __shared__ float rs[256], rq[256];
    rs[tid] = s; rq[tid] = sq;
    __syncthreads();
    for (int o = 128; o > 0; o >>= 1) {
        if (tid < o) { rs[tid] += rs[tid + o]; rq[tid] += rq[tid + o]; }
        __syncthreads();
    }
    if (tid == 0) {
        float mean = rs[0] / (float)N;
        float var  = rq[0] / (float)N - mean * mean;
        float sc   = gamma[c] * rsqrtf(var + EPSV);
        g_bn[c]      = sc;
        g_bn[80 + c] = beta[c] - mean * sc;
    }
}

__global__ void __launch_bounds__(512) zero_h_kernel() {
    int i = blockIdx.x * blockDim.x + threadIdx.x;
    if (i < B_ * HIDN) g_hstate[0][i] = 0.f;
}

// ---------------- weight transpose to fp16: tcr_w [l][kin][512] -> wh[l][n][kin] ----------------
__global__ void __launch_bounds__(256) wsplit_kernel(const float* __restrict__ tcr_w) {
    __shared__ float tile[32][33];
    const int l  = blockIdx.z;
    const int k0 = blockIdx.x * 32;
    const int n0 = blockIdx.y * 32;
    const int tx = threadIdx.x, ty = threadIdx.y;   // 32 x 8
#pragma unroll
    for (int j = 0; j < 32; j += 8)
        tile[ty + j][tx] = tcr_w[((size_t)l * 2560 + k0 + ty + j) * 512 + n0 + tx];
    __syncthreads();
#pragma unroll
    for (int j = 0; j < 32; j += 8) {
        float v = tile[tx][ty + j];
        size_t di = ((size_t)l * 512 + n0 + ty + j) * 2560 + k0 + tx;
        g_wh[di] = __float2half_rn(v);
    }
}

// ---------------- enc16 [b][t][d] -> encT16 [b][d][TPAD] (t-padded with zeros) ----------------
__global__ void __launch_bounds__(256) enct_kernel() {
    __shared__ __half tile[32][33];
    const int b  = blockIdx.z;
    const int t0 = blockIdx.x * 32;
    const int d0 = blockIdx.y * 32;
    const int tx = threadIdx.x, ty = threadIdx.y;   // 32 x 8
#pragma unroll
    for (int j = 0; j < 32; j += 8) {
        int t = t0 + ty + j;
        __half v = __float2half(0.f);
        if (t < T1) v = g_sa0[((size_t)b * T1 + t) * 512 + d0 + tx];
        tile[ty + j][tx] = v;
    }
    __syncthreads();
#pragma unroll
    for (int j = 0; j < 32; j += 8)
        g_encT16[((size_t)b * D_ + d0 + ty + j) * TPAD + t0 + tx] = tile[tx][ty + j];
}

// ---------------- fc_w [1024][1000] -> fcwT16 [1024(c, padded)][1024(k)] ----------------
__global__ void __launch_bounds__(256) fcwt_kernel(const float* __restrict__ fw) {
    __shared__ __half tile[32][33];
    const int k0 = blockIdx.x * 32;
    const int c0 = blockIdx.y * 32;
    const int tx = threadIdx.x, ty = threadIdx.y;   // 32 x 8
#pragma unroll
    for (int j = 0; j < 32; j += 8) {
        int c = c0 + tx;
        float v = (c < VOCABN) ? fw[(size_t)(k0 + ty + j) * VOCABN + c] : 0.f;
        tile[ty + j][tx] = __float2half_rn(v);
    }
    __syncthreads();
#pragma unroll
    for (int j = 0; j < 32; j += 8)
        g_fcwT16[(size_t)(c0 + ty + j) * 1024 + k0 + tx] = tile[tx][ty + j];
}

// ---------------- conv0: implicit-im2col SGEMM 128x128x32 FFMA2 (+ fp16 epilogue) ----------------
template<int CIN, int TIN, int TOUT, int STRIDE, int PADL, bool FUSE_BN, bool RESID, bool SPLIT>
__global__ void __launch_bounds__(256, 2) conv5x_kernel(const float* __restrict__ in,
                                                        const float* __restrict__ w,
                                                        const float* __restrict__ bias,
                                                        float* __restrict__ out,
                                                        __half* __restrict__ oh) {
    __shared__ __align__(16) float As[32][128];
    __shared__ __align__(16) float Bs[32][128];
    __shared__ __align__(16) float s_bn[160];

    const int tid = threadIdx.x;
    if (FUSE_BN && tid < 160) s_bn[tid] = g_bn[tid];

    const int n0 = blockIdx.x * 128;
    const int m0 = blockIdx.y * 128;
    const int tx = tid & 15;
    const int ty = tid >> 4;

    ull acc[4][8];
#pragma unroll
    for (int i = 0; i < 4; i++)
#pragma unroll
        for (int j = 0; j < 8; j++) acc[i][j] = 0ull;

    __syncthreads();

    const int KIN = 5 * CIN;
    for (int p0 = 0; p0 < KIN; p0 += 32) {
#pragma unroll
        for (int it = 0; it < 4; it++) {
            int s  = tid + it * 256;
            int kq = s & 7;
            int ml = s >> 3;
            int p  = p0 + (kq << 2);
            int k  = p / CIN;
            int ci = p - k * CIN;
            int m  = m0 + ml;
            int bb = m / TOUT;
            int t  = m - bb * TOUT;
            int tin = t * STRIDE - PADL + k;
            float4 av = make_float4(0.f, 0.f, 0.f, 0.f);
            if (tin >= 0 && tin < TIN && p < KIN) {
                av = *reinterpret_cast<const float4*>(in + ((size_t)bb * TIN + tin) * CIN + ci);
                if (FUSE_BN) {
                    float4 sc = *reinterpret_cast<const float4*>(&s_bn[ci]);
                    float4 sh = *reinterpret_cast<const float4*>(&s_bn[80 + ci]);
                    av.x = av.x * sc.x + sh.x;
                    av.y = av.y * sc.y + sh.y;
                    av.z = av.z * sc.z + sh.z;
                    av.w = av.w * sc.w + sh.w;
                }
            }
            int pc = ml ^ (kq << 2);
            As[(kq << 2) + 0][pc] = av.x;
            As[(kq << 2) + 1][pc] = av.y;
            As[(kq << 2) + 2][pc] = av.z;
            As[(kq << 2) + 3][pc] = av.w;
        }
#pragma unroll
        for (int it = 0; it < 4; it++) {
            int s  = tid + it * 256;
            int cq = s & 31;
            int kr = s >> 5;
            float4 v = make_float4(0.f, 0.f, 0.f, 0.f);
            if (p0 + kr < KIN)
                v = *reinterpret_cast<const float4*>(w + (size_t)(p0 + kr) * 512 + n0 + (cq << 2));
            *reinterpret_cast<float4*>(&Bs[kr][cq << 2]) = v;
        }
        __syncthreads();

#pragma unroll
        for (int kk = 0; kk < 32; kk++) {
            const int sw = (kk >> 2) << 2;
            ulonglong2 ap0 = *reinterpret_cast<const ulonglong2*>(&As[kk][(ty << 3) ^ sw]);
            ulonglong2 ap1 = *reinterpret_cast<const ulonglong2*>(&As[kk][((ty << 3) + 4) ^ sw]);
            ull ap[4] = {ap0.x, ap0.y, ap1.x, ap1.y};
            float4 bA = *reinterpret_cast<const float4*>(&Bs[kk][tx << 2]);
            float4 bB = *reinterpret_cast<const float4*>(&Bs[kk][64 + (tx << 2)]);
            ull bd[8];
            bd[0] = pack2(bA.x); bd[1] = pack2(bA.y); bd[2] = pack2(bA.z); bd[3] = pack2(bA.w);
            bd[4] = pack2(bB.x); bd[5] = pack2(bB.y); bd[6] = pack2(bB.z); bd[7] = pack2(bB.w);
#pragma unroll
            for (int mp = 0; mp < 4; mp++)
#pragma unroll
                for (int n = 0; n < 8; n++) fma2(acc[mp][n], ap[mp], bd[n]);
        }
        __syncthreads();
    }

    const int c0 = n0 + (tx << 2);
    const int c1 = n0 + 64 + (tx << 2);
    const float4 bias0 = *reinterpret_cast<const float4*>(bias + c0);
    const float4 bias1 = *reinterpret_cast<const float4*>(bias + c1);
    float2 u0[4][4], u1[4][4];
#pragma unroll
    for (int mp = 0; mp < 4; mp++)
#pragma unroll
        for (int n = 0; n < 4; n++) {
            u0[mp][n] = unpack2(acc[mp][n]);
            u1[mp][n] = unpack2(acc[mp][4 + n]);
        }
#pragma unroll
    for (int i = 0; i < 8; i++) {
        const int mp = i >> 1;
        const bool hi = i & 1;
        int m = m0 + (ty << 3) + i;
        float4 r0, r1;
        r0.x = fmaxf((hi ? u0[mp][0].y : u0[mp][0].x) + bias0.x, 0.f);
        r0.y = fmaxf((hi ? u0[mp][1].y : u0[mp][1].x) + bias0.y, 0.f);
        r0.z = fmaxf((hi ? u0[mp][2].y : u0[mp][2].x) + bias0.z, 0.f);
        r0.w = fmaxf((hi ? u0[mp][3].y : u0[mp][3].x) + bias0.w, 0.f);
        r1.x = fmaxf((hi ? u1[mp][0].y : u1[mp][0].x) + bias1.x, 0.f);
        r1.y = fmaxf((hi ? u1[mp][1].y : u1[mp][1].x) + bias1.y, 0.f);
        r1.z = fmaxf((hi ? u1[mp][2].y : u1[mp][2].x) + bias1.z, 0.f);
        r1.w = fmaxf((hi ? u1[mp][3].y : u1[mp][3].x) + bias1.w, 0.f);
        if (RESID) {
            float4 e0 = *reinterpret_cast<const float4*>(in + (size_t)m * CIN + c0);
            float4 e1 = *reinterpret_cast<const float4*>(in + (size_t)m * CIN + c1);
            r0.x += e0.x; r0.y += e0.y; r0.z += e0.z; r0.w += e0.w;
            r1.x += e1.x; r1.y += e1.y; r1.z += e1.z; r1.w += e1.w;
        }
        *reinterpret_cast<float4*>(out + (size_t)m * 512 + c0) = r0;
        *reinterpret_cast<float4*>(out + (size_t)m * 512 + c1) = r1;
        if (SPLIT) {
            __half* hp = oh + (size_t)m * 512;
            *reinterpret_cast<__half2*>(hp + c0)     = __floats2half2_rn(r0.x, r0.y);
            *reinterpret_cast<__half2*>(hp + c0 + 2) = __floats2half2_rn(r0.z, r0.w);
            *reinterpret_cast<__half2*>(hp + c1)     = __floats2half2_rn(r1.x, r1.y);
            *reinterpret_cast<__half2*>(hp + c1 + 2) = __floats2half2_rn(r1.z, r1.w);
        }
    }
}

// ---------------- tcr conv layer on mma.sync (pure fp16) ----------------
#define ASTR 72
template<bool SPLIT>
__global__ void __launch_bounds__(256, 2) tcr_mma_kernel(const __half* __restrict__ a16,
                                                         const __half* __restrict__ wh,
                                                         const float* __restrict__ resid_in,
                                                         const float* __restrict__ bias,
                                                         float* __restrict__ out,
                                                         __half* __restrict__ oh) {
    __shared__ __align__(16) __half sA[128 * ASTR];
    __shared__ __align__(16) __half sB[128 * ASTR];

    const int tid = threadIdx.x;
    const int wid = tid >> 5, lane = tid & 31;
    const int n0 = blockIdx.x * 128;
    const int m0 = blockIdx.y * 128;
    const int warp_m = (wid >> 1) << 5;
    const int warp_n = (wid & 1) << 6;

    float acc[2][8][4];
#pragma unroll
    for (int i = 0; i < 2; i++)
#pragma unroll
        for (int j = 0; j < 8; j++)
#pragma unroll
            for (int r = 0; r < 4; r++) acc[i][j][r] = 0.f;

    const int lq = tid & 7;
    const int lrow = tid >> 3;

    const uint32_t aAddr = smem_to_u32(sA) + (warp_m + (lane & 15)) * 144 + (lane >> 4) * 16;
    const int browoff = warp_n + (lane & 7) + ((lane >> 4) & 1) * 8;
    const uint32_t bAddr = smem_to_u32(sB) + browoff * 144 + ((lane >> 3) & 1) * 16;

    for (int c = 0; c < 40; c++) {
        const int tap = c >> 3;
        const int ci0 = (c & 7) << 6;
#pragma unroll
        for (int it = 0; it < 4; it++) {
            int ml = lrow + it * 32;
            int m  = m0 + ml;
            int bb = m / T1;
            int t  = m - bb * T1;
            int tin = t + tap - 2;
            uint4 va = make_uint4(0, 0, 0, 0);
            if (tin >= 0 && tin < T1)
                va = *reinterpret_cast<const uint4*>(a16 + ((size_t)bb * T1 + tin) * 512 + ci0 + lq * 8);
            *reinterpret_cast<uint4*>(&sA[ml * ASTR + lq * 8]) = va;
        }
#pragma unroll
        for (int it = 0; it < 4; it++) {
            int nl = lrow + it * 32;
            size_t src = (size_t)(n0 + nl) * 2560 + c * 64 + lq * 8;
            *reinterpret_cast<uint4*>(&sB[nl * ASTR + lq * 8]) = *reinterpret_cast<const uint4*>(wh + src);
        }
        __syncthreads();

#pragma unroll
        for (int s = 0; s < 4; s++) {
            uint32_t a[2][4];
            ldsm4(a[0], aAddr + s * 32);
            ldsm4(a[1], aAddr + s * 32 + 16 * 144);
#pragma unroll
            for (int jj = 0; jj < 4; jj++) {
                uint32_t b[4];
                ldsm4(b, bAddr + s * 32 + jj * 16 * 144);
#pragma unroll
                for (int i = 0; i < 2; i++) {
                    mma_f16(acc[i][2 * jj],     a[i], b);
                    mma_f16(acc[i][2 * jj + 1], a[i], b + 2);
                }
            }
        }
        __syncthreads();
    }

    const int r0 = lane >> 2;
    const int cc = (lane & 3) * 2;
#pragma unroll
    for (int i = 0; i < 2; i++) {
        int mrow = m0 + warp_m + i * 16 + r0;
#pragma unroll
        for (int j = 0; j < 8; j++) {
            int col = n0 + warp_n + j * 8 + cc;
            float2 b2 = *reinterpret_cast<const float2*>(bias + col);
#pragma unroll
            for (int half = 0; half < 2; half++) {
                int m = mrow + half * 8;
                float va = acc[i][j][half * 2 + 0];
                float vb = acc[i][j][half * 2 + 1];
                float2 e = *reinterpret_cast<const float2*>(resid_in + (size_t)m * 512 + col);
                float2 v;
                v.x = fmaxf(va + b2.x, 0.f) + e.x;
                v.y = fmaxf(vb + b2.y, 0.f) + e.y;
                *reinterpret_cast<float2*>(out + (size_t)m * 512 + col) = v;
                if (SPLIT)
                    *reinterpret_cast<__half2*>(oh + (size_t)m * 512 + col) = __floats2half2_rn(v.x, v.y);
            }
        }
    }
}

// ---------------- scores16: per b, S[u,t] = cat16[u,:512] . enc16[t,:] (fp16 mma) ----------------
__global__ void __launch_bounds__(256, 2) scores16_kernel() {
    __shared__ __align__(16) __half sA[128 * ASTR];
    __shared__ __align__(16) __half sB[128 * ASTR];
    const int tid = threadIdx.x;
    const int wid = tid >> 5, lane = tid & 31;
    const int n0 = blockIdx.x * 128;   // t
    const int m0 = blockIdx.y * 128;   // u
    const int b  = blockIdx.z;
    const int warp_m = (wid >> 1) << 5;
    const int warp_n = (wid & 1) << 6;

    float acc[2][8][4];
#pragma unroll
    for (int i = 0; i < 2; i++)
#pragma unroll
        for (int j = 0; j < 8; j++)
#pragma unroll
            for (int r = 0; r < 4; r++) acc[i][j][r] = 0.f;

    const int lq = tid & 7;
    const int lrow = tid >> 3;
    const uint32_t aAddr = smem_to_u32(sA) + (warp_m + (lane & 15)) * 144 + (lane >> 4) * 16;
    const int browoff = warp_n + (lane & 7) + ((lane >> 4) & 1) * 8;
    const uint32_t bAddr = smem_to_u32(sB) + browoff * 144 + ((lane >> 3) & 1) * 16;

    for (int c = 0; c < 8; c++) {      // K = 512
#pragma unroll
        for (int it = 0; it < 4; it++) {
            int ml = lrow + it * 32;
            int u  = m0 + ml;
            uint4 va = make_uint4(0, 0, 0, 0);
            if (u < USTEPS)
                va = *reinterpret_cast<const uint4*>(
                    g_cat16 + ((size_t)u * 32 + b) * 1024 + c * 64 + lq * 8);
            *reinterpret_cast<uint4*>(&sA[ml * ASTR + lq * 8]) = va;
        }
#pragma unroll
        for (int it = 0; it < 4; it++) {
            int nl = lrow + it * 32;
            int t  = n0 + nl;
            uint4 vb = make_uint4(0, 0, 0, 0);
            if (t < T1)
                vb = *reinterpret_cast<const uint4*>(
                    g_sa0 + ((size_t)b * T1 + t) * 512 + c * 64 + lq * 8);
            *reinterpret_cast<uint4*>(&sB[nl * ASTR + lq * 8]) = vb;
        }
        __syncthreads();
#pragma unroll
        for (int s = 0; s < 4; s++) {
            uint32_t a[2][4];
            ldsm4(a[0], aAddr + s * 32);
            ldsm4(a[1], aAddr + s * 32 + 16 * 144);
#pragma unroll
            for (int jj = 0; jj < 4; jj++) {
                uint32_t bb[4];
                ldsm4(bb, bAddr + s * 32 + jj * 16 * 144);
#pragma unroll
                for (int i = 0; i < 2; i++) {
                    mma_f16(acc[i][2 * jj],     a[i], bb);
                    mma_f16(acc[i][2 * jj + 1], a[i], bb + 2);
                }
            }
        }
        __syncthreads();
    }

    const int r0 = lane >> 2;
    const int cc = (lane & 3) * 2;
#pragma unroll
    for (int i = 0; i < 2; i++) {
        int urow = m0 + warp_m + i * 16 + r0;
#pragma unroll
        for (int j = 0; j < 8; j++) {
            int col = n0 + warp_n + j * 8 + cc;
#pragma unroll
            for (int half = 0; half < 2; half++) {
                int u = urow + half * 8;
                if (u < USTEPS && col < T1) {
                    float2 v = make_float2(acc[i][j][half * 2], acc[i][j][half * 2 + 1]);
                    *reinterpret_cast<float2*>(
                        g_scoresall + ((size_t)u * 32 + b) * T1 + col) = v;
                }
            }
        }
    }
}

// ---------------- ctx16: per b, C[u,d] = alpha16[u,:] . encT16[d,:] (fp16 mma) ----------------
__global__ void __launch_bounds__(256, 2) ctx16_kernel() {
    __shared__ __align__(16) __half sA[128 * ASTR];
    __shared__ __align__(16) __half sB[128 * ASTR];
    const int tid = threadIdx.x;
    const int wid = tid >> 5, lane = tid & 31;
    const int n0 = blockIdx.x * 128;   // d
    const int m0 = blockIdx.y * 128;   // u
    const int b  = blockIdx.z;
    const int warp_m = (wid >> 1) << 5;
    const int warp_n = (wid & 1) << 6;

    float acc[2][8][4];
#pragma unroll
    for (int i = 0; i < 2; i++)
#pragma unroll
        for (int j = 0; j < 8; j++)
#pragma unroll
            for (int r = 0; r < 4; r++) acc[i][j][r] = 0.f;

    const int lq = tid & 7;
    const int lrow = tid >> 3;
    const uint32_t aAddr = smem_to_u32(sA) + (warp_m + (lane & 15)) * 144 + (lane >> 4) * 16;
    const int browoff = warp_n + (lane & 7) + ((lane >> 4) & 1) * 8;
    const uint32_t bAddr = smem_to_u32(sB) + browoff * 144 + ((lane >> 3) & 1) * 16;

    for (int c = 0; c < 13; c++) {     // K = TPAD = 832
#pragma unroll
        for (int it = 0; it < 4; it++) {
            int ml = lrow + it * 32;
            int u  = m0 + ml;
            uint4 va = make_uint4(0, 0, 0, 0);
            if (u < USTEPS)
                va = *reinterpret_cast<const uint4*>(
                    g_alpha16 + ((size_t)u * 32 + b) * TPAD + c * 64 + lq * 8);
            *reinterpret_cast<uint4*>(&sA[ml * ASTR + lq * 8]) = va;
        }
#pragma unroll
        for (int it = 0; it < 4; it++) {
            int nl = lrow + it * 32;
            *reinterpret_cast<uint4*>(&sB[nl * ASTR + lq * 8]) =
                *reinterpret_cast<const uint4*>(
                    g_encT16 + ((size_t)b * D_ + n0 + nl) * TPAD + c * 64 + lq * 8);
        }
        __syncthreads();
#pragma unroll
        for (int s = 0; s < 4; s++) {
            uint32_t a[2][4];
            ldsm4(a[0], aAddr + s * 32);
            ldsm4(a[1], aAddr + s * 32 + 16 * 144);
#pragma unroll
            for (int jj = 0; jj < 4; jj++) {
                uint32_t bb[4];
                ldsm4(bb, bAddr + s * 32 + jj * 16 * 144);
#pragma unroll
                for (int i = 0; i < 2; i++) {
                    mma_f16(acc[i][2 * jj],     a[i], bb);
                    mma_f16(acc[i][2 * jj + 1], a[i], bb + 2);
                }
            }
        }
        __syncthreads();
    }

    const int r0 = lane >> 2;
    const int cc = (lane & 3) * 2;
#pragma unroll
    for (int i = 0; i < 2; i++) {
        int urow = m0 + warp_m + i * 16 + r0;
#pragma unroll
        for (int j = 0; j < 8; j++) {
            int col = n0 + warp_n + j * 8 + cc;
#pragma unroll
            for (int half = 0; half < 2; half++) {
                int u = urow + half * 8;
                if (u < USTEPS) {
                    *reinterpret_cast<__half2*>(
                        g_cat16 + ((size_t)u * 32 + b) * 1024 + 512 + col) =
                        __floats2half2_rn(acc[i][j][half * 2], acc[i][j][half * 2 + 1]);
                }
            }
        }
    }
}

// ---------------- fc16: logits[m,c] = cat16[m,:] . fcwT16[c,:] + fb (fp16 mma) ----------------
__global__ void __launch_bounds__(256, 2) fc16_kernel(const float* __restrict__ fb) {
    __shared__ __align__(16) __half sA[128 * ASTR];
    __shared__ __align__(16) __half sB[128 * ASTR];
    const int tid = threadIdx.x;
    const int wid = tid >> 5, lane = tid & 31;
    const int n0 = blockIdx.x * 128;   // c
    const int m0 = blockIdx.y * 128;   // m
    const int warp_m = (wid >> 1) << 5;
    const int warp_n = (wid & 1) << 6;

    float acc[2][8][4];
#pragma unroll
    for (int i = 0; i < 2; i++)
#pragma unroll
        for (int j = 0; j < 8; j++)
#pragma unroll
            for (int r = 0; r < 4; r++) acc[i][j][r] = 0.f;

    const int lq = tid & 7;
    const int lrow = tid >> 3;
    const uint32_t aAddr = smem_to_u32(sA) + (warp_m + (lane & 15)) * 144 + (lane >> 4) * 16;
    const int browoff = warp_n + (lane & 7) + ((lane >> 4) & 1) * 8;
    const uint32_t bAddr = smem_to_u32(sB) + browoff * 144 + ((lane >> 3) & 1) * 16;

    for (int c = 0; c < 16; c++) {     // K = 1024
#pragma unroll
        for (int it = 0; it < 4; it++) {
            int ml = lrow + it * 32;
            *reinterpret_cast<uint4*>(&sA[ml * ASTR + lq * 8]) =
                *reinterpret_cast<const uint4*>(
                    g_cat16 + (size_t)(m0 + ml) * 1024 + c * 64 + lq * 8);
        }
#pragma unroll
        for (int it = 0; it < 4; it++) {
            int nl = lrow + it * 32;
            *reinterpret_cast<uint4*>(&sB[nl * ASTR + lq * 8]) =
                *reinterpret_cast<const uint4*>(
                    g_fcwT16 + (size_t)(n0 + nl) * 1024 + c * 64 + lq * 8);
        }
        __syncthreads();
#pragma unroll
        for (int s = 0; s < 4; s++) {
            uint32_t a[2][4];
            ldsm4(a[0], aAddr + s * 32);
            ldsm4(a[1], aAddr + s * 32 + 16 * 144);
#pragma unroll
            for (int jj = 0; jj < 4; jj++) {
                uint32_t bb[4];
                ldsm4(bb, bAddr + s * 32 + jj * 16 * 144);
#pragma unroll
                for (int i = 0; i < 2; i++) {
                    mma_f16(acc[i][2 * jj],     a[i], bb);
                    mma_f16(acc[i][2 * jj + 1], a[i], bb + 2);
                }
            }
        }
        __syncthreads();
    }

    const int r0 = lane >> 2;
    const int cc = (lane & 3) * 2;
#pragma unroll
    for (int i = 0; i < 2; i++) {
        int mrow = m0 + warp_m + i * 16 + r0;
#pragma unroll
        for (int j = 0; j < 8; j++) {
            int col = n0 + warp_n + j * 8 + cc;
            if (col < VOCABN) {
                float2 b2 = *reinterpret_cast<const float2*>(fb + col);
#pragma unroll
                for (int half = 0; half < 2; half++) {
                    int m = mrow + half * 8;
                    float2 v = make_float2(acc[i][j][half * 2] + b2.x,
                                           acc[i][j][half * 2 + 1] + b2.y);
                    *reinterpret_cast<float2*>(g_logitsall + (size_t)m * 1000 + col) = v;
                }
            }
        }
    }
}

// ---------------- Recurrence kernel A: mh partials (k-split x8 GEMM) ----------------
__global__ void __launch_bounds__(256) gru_part_kernel(const float* __restrict__ grk, int u) {
    __shared__ float Hs[16][33];
    __shared__ __align__(16) float Ws[16][128];
    const float* h = g_hstate[u & 1];
    const int tid = threadIdx.x;
    const int n0 = blockIdx.x * 128;
    const int kb = blockIdx.y * 64;
    const int nx = tid & 31;
    const int my = tid >> 5;

    ull acc[4][2];
#pragma unroll
    for (int i = 0; i < 4; i++) { acc[i][0] = 0ull; acc[i][1] = 0ull; }

    for (int k0 = 0; k0 < 64; k0 += 16) {
#pragma unroll
        for (int it = 0; it < 2; it++) {
            int e = tid + it * 256;
            int kk = e & 15, m = e >> 4;
            Hs[kk][m] = h[m * 512 + kb + k0 + kk];
        }
#pragma unroll
        for (int it = 0; it < 2; it++) {
            int s = tid + it * 256;
            int cq = s & 31, kr = s >> 5;
            *reinterpret_cast<float4*>(&Ws[kr][cq << 2]) =
                *reinterpret_cast<const float4*>(grk + (size_t)(kb + k0 + kr) * 1536 + n0 + (cq << 2));
        }
        __syncthreads();
#pragma unroll
        for (int kk = 0; kk < 16; kk++) {
            ulonglong2 bp = *reinterpret_cast<const ulonglong2*>(&Ws[kk][nx << 2]);
#pragma unroll
            for (int i = 0; i < 4; i++) {
                ull ad = pack2(Hs[kk][(my << 2) + i]);
                fma2(acc[i][0], ad, bp.x);
                fma2(acc[i][1], ad, bp.y);
            }
        }
        __syncthreads();
    }
    float* outp = g_mhp[blockIdx.y];
#pragma unroll
    for (int i = 0; i < 4; i++) {
        float2 v0 = unpack2(acc[i][0]);
        float2 v1 = unpack2(acc[i][1]);
        *reinterpret_cast<float4*>(&outp[((my << 2) + i) * 1536 + n0 + (nx << 2)]) =
            make_float4(v0.x, v0.y, v1.x, v1.y);
    }
}

// ---------------- Recurrence kernel B: sum 8 partials + GRU gates ----------------
__global__ void __launch_bounds__(512) gru_gates_kernel(const int* __restrict__ y,
                                                        const float* __restrict__ gk,
                                                        const float* __restrict__ gb,
                                                        int u) {
    const int b = blockIdx.x;
    const int j = threadIdx.x;
    float hz = 0.f, hr = 0.f, hh = 0.f;
#pragma unroll
    for (int c = 0; c < 8; c++) {
        const float* p = g_mhp[c] + b * 1536;
        hz += p[j];
        hr += p[512 + j];
        hh += p[1024 + j];
    }
    const float* bi = gb;
    const float* br = gb + 1536;
    const int tok   = y[b * 201 + u];
    const float* gx = gk + (size_t)tok * 1536;
    float xz = gx[j]        + bi[j];
    float xr = gx[512 + j]  + bi[512 + j];
    float xh = gx[1024 + j] + bi[1024 + j];
    hz += br[j];
    hr += br[512 + j];
    hh += br[1024 + j];
    float z = 1.f / (1.f + expf(-(xz + hz)));
    float r = 1.f / (1.f + expf(-(xr + hr)));
    float cand = tanhf(xh + r * hh);
    float hold = g_hstate[u & 1][b * 512 + j];
    float hn = z * hold + (1.f - z) * cand;
    g_hstate[(u + 1) & 1][b * 512 + j] = hn;
    g_cat16[((size_t)u * 32 + b) * 1024 + j] = __float2half_rn(hn);
}

// ---------------- Batched softmax over 800 -> alpha16 (padded) ----------------
__global__ void __launch_bounds__(256) sm800_kernel() {
    const int row = blockIdx.x;
    const int tid = threadIdx.x;
    const float* sp = g_scoresall + (size_t)row * T1;
    __half* ap = g_alpha16 + (size_t)row * TPAD;
    __shared__ float sa[800];
    __shared__ float red[8], red2[8];
    const int w = tid >> 5, lane = tid & 31;

    float m = -1e30f;
    for (int t = tid; t < 800; t += 256) {
        float v = sp[t];
        sa[t] = v;
        m = fmaxf(m, v);
    }
#pragma unroll
    for (int o = 16; o; o >>= 1) m = fmaxf(m, __shfl_xor_sync(0xffffffffu, m, o));
    if (lane == 0) red[w] = m;
    __syncthreads();
    float mm = red[0];
#pragma unroll
    for (int i = 1; i < 8; i++) mm = fmaxf(mm, red[i]);

    float ps = 0.f;
    for (int t = tid; t < 800; t += 256) {
        float e = expf(sa[t] - mm);
        sa[t] = e;
        ps += e;
    }
#pragma unroll
    for (int o = 16; o; o >>= 1) ps += __shfl_xor_sync(0xffffffffu, ps, o);
    if (lane == 0) red2[w] = ps;
    __syncthreads();
    float sum = 0.f;
#pragma unroll
    for (int i = 0; i < 8; i++) sum += red2[i];
    const float inv = 1.f / sum;

    for (int t = tid; t < 800; t += 256) ap[t] = __float2half_rn(sa[t] * inv);
    if (tid < 32) ap[800 + tid] = __float2half(0.f);
}

// ---------------- Batched output softmax ----------------
__global__ void __launch_bounds__(256) outsm_all_kernel(float* __restrict__ out) {
    const int m = blockIdx.x;
    const int u = m >> 5, b = m & 31;
    const int tid = threadIdx.x;
    __shared__ float sh[1000];
    __shared__ float red[8], red2[8];
    const int w = tid >> 5, lane = tid & 31;
    const float* lp = g_logitsall + (size_t)m * 1000;

    float mx = -1e30f;
    for (int c = tid; c < 1000; c += 256) {
        float v = lp[c];
        sh[c] = v;
        mx = fmaxf(mx, v);
    }
#pragma unroll
    for (int o = 16; o; o >>= 1) mx = fmaxf(mx, __shfl_xor_sync(0xffffffffu, mx, o));
    if (lane == 0) red[w] = mx;
    __syncthreads();
    float mm = red[0];
#pragma unroll
    for (int i = 1; i < 8; i++) mm = fmaxf(mm, red[i]);

    float ps = 0.f;
    for (int c = tid; c < 1000; c += 256) {
        float e = expf(sh[c] - mm);
        sh[c] = e;
        ps += e;
    }
#pragma unroll
    for (int o = 16; o; o >>= 1) ps += __shfl_xor_sync(0xffffffffu, ps, o);
    if (lane == 0) red2[w] = ps;
    __syncthreads();
    float sum = 0.f;
#pragma unroll
    for (int i = 0; i < 8; i++) sum += red2[i];
    const float inv = 1.f / sum;

    float* op = out + ((size_t)b * USTEPS + u) * VOCABN;
    for (int c = tid; c < 1000; c += 256) op[c] = sh[c] * inv;
}

// ---------------- launch ----------------
extern "C" void kernel_launch(void* const* d_in, const int* in_sizes, int n_in,
                              void* d_out, int out_size) {
    const float* x        = (const float*)d_in[0];
    const int*   y        = (const int*)  d_in[1];
    const float* bn_gamma = (const float*)d_in[2];
    const float* bn_beta  = (const float*)d_in[3];
    const float* conv0_w  = (const float*)d_in[4];
    const float* conv0_b  = (const float*)d_in[5];
    const float* tcr_w    = (const float*)d_in[6];
    const float* tcr_b    = (const float*)d_in[7];
    const float* gru_k    = (const float*)d_in[8];
    const float* gru_rk   = (const float*)d_in[9];
    const float* gru_b    = (const float*)d_in[10];
    const float* fc_w     = (const float*)d_in[11];
    const float* fc_b     = (const float*)d_in[12];
    float* out = (float*)d_out;

    float *h1, *h2;
    __half *a0, *a1, *wh;
    cudaGetSymbolAddress((void**)&h1, g_h1);
    cudaGetSymbolAddress((void**)&h2, g_h2);
    cudaGetSymbolAddress((void**)&a0, g_sa0);
    cudaGetSymbolAddress((void**)&a1, g_sa1);
    cudaGetSymbolAddress((void**)&wh, g_wh);

    // ---- encoder ----
    bn_stats_kernel<<<80, 256>>>(x, bn_gamma, bn_beta);
    zero_h_kernel<<<32, 512>>>();
    dim3 wgrid(80, 16, 4);
    wsplit_kernel<<<wgrid, dim3(32, 8)>>>(tcr_w);
    fcwt_kernel<<<dim3(32, 32), dim3(32, 8)>>>(fc_w);

    dim3 cgrid(4, 200);
    conv5x_kernel<80, 1600, 800, 2, 1, true, false, true><<<cgrid, 256>>>(
        x, conv0_w, conv0_b, h1, a0);

    const size_t WT = (size_t)512 * 2560;
    dim3 tgrid(4, 200);
    tcr_mma_kernel<true><<<tgrid, 256>>>(a0, wh + 0 * WT, h1, tcr_b + 0 * 512, h2, a1);
    tcr_mma_kernel<true><<<tgrid, 256>>>(a1, wh + 1 * WT, h2, tcr_b + 1 * 512, h1, a0);
    tcr_mma_kernel<true><<<tgrid, 256>>>(a0, wh + 2 * WT, h1, tcr_b + 2 * 512, h2, a1);
    tcr_mma_kernel<true><<<tgrid, 256>>>(a1, wh + 3 * WT, h2, tcr_b + 3 * 512, h1, a0);
    // enc16 lives in g_sa0 (and fp32 in g_h1 for nothing downstream)

    // transpose enc16 -> encT16 (padded)
    enct_kernel<<<dim3(26, 16, 32), dim3(32, 8)>>>();

    // ---- GRU recurrence: 2 kernels per step, 8-way k-split (96 blocks) ----
    dim3 pgrid(12, 8);
    for (int u = 0; u < USTEPS; u++) {
        gru_part_kernel<<<pgrid, 256>>>(gru_rk, u);
        gru_gates_kernel<<<32, 512>>>(y, gru_k, gru_b, u);
    }

    // ---- batched tail (all fp16 mma) ----
    scores16_kernel<<<dim3(7, 2, 32), 256>>>();
    sm800_kernel<<<USTEPS * B_, 256>>>();
    ctx16_kernel<<<dim3(4, 2, 32), 256>>>();
    fc16_kernel<<<dim3(8, 50), 256>>>(fc_b);
    outsm_all_kernel<<<USTEPS * B_, 256>>>(out);
}

// round 15
// speedup vs baseline: 2.1059x; 1.0513x over previous
#include <cuda_runtime.h>
#include <cuda_fp16.h>
#include <cstdint>
#include <math.h>

typedef unsigned long long ull;
typedef unsigned int uint;

#define B_     32
#define T0     1600
#define C0     80
#define T1     800
#define D_     512
#define VOCABN 1000
#define HIDN   512
#define USTEPS 200
#define EPSV   1e-3f
#define TPAD   832

// ---------------- scratch (static device globals; no allocation) ----------------
__device__ float g_bn[160];
__device__ float g_h1[B_ * T1 * D_];
__device__ float g_h2[B_ * T1 * D_];
__device__ float g_hstate[2][B_ * HIDN];
__device__ float g_mhp[8][B_ * 1536];
__device__ float g_scoresall[USTEPS * B_ * T1];
__device__ float g_logitsall[USTEPS * B_ * VOCABN];
// fp16 side
__device__ __half g_sa0[B_ * T1 * D_];
__device__ __half g_sa1[B_ * T1 * D_];
__device__ __half g_wh[4 * 512 * 2560];             // tcr weights [l][n][kin]
__device__ __half g_x16[B_ * T0 * 128];             // bn-applied input, channel-padded
__device__ __half g_wc16[512 * 640];                // conv0 weights [n][5*128]
__device__ __half g_cat16[USTEPS * B_ * 1024];
__device__ __half g_alpha16[USTEPS * B_ * TPAD];
__device__ __half g_encT16[B_ * D_ * TPAD];
__device__ __half g_fcwT16[1024 * 1024];

// ---------------- packed f32x2 helpers (for gru_part) ----------------
__device__ __forceinline__ void fma2(ull& d, ull a, ull b) {
    asm("fma.rn.f32x2 %0, %1, %2, %0;" : "+l"(d) : "l"(a), "l"(b));
}
__device__ __forceinline__ ull pack2(float x) {
    ull r;
    asm("mov.b64 %0, {%1, %1};" : "=l"(r) : "f"(x));
    return r;
}
__device__ __forceinline__ float2 unpack2(ull v) {
    float2 f;
    asm("mov.b64 {%0, %1}, %2;" : "=f"(f.x), "=f"(f.y) : "l"(v));
    return f;
}

// ---------------- mma.sync / ldmatrix / cp.async helpers ----------------
__device__ __forceinline__ uint32_t smem_to_u32(const void* p) {
    uint32_t a;
    asm("{ .reg .u64 t; cvta.to.shared.u64 t, %1; cvt.u32.u64 %0, t; }" : "=r"(a) : "l"(p));
    return a;
}
__device__ __forceinline__ void mma_f16(float* d, const uint32_t* a, const uint32_t* b) {
    asm volatile(
        "mma.sync.aligned.m16n8k16.row.col.f32.f16.f16.f32 "
        "{%0,%1,%2,%3}, {%4,%5,%6,%7}, {%8,%9}, {%0,%1,%2,%3};"
        : "+f"(d[0]), "+f"(d[1]), "+f"(d[2]), "+f"(d[3])
        : "r"(a[0]), "r"(a[1]), "r"(a[2]), "r"(a[3]), "r"(b[0]), "r"(b[1]));
}
__device__ __forceinline__ void ldsm4(uint32_t* r, uint32_t addr) {
    asm volatile("ldmatrix.sync.aligned.m8n8.x4.shared.b16 {%0,%1,%2,%3}, [%4];"
                 : "=r"(r[0]), "=r"(r[1]), "=r"(r[2]), "=r"(r[3]) : "r"(addr));
}
__device__ __forceinline__ void cp16(uint32_t d, const void* s, int sz) {
    asm volatile("cp.async.cg.shared.global [%0], [%1], 16, %2;"
                 :: "r"(d), "l"(s), "r"(sz) : "memory");
}
#define CP_COMMIT() asm volatile("cp.async.commit_group;" ::: "memory")

// ---------------- BatchNorm statistics ----------------
__global__ void __launch_bounds__(256) bn_stats_kernel(const float* __restrict__ x,
                                                       const float* __restrict__ gamma,
                                                       const float* __restrict__ beta) {
    const int c = blockIdx.x;
    const int tid = threadIdx.x;
    const int N = B_ * T0;
    float s = 0.f, sq = 0.f;
    for (int i = tid; i < N; i += 256) {
        float v = x[(size_t)i * C0 + c];
        s += v; sq += v * v;
    }
    __shared__ float rs[256], rq[256];
    rs[tid] = s; rq[tid] = sq;
    __syncthreads();
    for (int o = 128; o > 0; o >>= 1) {
        if (tid < o) { rs[tid] += rs[tid + o]; rq[tid] += rq[tid + o]; }
        __syncthreads();
    }
    if (tid == 0) {
        float mean = rs[0] / (float)N;
        float var  = rq[0] / (float)N - mean * mean;
        float sc   = gamma[c] * rsqrtf(var + EPSV);
        g_bn[c]      = sc;
        g_bn[80 + c] = beta[c] - mean * sc;
    }
}

__global__ void __launch_bounds__(512) zero_h_kernel() {
    int i = blockIdx.x * blockDim.x + threadIdx.x;
    if (i < B_ * HIDN) g_hstate[0][i] = 0.f;
}

// ---------------- x -> bn-normalized fp16, channel-padded to 128 ----------------
__global__ void __launch_bounds__(256) x16prep_kernel(const float* __restrict__ x) {
    int i = blockIdx.x * 256 + threadIdx.x;
    if (i >= B_ * T0 * 128) return;
    int ci = i & 127;
    int row = i >> 7;
    __half v = __float2half(0.f);
    if (ci < C0) {
        float f = x[(size_t)row * C0 + ci] * g_bn[ci] + g_bn[80 + ci];
        v = __float2half_rn(f);
    }
    g_x16[i] = v;
}

// ---------------- conv0 weights -> fp16 [n][5*128] ----------------
__global__ void __launch_bounds__(256) wc0_kernel(const float* __restrict__ w) {
    int i = blockIdx.x * 256 + threadIdx.x;
    if (i >= 512 * 640) return;
    int kin = i % 640;
    int n   = i / 640;
    int tap = kin >> 7, ci = kin & 127;
    float v = (ci < C0) ? w[(size_t)(tap * C0 + ci) * 512 + n] : 0.f;
    g_wc16[i] = __float2half_rn(v);
}

// ---------------- tcr weights transpose to fp16 [l][n][kin] ----------------
__global__ void __launch_bounds__(256) wsplit_kernel(const float* __restrict__ tcr_w) {
    __shared__ float tile[32][33];
    const int l  = blockIdx.z;
    const int k0 = blockIdx.x * 32;
    const int n0 = blockIdx.y * 32;
    const int tx = threadIdx.x, ty = threadIdx.y;
#pragma unroll
    for (int j = 0; j < 32; j += 8)
        tile[ty + j][tx] = tcr_w[((size_t)l * 2560 + k0 + ty + j) * 512 + n0 + tx];
    __syncthreads();
#pragma unroll
    for (int j = 0; j < 32; j += 8) {
        float v = tile[tx][ty + j];
        size_t di = ((size_t)l * 512 + n0 + ty + j) * 2560 + k0 + tx;
        g_wh[di] = __float2half_rn(v);
    }
}

// ---------------- enc16 [b][t][d] -> encT16 [b][d][TPAD] ----------------
__global__ void __launch_bounds__(256) enct_kernel() {
    __shared__ __half tile[32][33];
    const int b  = blockIdx.z;
    const int t0 = blockIdx.x * 32;
    const int d0 = blockIdx.y * 32;
    const int tx = threadIdx.x, ty = threadIdx.y;
#pragma unroll
    for (int j = 0; j < 32; j += 8) {
        int t = t0 + ty + j;
        __half v = __float2half(0.f);
        if (t < T1) v = g_sa0[((size_t)b * T1 + t) * 512 + d0 + tx];
        tile[ty + j][tx] = v;
    }
    __syncthreads();
#pragma unroll
    for (int j = 0; j < 32; j += 8)
        g_encT16[((size_t)b * D_ + d0 + ty + j) * TPAD + t0 + tx] = tile[tx][ty + j];
}

// ---------------- fc_w -> fcwT16 [c(pad 1024)][k 1024] ----------------
__global__ void __launch_bounds__(256) fcwt_kernel(const float* __restrict__ fw) {
    __shared__ __half tile[32][33];
    const int k0 = blockIdx.x * 32;
    const int c0 = blockIdx.y * 32;
    const int tx = threadIdx.x, ty = threadIdx.y;
#pragma unroll
    for (int j = 0; j < 32; j += 8) {
        int c = c0 + tx;
        float v = (c < VOCABN) ? fw[(size_t)(k0 + ty + j) * VOCABN + c] : 0.f;
        tile[ty + j][tx] = __float2half_rn(v);
    }
    __syncthreads();
#pragma unroll
    for (int j = 0; j < 32; j += 8)
        g_fcwT16[(size_t)(c0 + ty + j) * 1024 + k0 + tx] = tile[tx][ty + j];
}

// ---------------- unified fp16 conv (im2col GEMM) with cp.async 2-stage pipeline ----------------
// CTA 128x128, 8 warps. A = fp16 activations [b][tin][CIN_PAD] via taps; B = weights [n][KTOT].
// K-chunk 64. smem rows 72 halves (144 B). Non-trans ldmatrix for both fragments.
#define ASTR 72
#define CBUF (128 * ASTR * 2)     // 18432 B per buffer
#define CSTAGE (2 * CBUF)         // 36864 B per stage (A, B)
#define CDSMEM (2 * CSTAGE)       // 73728 B
template<int TIN, int STRIDE, int PADL, int CIN_PAD, int KCHUNKS, bool RESID, bool SPLIT>
__global__ void __launch_bounds__(256, 2) conv16_kernel(const __half* __restrict__ a16,
                                                        const __half* __restrict__ wh,
                                                        const float* __restrict__ resid_in,
                                                        const float* __restrict__ bias,
                                                        float* __restrict__ out,
                                                        __half* __restrict__ oh) {
    extern __shared__ __align__(16) uint8_t dsm[];
    const uint32_t base = smem_to_u32(dsm);

    const int tid = threadIdx.x;
    const int wid = tid >> 5, lane = tid & 31;
    const int n0 = blockIdx.x * 128;
    const int m0 = blockIdx.y * 128;
    const int warp_m = (wid >> 1) << 5;
    const int warp_n = (wid & 1) << 6;
    const int KTOT = KCHUNKS * 64;

    float acc[2][8][4];
#pragma unroll
    for (int i = 0; i < 2; i++)
#pragma unroll
        for (int j = 0; j < 8; j++)
#pragma unroll
            for (int r = 0; r < 4; r++) acc[i][j][r] = 0.f;

    const int lq = tid & 7;
    const int lrow = tid >> 3;

    const uint32_t aoff = (warp_m + (lane & 15)) * 144 + (lane >> 4) * 16;
    const int browoff = warp_n + (lane & 7) + ((lane >> 4) & 1) * 8;
    const uint32_t boff = browoff * 144 + ((lane >> 3) & 1) * 16;

    auto issue = [&](int c, int st) {
        const int tap = c / (CIN_PAD / 64);
        const int ci0 = (c % (CIN_PAD / 64)) * 64;
        const uint32_t sb = base + st * CSTAGE;
#pragma unroll
        for (int it = 0; it < 4; it++) {
            int ml = lrow + it * 32;
            int m  = m0 + ml;
            int bb = m / T1;
            int t  = m - bb * T1;
            int tin = t * STRIDE - PADL + tap;
            bool v = (tin >= 0 && tin < TIN);
            int tinc = v ? tin : 0;
            const __half* src = a16 + ((size_t)bb * TIN + tinc) * CIN_PAD + ci0 + lq * 8;
            cp16(sb + (uint32_t)(ml * ASTR + lq * 8) * 2, src, v ? 16 : 0);
        }
#pragma unroll
        for (int it = 0; it < 4; it++) {
            int nl = lrow + it * 32;
            const __half* src = wh + (size_t)(n0 + nl) * KTOT + c * 64 + lq * 8;
            cp16(sb + CBUF + (uint32_t)(nl * ASTR + lq * 8) * 2, src, 16);
        }
        CP_COMMIT();
    };

    issue(0, 0);
    for (int c = 0; c < KCHUNKS; c++) {
        const int st = c & 1;
        if (c + 1 < KCHUNKS) {
            issue(c + 1, (c + 1) & 1);
            asm volatile("cp.async.wait_group 1;" ::: "memory");
        } else {
            asm volatile("cp.async.wait_group 0;" ::: "memory");
        }
        __syncthreads();

        const uint32_t sb = base + st * CSTAGE;
        const uint32_t aAddr = sb + aoff;
        const uint32_t bAddr = sb + CBUF + boff;
#pragma unroll
        for (int s = 0; s < 4; s++) {
            uint32_t a[2][4];
            ldsm4(a[0], aAddr + s * 32);
            ldsm4(a[1], aAddr + s * 32 + 16 * 144);
#pragma unroll
            for (int jj = 0; jj < 4; jj++) {
                uint32_t b[4];
                ldsm4(b, bAddr + s * 32 + jj * 16 * 144);
#pragma unroll
                for (int i = 0; i < 2; i++) {
                    mma_f16(acc[i][2 * jj],     a[i], b);
                    mma_f16(acc[i][2 * jj + 1], a[i], b + 2);
                }
            }
        }
        __syncthreads();
    }

    // ---- epilogue: bias + relu (+ residual) (+ fp16 emit) ----
    const int r0 = lane >> 2;
    const int cc = (lane & 3) * 2;
#pragma unroll
    for (int i = 0; i < 2; i++) {
        int mrow = m0 + warp_m + i * 16 + r0;
#pragma unroll
        for (int j = 0; j < 8; j++) {
            int col = n0 + warp_n + j * 8 + cc;
            float2 b2 = *reinterpret_cast<const float2*>(bias + col);
#pragma unroll
            for (int half = 0; half < 2; half++) {
                int m = mrow + half * 8;
                float va = acc[i][j][half * 2 + 0];
                float vb = acc[i][j][half * 2 + 1];
                float2 v;
                v.x = fmaxf(va + b2.x, 0.f);
                v.y = fmaxf(vb + b2.y, 0.f);
                if (RESID) {
                    float2 e = *reinterpret_cast<const float2*>(resid_in + (size_t)m * 512 + col);
                    v.x += e.x;
                    v.y += e.y;
                }
                *reinterpret_cast<float2*>(out + (size_t)m * 512 + col) = v;
                if (SPLIT)
                    *reinterpret_cast<__half2*>(oh + (size_t)m * 512 + col) = __floats2half2_rn(v.x, v.y);
            }
        }
    }
}

// ---------------- scores16 ----------------
__global__ void __launch_bounds__(256, 2) scores16_kernel() {
    __shared__ __align__(16) __half sA[128 * ASTR];
    __shared__ __align__(16) __half sB[128 * ASTR];
    const int tid = threadIdx.x;
    const int wid = tid >> 5, lane = tid & 31;
    const int n0 = blockIdx.x * 128;
    const int m0 = blockIdx.y * 128;
    const int b  = blockIdx.z;
    const int warp_m = (wid >> 1) << 5;
    const int warp_n = (wid & 1) << 6;

    float acc[2][8][4];
#pragma unroll
    for (int i = 0; i < 2; i++)
#pragma unroll
        for (int j = 0; j < 8; j++)
#pragma unroll
            for (int r = 0; r < 4; r++) acc[i][j][r] = 0.f;

    const int lq = tid & 7;
    const int lrow = tid >> 3;
    const uint32_t aAddr = smem_to_u32(sA) + (warp_m + (lane & 15)) * 144 + (lane >> 4) * 16;
    const int browoff = warp_n + (lane & 7) + ((lane >> 4) & 1) * 8;
    const uint32_t bAddr = smem_to_u32(sB) + browoff * 144 + ((lane >> 3) & 1) * 16;

    for (int c = 0; c < 8; c++) {
#pragma unroll
        for (int it = 0; it < 4; it++) {
            int ml = lrow + it * 32;
            int u  = m0 + ml;
            uint4 va = make_uint4(0, 0, 0, 0);
            if (u < USTEPS)
                va = *reinterpret_cast<const uint4*>(
                    g_cat16 + ((size_t)u * 32 + b) * 1024 + c * 64 + lq * 8);
            *reinterpret_cast<uint4*>(&sA[ml * ASTR + lq * 8]) = va;
        }
#pragma unroll
        for (int it = 0; it < 4; it++) {
            int nl = lrow + it * 32;
            int t  = n0 + nl;
            uint4 vb = make_uint4(0, 0, 0, 0);
            if (t < T1)
                vb = *reinterpret_cast<const uint4*>(
                    g_sa0 + ((size_t)b * T1 + t) * 512 + c * 64 + lq * 8);
            *reinterpret_cast<uint4*>(&sB[nl * ASTR + lq * 8]) = vb;
        }
        __syncthreads();
#pragma unroll
        for (int s = 0; s < 4; s++) {
            uint32_t a[2][4];
            ldsm4(a[0], aAddr + s * 32);
            ldsm4(a[1], aAddr + s * 32 + 16 * 144);
#pragma unroll
            for (int jj = 0; jj < 4; jj++) {
                uint32_t bb[4];
                ldsm4(bb, bAddr + s * 32 + jj * 16 * 144);
#pragma unroll
                for (int i = 0; i < 2; i++) {
                    mma_f16(acc[i][2 * jj],     a[i], bb);
                    mma_f16(acc[i][2 * jj + 1], a[i], bb + 2);
                }
            }
        }
        __syncthreads();
    }

    const int r0 = lane >> 2;
    const int cc = (lane & 3) * 2;
#pragma unroll
    for (int i = 0; i < 2; i++) {
        int urow = m0 + warp_m + i * 16 + r0;
#pragma unroll
        for (int j = 0; j < 8; j++) {
            int col = n0 + warp_n + j * 8 + cc;
#pragma unroll
            for (int half = 0; half < 2; half++) {
                int u = urow + half * 8;
                if (u < USTEPS && col < T1) {
                    float2 v = make_float2(acc[i][j][half * 2], acc[i][j][half * 2 + 1]);
                    *reinterpret_cast<float2*>(
                        g_scoresall + ((size_t)u * 32 + b) * T1 + col) = v;
                }
            }
        }
    }
}

// ---------------- ctx16 ----------------
__global__ void __launch_bounds__(256, 2) ctx16_kernel() {
    __shared__ __align__(16) __half sA[128 * ASTR];
    __shared__ __align__(16) __half sB[128 * ASTR];
    const int tid = threadIdx.x;
    const int wid = tid >> 5, lane = tid & 31;
    const int n0 = blockIdx.x * 128;
    const int m0 = blockIdx.y * 128;
    const int b  = blockIdx.z;
    const int warp_m = (wid >> 1) << 5;
    const int warp_n = (wid & 1) << 6;

    float acc[2][8][4];
#pragma unroll
    for (int i = 0; i < 2; i++)
#pragma unroll
        for (int j = 0; j < 8; j++)
#pragma unroll
            for (int r = 0; r < 4; r++) acc[i][j][r] = 0.f;

    const int lq = tid & 7;
    const int lrow = tid >> 3;
    const uint32_t aAddr = smem_to_u32(sA) + (warp_m + (lane & 15)) * 144 + (lane >> 4) * 16;
    const int browoff = warp_n + (lane & 7) + ((lane >> 4) & 1) * 8;
    const uint32_t bAddr = smem_to_u32(sB) + browoff * 144 + ((lane >> 3) & 1) * 16;

    for (int c = 0; c < 13; c++) {
#pragma unroll
        for (int it = 0; it < 4; it++) {
            int ml = lrow + it * 32;
            int u  = m0 + ml;
            uint4 va = make_uint4(0, 0, 0, 0);
            if (u < USTEPS)
                va = *reinterpret_cast<const uint4*>(
                    g_alpha16 + ((size_t)u * 32 + b) * TPAD + c * 64 + lq * 8);
            *reinterpret_cast<uint4*>(&sA[ml * ASTR + lq * 8]) = va;
        }
#pragma unroll
        for (int it = 0; it < 4; it++) {
            int nl = lrow + it * 32;
            *reinterpret_cast<uint4*>(&sB[nl * ASTR + lq * 8]) =
                *reinterpret_cast<const uint4*>(
                    g_encT16 + ((size_t)b * D_ + n0 + nl) * TPAD + c * 64 + lq * 8);
        }
        __syncthreads();
#pragma unroll
        for (int s = 0; s < 4; s++) {
            uint32_t a[2][4];
            ldsm4(a[0], aAddr + s * 32);
            ldsm4(a[1], aAddr + s * 32 + 16 * 144);
#pragma unroll
            for (int jj = 0; jj < 4; jj++) {
                uint32_t bb[4];
                ldsm4(bb, bAddr + s * 32 + jj * 16 * 144);
#pragma unroll
                for (int i = 0; i < 2; i++) {
                    mma_f16(acc[i][2 * jj],     a[i], bb);
                    mma_f16(acc[i][2 * jj + 1], a[i], bb + 2);
                }
            }
        }
        __syncthreads();
    }

    const int r0 = lane >> 2;
    const int cc = (lane & 3) * 2;
#pragma unroll
    for (int i = 0; i < 2; i++) {
        int urow = m0 + warp_m + i * 16 + r0;
#pragma unroll
        for (int j = 0; j < 8; j++) {
            int col = n0 + warp_n + j * 8 + cc;
#pragma unroll
            for (int half = 0; half < 2; half++) {
                int u = urow + half * 8;
                if (u < USTEPS) {
                    *reinterpret_cast<__half2*>(
                        g_cat16 + ((size_t)u * 32 + b) * 1024 + 512 + col) =
                        __floats2half2_rn(acc[i][j][half * 2], acc[i][j][half * 2 + 1]);
                }
            }
        }
    }
}

// ---------------- fc16 ----------------
__global__ void __launch_bounds__(256, 2) fc16_kernel(const float* __restrict__ fb) {
    __shared__ __align__(16) __half sA[128 * ASTR];
    __shared__ __align__(16) __half sB[128 * ASTR];
    const int tid = threadIdx.x;
    const int wid = tid >> 5, lane = tid & 31;
    const int n0 = blockIdx.x * 128;
    const int m0 = blockIdx.y * 128;
    const int warp_m = (wid >> 1) << 5;
    const int warp_n = (wid & 1) << 6;

    float acc[2][8][4];
#pragma unroll
    for (int i = 0; i < 2; i++)
#pragma unroll
        for (int j = 0; j < 8; j++)
#pragma unroll
            for (int r = 0; r < 4; r++) acc[i][j][r] = 0.f;

    const int lq = tid & 7;
    const int lrow = tid >> 3;
    const uint32_t aAddr = smem_to_u32(sA) + (warp_m + (lane & 15)) * 144 + (lane >> 4) * 16;
    const int browoff = warp_n + (lane & 7) + ((lane >> 4) & 1) * 8;
    const uint32_t bAddr = smem_to_u32(sB) + browoff * 144 + ((lane >> 3) & 1) * 16;

    for (int c = 0; c < 16; c++) {
#pragma unroll
        for (int it = 0; it < 4; it++) {
            int ml = lrow + it * 32;
            *reinterpret_cast<uint4*>(&sA[ml * ASTR + lq * 8]) =
                *reinterpret_cast<const uint4*>(
                    g_cat16 + (size_t)(m0 + ml) * 1024 + c * 64 + lq * 8);
        }
#pragma unroll
        for (int it = 0; it < 4; it++) {
            int nl = lrow + it * 32;
            *reinterpret_cast<uint4*>(&sB[nl * ASTR + lq * 8]) =
                *reinterpret_cast<const uint4*>(
                    g_fcwT16 + (size_t)(n0 + nl) * 1024 + c * 64 + lq * 8);
        }
        __syncthreads();
#pragma unroll
        for (int s = 0; s < 4; s++) {
            uint32_t a[2][4];
            ldsm4(a[0], aAddr + s * 32);
            ldsm4(a[1], aAddr + s * 32 + 16 * 144);
#pragma unroll
            for (int jj = 0; jj < 4; jj++) {
                uint32_t bb[4];
                ldsm4(bb, bAddr + s * 32 + jj * 16 * 144);
#pragma unroll
                for (int i = 0; i < 2; i++) {
                    mma_f16(acc[i][2 * jj],     a[i], bb);
                    mma_f16(acc[i][2 * jj + 1], a[i], bb + 2);
                }
            }
        }
        __syncthreads();
    }

    const int r0 = lane >> 2;
    const int cc = (lane & 3) * 2;
#pragma unroll
    for (int i = 0; i < 2; i++) {
        int mrow = m0 + warp_m + i * 16 + r0;
#pragma unroll
        for (int j = 0; j < 8; j++) {
            int col = n0 + warp_n + j * 8 + cc;
            if (col < VOCABN) {
                float2 b2 = *reinterpret_cast<const float2*>(fb + col);
#pragma unroll
                for (int half = 0; half < 2; half++) {
                    int m = mrow + half * 8;
                    float2 v = make_float2(acc[i][j][half * 2] + b2.x,
                                           acc[i][j][half * 2 + 1] + b2.y);
                    *reinterpret_cast<float2*>(g_logitsall + (size_t)m * 1000 + col) = v;
                }
            }
        }
    }
}

// ---------------- Recurrence kernel A: mh partials ----------------
__global__ void __launch_bounds__(256) gru_part_kernel(const float* __restrict__ grk, int u) {
    __shared__ float Hs[16][33];
    __shared__ __align__(16) float Ws[16][128];
    const float* h = g_hstate[u & 1];
    const int tid = threadIdx.x;
    const int n0 = blockIdx.x * 128;
    const int kb = blockIdx.y * 64;
    const int nx = tid & 31;
    const int my = tid >> 5;

    ull acc[4][2];
#pragma unroll
    for (int i = 0; i < 4; i++) { acc[i][0] = 0ull; acc[i][1] = 0ull; }

    for (int k0 = 0; k0 < 64; k0 += 16) {
#pragma unroll
        for (int it = 0; it < 2; it++) {
            int e = tid + it * 256;
            int kk = e & 15, m = e >> 4;
            Hs[kk][m] = h[m * 512 + kb + k0 + kk];
        }
#pragma unroll
        for (int it = 0; it < 2; it++) {
            int s = tid + it * 256;
            int cq = s & 31, kr = s >> 5;
            *reinterpret_cast<float4*>(&Ws[kr][cq << 2]) =
                *reinterpret_cast<const float4*>(grk + (size_t)(kb + k0 + kr) * 1536 + n0 + (cq << 2));
        }
        __syncthreads();
#pragma unroll
        for (int kk = 0; kk < 16; kk++) {
            ulonglong2 bp = *reinterpret_cast<const ulonglong2*>(&Ws[kk][nx << 2]);
#pragma unroll
            for (int i = 0; i < 4; i++) {
                ull ad = pack2(Hs[kk][(my << 2) + i]);
                fma2(acc[i][0], ad, bp.x);
                fma2(acc[i][1], ad, bp.y);
            }
        }
        __syncthreads();
    }
    float* outp = g_mhp[blockIdx.y];
#pragma unroll
    for (int i = 0; i < 4; i++) {
        float2 v0 = unpack2(acc[i][0]);
        float2 v1 = unpack2(acc[i][1]);
        *reinterpret_cast<float4*>(&outp[((my << 2) + i) * 1536 + n0 + (nx << 2)]) =
            make_float4(v0.x, v0.y, v1.x, v1.y);
    }
}

// ---------------- Recurrence kernel B: sum 8 partials + GRU gates ----------------
__global__ void __launch_bounds__(512) gru_gates_kernel(const int* __restrict__ y,
                                                        const float* __restrict__ gk,
                                                        const float* __restrict__ gb,
                                                        int u) {
    const int b = blockIdx.x;
    const int j = threadIdx.x;
    float hz = 0.f, hr = 0.f, hh = 0.f;
#pragma unroll
    for (int c = 0; c < 8; c++) {
        const float* p = g_mhp[c] + b * 1536;
        hz += p[j];
        hr += p[512 + j];
        hh += p[1024 + j];
    }
    const float* bi = gb;
    const float* br = gb + 1536;
    const int tok   = y[b * 201 + u];
    const float* gx = gk + (size_t)tok * 1536;
    float xz = gx[j]        + bi[j];
    float xr = gx[512 + j]  + bi[512 + j];
    float xh = gx[1024 + j] + bi[1024 + j];
    hz += br[j];
    hr += br[512 + j];
    hh += br[1024 + j];
    float z = 1.f / (1.f + expf(-(xz + hz)));
    float r = 1.f / (1.f + expf(-(xr + hr)));
    float cand = tanhf(xh + r * hh);
    float hold = g_hstate[u & 1][b * 512 + j];
    float hn = z * hold + (1.f - z) * cand;
    g_hstate[(u + 1) & 1][b * 512 + j] = hn;
    g_cat16[((size_t)u * 32 + b) * 1024 + j] = __float2half_rn(hn);
}

// ---------------- Batched softmax over 800 -> alpha16 (padded) ----------------
__global__ void __launch_bounds__(256) sm800_kernel() {
    const int row = blockIdx.x;
    const int tid = threadIdx.x;
    const float* sp = g_scoresall + (size_t)row * T1;
    __half* ap = g_alpha16 + (size_t)row * TPAD;
    __shared__ float sa[800];
    __shared__ float red[8], red2[8];
    const int w = tid >> 5, lane = tid & 31;

    float m = -1e30f;
    for (int t = tid; t < 800; t += 256) {
        float v = sp[t];
        sa[t] = v;
        m = fmaxf(m, v);
    }
#pragma unroll
    for (int o = 16; o; o >>= 1) m = fmaxf(m, __shfl_xor_sync(0xffffffffu, m, o));
    if (lane == 0) red[w] = m;
    __syncthreads();
    float mm = red[0];
#pragma unroll
    for (int i = 1; i < 8; i++) mm = fmaxf(mm, red[i]);

    float ps = 0.f;
    for (int t = tid; t < 800; t += 256) {
        float e = expf(sa[t] - mm);
        sa[t] = e;
        ps += e;
    }
#pragma unroll
    for (int o = 16; o; o >>= 1) ps += __shfl_xor_sync(0xffffffffu, ps, o);
    if (lane == 0) red2[w] = ps;
    __syncthreads();
    float sum = 0.f;
#pragma unroll
    for (int i = 0; i < 8; i++) sum += red2[i];
    const float inv = 1.f / sum;

    for (int t = tid; t < 800; t += 256) ap[t] = __float2half_rn(sa[t] * inv);
    if (tid < 32) ap[800 + tid] = __float2half(0.f);
}

// ---------------- Batched output softmax ----------------
__global__ void __launch_bounds__(256) outsm_all_kernel(float* __restrict__ out) {
    const int m = blockIdx.x;
    const int u = m >> 5, b = m & 31;
    const int tid = threadIdx.x;
    __shared__ float sh[1000];
    __shared__ float red[8], red2[8];
    const int w = tid >> 5, lane = tid & 31;
    const float* lp = g_logitsall + (size_t)m * 1000;

    float mx = -1e30f;
    for (int c = tid; c < 1000; c += 256) {
        float v = lp[c];
        sh[c] = v;
        mx = fmaxf(mx, v);
    }
#pragma unroll
    for (int o = 16; o; o >>= 1) mx = fmaxf(mx, __shfl_xor_sync(0xffffffffu, mx, o));
    if (lane == 0) red[w] = mx;
    __syncthreads();
    float mm = red[0];
#pragma unroll
    for (int i = 1; i < 8; i++) mm = fmaxf(mm, red[i]);

    float ps = 0.f;
    for (int c = tid; c < 1000; c += 256) {
        float e = expf(sh[c] - mm);
        sh[c] = e;
        ps += e;
    }
#pragma unroll
    for (int o = 16; o; o >>= 1) ps += __shfl_xor_sync(0xffffffffu, ps, o);
    if (lane == 0) red2[w] = ps;
    __syncthreads();
    float sum = 0.f;
#pragma unroll
    for (int i = 0; i < 8; i++) sum += red2[i];
    const float inv = 1.f / sum;

    float* op = out + ((size_t)b * USTEPS + u) * VOCABN;
    for (int c = tid; c < 1000; c += 256) op[c] = sh[c] * inv;
}

// ---------------- launch ----------------
extern "C" void kernel_launch(void* const* d_in, const int* in_sizes, int n_in,
                              void* d_out, int out_size) {
    const float* x        = (const float*)d_in[0];
    const int*   y        = (const int*)  d_in[1];
    const float* bn_gamma = (const float*)d_in[2];
    const float* bn_beta  = (const float*)d_in[3];
    const float* conv0_w  = (const float*)d_in[4];
    const float* conv0_b  = (const float*)d_in[5];
    const float* tcr_w    = (const float*)d_in[6];
    const float* tcr_b    = (const float*)d_in[7];
    const float* gru_k    = (const float*)d_in[8];
    const float* gru_rk   = (const float*)d_in[9];
    const float* gru_b    = (const float*)d_in[10];
    const float* fc_w     = (const float*)d_in[11];
    const float* fc_b     = (const float*)d_in[12];
    float* out = (float*)d_out;

    float *h1, *h2;
    __half *a0, *a1, *wh, *x16, *wc16;
    cudaGetSymbolAddress((void**)&h1, g_h1);
    cudaGetSymbolAddress((void**)&h2, g_h2);
    cudaGetSymbolAddress((void**)&a0, g_sa0);
    cudaGetSymbolAddress((void**)&a1, g_sa1);
    cudaGetSymbolAddress((void**)&wh, g_wh);
    cudaGetSymbolAddress((void**)&x16, g_x16);
    cudaGetSymbolAddress((void**)&wc16, g_wc16);

    // conv16 instantiations used
    auto conv0k = conv16_kernel<T0, 2, 1, 128, 10, false, true>;
    auto tcrk   = conv16_kernel<T1, 1, 2, 512, 40, true,  true>;
    cudaFuncSetAttribute(conv0k, cudaFuncAttributeMaxDynamicSharedMemorySize, CDSMEM);
    cudaFuncSetAttribute(tcrk,   cudaFuncAttributeMaxDynamicSharedMemorySize, CDSMEM);

    // ---- encoder ----
    bn_stats_kernel<<<80, 256>>>(x, bn_gamma, bn_beta);
    zero_h_kernel<<<32, 512>>>();
    dim3 wgrid(80, 16, 4);
    wsplit_kernel<<<wgrid, dim3(32, 8)>>>(tcr_w);
    fcwt_kernel<<<dim3(32, 32), dim3(32, 8)>>>(fc_w);
    wc0_kernel<<<(512 * 640 + 255) / 256, 256>>>(conv0_w);
    x16prep_kernel<<<(B_ * T0 * 128 + 255) / 256, 256>>>(x);

    dim3 cgrid(4, 200);
    conv0k<<<cgrid, 256, CDSMEM>>>(x16, wc16, nullptr, conv0_b, h1, a0);

    const size_t WT = (size_t)512 * 2560;
    tcrk<<<cgrid, 256, CDSMEM>>>(a0, wh + 0 * WT, h1, tcr_b + 0 * 512, h2, a1);
    tcrk<<<cgrid, 256, CDSMEM>>>(a1, wh + 1 * WT, h2, tcr_b + 1 * 512, h1, a0);
    tcrk<<<cgrid, 256, CDSMEM>>>(a0, wh + 2 * WT, h1, tcr_b + 2 * 512, h2, a1);
    tcrk<<<cgrid, 256, CDSMEM>>>(a1, wh + 3 * WT, h2, tcr_b + 3 * 512, h1, a0);
    // enc16 lives in g_sa0

    enct_kernel<<<dim3(26, 16, 32), dim3(32, 8)>>>();

    // ---- GRU recurrence ----
    dim3 pgrid(12, 8);
    for (int u = 0; u < USTEPS; u++) {
        gru_part_kernel<<<pgrid, 256>>>(gru_rk, u);
        gru_gates_kernel<<<32, 512>>>(y, gru_k, gru_b, u);
    }

    // ---- batched tail (all fp16 mma) ----
    scores16_kernel<<<dim3(7, 2, 32), 256>>>();
    sm800_kernel<<<USTEPS * B_, 256>>>();
    ctx16_kernel<<<dim3(4, 2, 32), 256>>>();
    fc16_kernel<<<dim3(8, 50), 256>>>(fc_b);
    outsm_all_kernel<<<USTEPS * B_, 256>>>(out);
}